// round 3
// baseline (speedup 1.0000x reference)
#include <cuda_runtime.h>

#define Bb 8
#define Nn 2048
#define Cc 64
#define HD 128

#define QT 64
#define KT 64
#define QPAD 132   // 128 + 4 pad, keeps float4 alignment, kills row bank conflicts
#define VPAD 68    // 64 + 4 pad

// scratch (allocation-free rule: __device__ globals)
__device__ float g_lhs[Bb*Nn*HD];
__device__ float g_rhs[Bb*Nn*HD];
__device__ float g_A[Bb*Nn*Cc];

// ---------------------------------------------------------------------------
// Kernel 1: lhs = X @ W_ha1^T ; rhs = H_pre @ W_ha2^T + b_ha2
// one block per row n (B*N rows), 128 threads (one per h)
// ---------------------------------------------------------------------------
__global__ void prep_kernel(const float* __restrict__ X,
                            const float* __restrict__ Hp,
                            const float* __restrict__ W_ha1,
                            const float* __restrict__ W_ha2,
                            const float* __restrict__ b_ha2) {
    int n = blockIdx.x;
    int h = threadIdx.x;
    __shared__ float xs[Cc];
    __shared__ float hs[HD];
    if (h < Cc) xs[h] = X[n*Cc + h];
    hs[h] = Hp[n*HD + h];
    __syncthreads();

    float acc1 = 0.f;
    const float* w1 = W_ha1 + h*Cc;
#pragma unroll
    for (int c = 0; c < Cc; c++) acc1 += xs[c] * __ldg(&w1[c]);

    float acc2 = b_ha2[h];
    const float* w2 = W_ha2 + h*HD;
#pragma unroll
    for (int g = 0; g < HD; g++) acc2 += hs[g] * __ldg(&w2[g]);

    g_lhs[n*HD + h] = acc1;
    g_rhs[n*HD + h] = acc2;
}

// ---------------------------------------------------------------------------
// Kernel 2: flash-style attention
//   S = leaky_relu(lhs @ rhs^T), P = softmax_row(S), A = P @ X
// grid (N/QT, B), 256 threads (16x16), 4x4 register tile per thread
// ---------------------------------------------------------------------------
__global__ void attn_kernel(const float* __restrict__ X) {
    extern __shared__ float sm[];
    float* Qs  = sm;                    // QT*QPAD
    float* Ks  = Qs + QT*QPAD;          // KT*QPAD
    float* Vs  = Ks + KT*QPAD;          // KT*VPAD
    float* Ps  = Vs + KT*VPAD;          // QT*VPAD
    float* m_s = Ps + QT*VPAD;          // QT
    float* l_s = m_s + QT;              // QT
    float* a_s = l_s + QT;              // QT

    const int b  = blockIdx.y;
    const int q0 = blockIdx.x * QT;
    const int t  = threadIdx.x;
    const int ti = t >> 4;              // 0..15
    const int tj = t & 15;              // 0..15

    // load Q tile (64x128)
    const float* Qg = g_lhs + (size_t)(b*Nn + q0)*HD;
    for (int idx = t; idx < QT*(HD/4); idx += 256) {
        int r = idx >> 5, c4 = idx & 31;
        float4 v = ((const float4*)(Qg + r*HD))[c4];
        *(float4*)(&Qs[r*QPAD + c4*4]) = v;
    }
    if (t < QT) { m_s[t] = -1e30f; l_s[t] = 0.f; }

    float acc[4][4];
#pragma unroll
    for (int i = 0; i < 4; i++)
#pragma unroll
        for (int j = 0; j < 4; j++) acc[i][j] = 0.f;
    __syncthreads();

    for (int k0 = 0; k0 < Nn; k0 += KT) {
        // load K tile (64x128) and V tile (64x64)
        const float* Kg = g_rhs + (size_t)(b*Nn + k0)*HD;
        for (int idx = t; idx < KT*(HD/4); idx += 256) {
            int r = idx >> 5, c4 = idx & 31;
            float4 v = ((const float4*)(Kg + r*HD))[c4];
            *(float4*)(&Ks[r*QPAD + c4*4]) = v;
        }
        const float* Vg = X + (size_t)(b*Nn + k0)*Cc;
        for (int idx = t; idx < KT*(Cc/4); idx += 256) {
            int r = idx >> 4, c4 = idx & 15;
            float4 v = ((const float4*)(Vg + r*Cc))[c4];
            *(float4*)(&Vs[r*VPAD + c4*4]) = v;
        }
        __syncthreads();

        // S tile: 4x4 per thread, K = 128
        float s[4][4];
#pragma unroll
        for (int i = 0; i < 4; i++)
#pragma unroll
            for (int j = 0; j < 4; j++) s[i][j] = 0.f;

        for (int k = 0; k < HD; k += 4) {
            float4 qv[4], kv[4];
#pragma unroll
            for (int i = 0; i < 4; i++)
                qv[i] = *(const float4*)(&Qs[(4*ti + i)*QPAD + k]);
#pragma unroll
            for (int j = 0; j < 4; j++)
                kv[j] = *(const float4*)(&Ks[(4*tj + j)*QPAD + k]);
#pragma unroll
            for (int i = 0; i < 4; i++) {
#pragma unroll
                for (int j = 0; j < 4; j++) {
                    s[i][j] += qv[i].x*kv[j].x + qv[i].y*kv[j].y
                             + qv[i].z*kv[j].z + qv[i].w*kv[j].w;
                }
            }
        }
        // leaky_relu and stash in smem
#pragma unroll
        for (int i = 0; i < 4; i++) {
#pragma unroll
            for (int j = 0; j < 4; j++) {
                float v = s[i][j];
                v = (v > 0.f) ? v : 0.01f*v;
                Ps[(4*ti + i)*VPAD + 4*tj + j] = v;
            }
        }
        __syncthreads();

        // per-row running max / alpha
        if (t < QT) {
            float mx = -1e30f;
#pragma unroll 8
            for (int j = 0; j < KT; j++) mx = fmaxf(mx, Ps[t*VPAD + j]);
            float mo = m_s[t];
            float mn = fmaxf(mo, mx);
            m_s[t] = mn;
            a_s[t] = __expf(mo - mn);
        }
        __syncthreads();

        // exponentiate in place (each thread its own 4x4)
#pragma unroll
        for (int i = 0; i < 4; i++) {
            int row = 4*ti + i;
            float mrow = m_s[row];
#pragma unroll
            for (int j = 0; j < 4; j++) {
                int idx = row*VPAD + 4*tj + j;
                Ps[idx] = __expf(Ps[idx] - mrow);
            }
        }
        __syncthreads();

        // row sums update l
        if (t < QT) {
            float rs = 0.f;
#pragma unroll 8
            for (int j = 0; j < KT; j++) rs += Ps[t*VPAD + j];
            l_s[t] = l_s[t]*a_s[t] + rs;
        }

        // rescale accumulators and add P @ V
#pragma unroll
        for (int i = 0; i < 4; i++) {
            float a = a_s[4*ti + i];
#pragma unroll
            for (int j = 0; j < 4; j++) acc[i][j] *= a;
        }
        for (int j = 0; j < KT; j++) {
            float p0 = Ps[(4*ti + 0)*VPAD + j];
            float p1 = Ps[(4*ti + 1)*VPAD + j];
            float p2 = Ps[(4*ti + 2)*VPAD + j];
            float p3 = Ps[(4*ti + 3)*VPAD + j];
            float4 vv = *(const float4*)(&Vs[j*VPAD + 4*tj]);
            acc[0][0] += p0*vv.x; acc[0][1] += p0*vv.y; acc[0][2] += p0*vv.z; acc[0][3] += p0*vv.w;
            acc[1][0] += p1*vv.x; acc[1][1] += p1*vv.y; acc[1][2] += p1*vv.z; acc[1][3] += p1*vv.w;
            acc[2][0] += p2*vv.x; acc[2][1] += p2*vv.y; acc[2][2] += p2*vv.z; acc[2][3] += p2*vv.w;
            acc[3][0] += p3*vv.x; acc[3][1] += p3*vv.y; acc[3][2] += p3*vv.z; acc[3][3] += p3*vv.w;
        }
        __syncthreads();
    }

    // normalize and write A
#pragma unroll
    for (int i = 0; i < 4; i++) {
        int row = 4*ti + i;
        float inv = 1.f / l_s[row];
        float* dst = g_A + ((size_t)(b*Nn + q0 + row))*Cc + 4*tj;
        dst[0] = acc[i][0]*inv;
        dst[1] = acc[i][1]*inv;
        dst[2] = acc[i][2]*inv;
        dst[3] = acc[i][3]*inv;
    }
}

// ---------------------------------------------------------------------------
// Kernel 3: fused GRU gates + output projection. One block per row, 128 thr.
// ---------------------------------------------------------------------------
__global__ void gru_kernel(const float* __restrict__ X,
                           const float* __restrict__ Hp,
                           const float* __restrict__ W_xr, const float* __restrict__ b_xr,
                           const float* __restrict__ W_xz, const float* __restrict__ b_xz,
                           const float* __restrict__ W_xh, const float* __restrict__ b_xh,
                           const float* __restrict__ W_hh, const float* __restrict__ b_hh,
                           const float* __restrict__ W_y,  const float* __restrict__ b_y,
                           float* __restrict__ y_out, float* __restrict__ H_out) {
    int n = blockIdx.x;
    int h = threadIdx.x;   // 0..127
    __shared__ float as[Cc], xs[Cc], hps[HD], rh[HD], Hs[HD];

    if (h < Cc) { as[h] = g_A[n*Cc + h]; xs[h] = X[n*Cc + h]; }
    hps[h] = Hp[n*HD + h];
    __syncthreads();

    float r = b_xr[h], z = b_xz[h], xh = b_xh[h];
    const float* wr = W_xr + h*Cc;
    const float* wz = W_xz + h*Cc;
    const float* wh = W_xh + h*Cc;
#pragma unroll
    for (int c = 0; c < Cc; c++) {
        float a = as[c];
        r  += a     * __ldg(&wr[c]);
        z  += a     * __ldg(&wz[c]);
        xh += xs[c] * __ldg(&wh[c]);
    }
    r = 1.f / (1.f + __expf(-r));
    z = 1.f / (1.f + __expf(-z));
    rh[h] = r * hps[h];
    __syncthreads();

    float hh = b_hh[h];
    const float* whh = W_hh + h*HD;
#pragma unroll
    for (int g = 0; g < HD; g++) hh += rh[g] * __ldg(&whh[g]);

    float hc = tanhf(xh + hh);
    float Hn = z * hps[h] + (1.f - z) * hc;
    H_out[n*HD + h] = Hn;
    Hs[h] = Hn;
    __syncthreads();

    if (h < Cc) {
        float yv = b_y[h];
        const float* wy = W_y + h*HD;
#pragma unroll
        for (int g = 0; g < HD; g++) yv += Hs[g] * __ldg(&wy[g]);
        y_out[n*Cc + h] = yv;
    }
}

// ---------------------------------------------------------------------------
extern "C" void kernel_launch(void* const* d_in, const int* in_sizes, int n_in,
                              void* d_out, int out_size) {
    const float* Hp    = (const float*)d_in[0];
    const float* X     = (const float*)d_in[1];
    const float* W_xr  = (const float*)d_in[2];
    const float* b_xr  = (const float*)d_in[3];
    const float* W_xz  = (const float*)d_in[4];
    const float* b_xz  = (const float*)d_in[5];
    const float* W_xh  = (const float*)d_in[6];
    const float* b_xh  = (const float*)d_in[7];
    const float* W_hh  = (const float*)d_in[8];
    const float* b_hh  = (const float*)d_in[9];
    const float* W_ha1 = (const float*)d_in[10];
    const float* W_ha2 = (const float*)d_in[11];
    const float* b_ha2 = (const float*)d_in[12];
    const float* W_y   = (const float*)d_in[13];
    const float* b_y   = (const float*)d_in[14];

    float* out = (float*)d_out;
    float* y_out = out;                        // [B,N,C]
    float* H_out = out + (size_t)Bb*Nn*Cc;     // [B,N,Hd]

    prep_kernel<<<Bb*Nn, 128>>>(X, Hp, W_ha1, W_ha2, b_ha2);

    size_t smem = (size_t)(QT*QPAD + KT*QPAD + KT*VPAD + QT*VPAD + 3*QT) * sizeof(float);
    cudaFuncSetAttribute(attn_kernel, cudaFuncAttributeMaxDynamicSharedMemorySize, (int)smem);
    attn_kernel<<<dim3(Nn/QT, Bb), 256, smem>>>(X);

    gru_kernel<<<Bb*Nn, 128>>>(X, Hp,
                               W_xr, b_xr, W_xz, b_xz, W_xh, b_xh,
                               W_hh, b_hh, W_y, b_y, y_out, H_out);
}

// round 4
// speedup vs baseline: 1.0468x; 1.0468x over previous
#include <cuda_runtime.h>

#define Bb 8
#define Nn 2048
#define Cc 64
#define HD 128

#define QT 64
#define KT 32
#define KPAD 132   // 128 + 4, float4-aligned rows, conflict-free
#define VPAD 68    // 64 + 4
#define PPAD 36    // 32 + 4

// scratch (allocation-free rule: __device__ globals)
__device__ float g_lhs[Bb*Nn*HD];
__device__ float g_rhs[Bb*Nn*HD];
__device__ float g_A[Bb*Nn*Cc];

__device__ __forceinline__ void cp_async16(void* smem_dst, const void* gmem_src) {
    unsigned s = (unsigned)__cvta_generic_to_shared(smem_dst);
    asm volatile("cp.async.ca.shared.global [%0], [%1], 16;\n" :: "r"(s), "l"(gmem_src));
}
__device__ __forceinline__ void cp_commit() {
    asm volatile("cp.async.commit_group;\n");
}
__device__ __forceinline__ void cp_wait_all() {
    asm volatile("cp.async.wait_group 0;\n" ::: "memory");
}

// ---------------------------------------------------------------------------
// Kernel 1: lhs = X @ W_ha1^T ; rhs = H_pre @ W_ha2^T + b_ha2
// ---------------------------------------------------------------------------
__global__ void prep_kernel(const float* __restrict__ X,
                            const float* __restrict__ Hp,
                            const float* __restrict__ W_ha1,
                            const float* __restrict__ W_ha2,
                            const float* __restrict__ b_ha2) {
    int n = blockIdx.x;
    int h = threadIdx.x;
    __shared__ float xs[Cc];
    __shared__ float hs[HD];
    if (h < Cc) xs[h] = X[n*Cc + h];
    hs[h] = Hp[n*HD + h];
    __syncthreads();

    float acc1 = 0.f;
    const float* w1 = W_ha1 + h*Cc;
#pragma unroll
    for (int c = 0; c < Cc; c++) acc1 += xs[c] * __ldg(&w1[c]);

    float acc2 = b_ha2[h];
    const float* w2 = W_ha2 + h*HD;
#pragma unroll
    for (int g = 0; g < HD; g++) acc2 += hs[g] * __ldg(&w2[g]);

    g_lhs[n*HD + h] = acc1;
    g_rhs[n*HD + h] = acc2;
}

// ---------------------------------------------------------------------------
// Kernel 2: flash attention, register softmax + shuffle reductions,
// double-buffered cp.async K/V tiles, 2 CTAs/SM.
//   S = leaky_relu(lhs @ rhs^T), P = softmax_row(S), A = P @ X
// 256 threads: ti = t>>4 (0..15), tj = t&15.
// Thread owns S rows 4ti..4ti+3, S cols 2tj..2tj+1, out cols 4tj..4tj+3.
// ---------------------------------------------------------------------------
__global__ void __launch_bounds__(256, 2) attn_kernel(const float* __restrict__ X) {
    extern __shared__ float sm[];
    float* Qs = sm;                       // QT*KPAD           = 8448
    float* Ks = Qs + QT*KPAD;             // 2 * KT*KPAD       = 8448
    float* Vs = Ks + 2*KT*KPAD;           // 2 * KT*VPAD       = 4352
    float* Ps = Vs + 2*KT*VPAD;           // QT*PPAD           = 2304

    const int b  = blockIdx.y;
    const int q0 = blockIdx.x * QT;
    const int t  = threadIdx.x;
    const int ti = t >> 4;
    const int tj = t & 15;

    // ---- load Q tile (64x128) once
    const float* Qg = g_lhs + (size_t)(b*Nn + q0)*HD;
    for (int idx = t; idx < QT*(HD/4); idx += 256) {
        int r = idx >> 5, c4 = idx & 31;
        float4 v = ((const float4*)(Qg + r*HD))[c4];
        *(float4*)(&Qs[r*KPAD + c4*4]) = v;
    }

    const float* Kg = g_rhs + (size_t)b*Nn*HD;
    const float* Vg = X + (size_t)b*Nn*Cc;

    // K tile: 32 rows x 32 float4 = 1024 -> 4/thread ; V tile: 32 x 16 float4 -> 2/thread
    const int kr0 = t >> 5, kc4 = t & 31;         // K: rows kr0, kr0+8, kr0+16, kr0+24
    const int vr0 = t >> 4, vc4 = t & 15;         // V: rows vr0, vr0+16

    // prefetch tile 0 into buffer 0
    {
        const float* kg = Kg + 0;
#pragma unroll
        for (int rr = 0; rr < 4; rr++)
            cp_async16(&Ks[(kr0 + 8*rr)*KPAD + kc4*4], kg + (kr0 + 8*rr)*HD + kc4*4);
        const float* vg = Vg + 0;
#pragma unroll
        for (int rr = 0; rr < 2; rr++)
            cp_async16(&Vs[(vr0 + 16*rr)*VPAD + vc4*4], vg + (vr0 + 16*rr)*Cc + vc4*4);
        cp_commit();
    }

    float acc[4][4];
#pragma unroll
    for (int i = 0; i < 4; i++)
#pragma unroll
        for (int j = 0; j < 4; j++) acc[i][j] = 0.f;
    float m_run[4], l_run[4];
#pragma unroll
    for (int i = 0; i < 4; i++) { m_run[i] = -1e30f; l_run[i] = 0.f; }

    const int NT = Nn / KT;  // 64 tiles
    for (int it = 0; it < NT; it++) {
        const int buf = it & 1;
        float* KsB = Ks + buf*KT*KPAD;
        float* VsB = Vs + buf*KT*VPAD;

        cp_wait_all();
        __syncthreads();   // tile `it` ready; all prior-tile reads complete

        // prefetch tile it+1 into the other buffer
        if (it + 1 < NT) {
            const int k1 = (it + 1) * KT;
            float* KsN = Ks + ((it+1)&1)*KT*KPAD;
            float* VsN = Vs + ((it+1)&1)*KT*VPAD;
#pragma unroll
            for (int rr = 0; rr < 4; rr++)
                cp_async16(&KsN[(kr0 + 8*rr)*KPAD + kc4*4], Kg + (k1 + kr0 + 8*rr)*HD + kc4*4);
#pragma unroll
            for (int rr = 0; rr < 2; rr++)
                cp_async16(&VsN[(vr0 + 16*rr)*VPAD + vc4*4], Vg + (k1 + vr0 + 16*rr)*Cc + vc4*4);
            cp_commit();
        }

        // ---- S tile: rows 4ti+i, cols 2tj+j, K-dim = 128
        float s[4][2];
#pragma unroll
        for (int i = 0; i < 4; i++) { s[i][0] = 0.f; s[i][1] = 0.f; }

#pragma unroll
        for (int k = 0; k < HD; k += 4) {
            float4 qv[4], kv[2];
#pragma unroll
            for (int i = 0; i < 4; i++)
                qv[i] = *(const float4*)(&Qs[(4*ti + i)*KPAD + k]);
#pragma unroll
            for (int j = 0; j < 2; j++)
                kv[j] = *(const float4*)(&KsB[(2*tj + j)*KPAD + k]);
#pragma unroll
            for (int i = 0; i < 4; i++) {
#pragma unroll
                for (int j = 0; j < 2; j++) {
                    s[i][j] += qv[i].x*kv[j].x + qv[i].y*kv[j].y
                             + qv[i].z*kv[j].z + qv[i].w*kv[j].w;
                }
            }
        }

        // leaky_relu in regs
#pragma unroll
        for (int i = 0; i < 4; i++) {
#pragma unroll
            for (int j = 0; j < 2; j++) {
                float v = s[i][j];
                s[i][j] = (v > 0.f) ? v : 0.01f*v;
            }
        }

        // row max across the 16 lanes sharing ti (lane bits 0..3)
        float mx[4];
#pragma unroll
        for (int i = 0; i < 4; i++) mx[i] = fmaxf(s[i][0], s[i][1]);
#pragma unroll
        for (int off = 1; off < 16; off <<= 1) {
#pragma unroll
            for (int i = 0; i < 4; i++)
                mx[i] = fmaxf(mx[i], __shfl_xor_sync(0xffffffffu, mx[i], off));
        }

        float al[4];
#pragma unroll
        for (int i = 0; i < 4; i++) {
            float mn = fmaxf(m_run[i], mx[i]);
            al[i] = __expf(m_run[i] - mn);
            m_run[i] = mn;
        }

        // exp in regs, local sums
        float rs[4];
#pragma unroll
        for (int i = 0; i < 4; i++) {
            s[i][0] = __expf(s[i][0] - m_run[i]);
            s[i][1] = __expf(s[i][1] - m_run[i]);
            rs[i] = s[i][0] + s[i][1];
        }
#pragma unroll
        for (int off = 1; off < 16; off <<= 1) {
#pragma unroll
            for (int i = 0; i < 4; i++)
                rs[i] += __shfl_xor_sync(0xffffffffu, rs[i], off);
        }
#pragma unroll
        for (int i = 0; i < 4; i++) l_run[i] = l_run[i]*al[i] + rs[i];

        // rescale accumulators
#pragma unroll
        for (int i = 0; i < 4; i++) {
#pragma unroll
            for (int j = 0; j < 4; j++) acc[i][j] *= al[i];
        }

        // stash P (one float2 per row per thread)
#pragma unroll
        for (int i = 0; i < 4; i++)
            *(float2*)(&Ps[(4*ti + i)*PPAD + 2*tj]) = make_float2(s[i][0], s[i][1]);
        __syncthreads();

        // ---- PV: acc[i][*] += sum_j P[row, j] * V[j, 4tj..4tj+3]
#pragma unroll
        for (int j0 = 0; j0 < KT; j0 += 4) {
            float4 pv[4], vv[4];
#pragma unroll
            for (int i = 0; i < 4; i++)
                pv[i] = *(const float4*)(&Ps[(4*ti + i)*PPAD + j0]);
#pragma unroll
            for (int jj = 0; jj < 4; jj++)
                vv[jj] = *(const float4*)(&VsB[(j0 + jj)*VPAD + 4*tj]);
#pragma unroll
            for (int i = 0; i < 4; i++) {
                acc[i][0] += pv[i].x*vv[0].x + pv[i].y*vv[1].x + pv[i].z*vv[2].x + pv[i].w*vv[3].x;
                acc[i][1] += pv[i].x*vv[0].y + pv[i].y*vv[1].y + pv[i].z*vv[2].y + pv[i].w*vv[3].y;
                acc[i][2] += pv[i].x*vv[0].z + pv[i].y*vv[1].z + pv[i].z*vv[2].z + pv[i].w*vv[3].z;
                acc[i][3] += pv[i].x*vv[0].w + pv[i].y*vv[1].w + pv[i].z*vv[2].w + pv[i].w*vv[3].w;
            }
        }
        __syncthreads();   // PV done before next prefetch overwrites / Ps rewrite
    }

    // normalize and write A
#pragma unroll
    for (int i = 0; i < 4; i++) {
        int row = 4*ti + i;
        float inv = 1.f / l_run[i];
        float4 o;
        o.x = acc[i][0]*inv; o.y = acc[i][1]*inv; o.z = acc[i][2]*inv; o.w = acc[i][3]*inv;
        *(float4*)(&g_A[((size_t)(b*Nn + q0 + row))*Cc + 4*tj]) = o;
    }
}

// ---------------------------------------------------------------------------
// Kernel 3: fused GRU gates + output projection. One block per row, 128 thr.
// ---------------------------------------------------------------------------
__global__ void gru_kernel(const float* __restrict__ X,
                           const float* __restrict__ Hp,
                           const float* __restrict__ W_xr, const float* __restrict__ b_xr,
                           const float* __restrict__ W_xz, const float* __restrict__ b_xz,
                           const float* __restrict__ W_xh, const float* __restrict__ b_xh,
                           const float* __restrict__ W_hh, const float* __restrict__ b_hh,
                           const float* __restrict__ W_y,  const float* __restrict__ b_y,
                           float* __restrict__ y_out, float* __restrict__ H_out) {
    int n = blockIdx.x;
    int h = threadIdx.x;   // 0..127
    __shared__ float as[Cc], xs[Cc], hps[HD], rh[HD], Hs[HD];

    if (h < Cc) { as[h] = g_A[n*Cc + h]; xs[h] = X[n*Cc + h]; }
    hps[h] = Hp[n*HD + h];
    __syncthreads();

    float r = b_xr[h], z = b_xz[h], xh = b_xh[h];
    const float* wr = W_xr + h*Cc;
    const float* wz = W_xz + h*Cc;
    const float* wh = W_xh + h*Cc;
#pragma unroll
    for (int c = 0; c < Cc; c++) {
        float a = as[c];
        r  += a     * __ldg(&wr[c]);
        z  += a     * __ldg(&wz[c]);
        xh += xs[c] * __ldg(&wh[c]);
    }
    r = 1.f / (1.f + __expf(-r));
    z = 1.f / (1.f + __expf(-z));
    rh[h] = r * hps[h];
    __syncthreads();

    float hh = b_hh[h];
    const float* whh = W_hh + h*HD;
#pragma unroll
    for (int g = 0; g < HD; g++) hh += rh[g] * __ldg(&whh[g]);

    float hc = tanhf(xh + hh);
    float Hn = z * hps[h] + (1.f - z) * hc;
    H_out[n*HD + h] = Hn;
    Hs[h] = Hn;
    __syncthreads();

    if (h < Cc) {
        float yv = b_y[h];
        const float* wy = W_y + h*HD;
#pragma unroll
        for (int g = 0; g < HD; g++) yv += Hs[g] * __ldg(&wy[g]);
        y_out[n*Cc + h] = yv;
    }
}

// ---------------------------------------------------------------------------
extern "C" void kernel_launch(void* const* d_in, const int* in_sizes, int n_in,
                              void* d_out, int out_size) {
    const float* Hp    = (const float*)d_in[0];
    const float* X     = (const float*)d_in[1];
    const float* W_xr  = (const float*)d_in[2];
    const float* b_xr  = (const float*)d_in[3];
    const float* W_xz  = (const float*)d_in[4];
    const float* b_xz  = (const float*)d_in[5];
    const float* W_xh  = (const float*)d_in[6];
    const float* b_xh  = (const float*)d_in[7];
    const float* W_hh  = (const float*)d_in[8];
    const float* b_hh  = (const float*)d_in[9];
    const float* W_ha1 = (const float*)d_in[10];
    const float* W_ha2 = (const float*)d_in[11];
    const float* b_ha2 = (const float*)d_in[12];
    const float* W_y   = (const float*)d_in[13];
    const float* b_y   = (const float*)d_in[14];

    float* out = (float*)d_out;
    float* y_out = out;                        // [B,N,C]
    float* H_out = out + (size_t)Bb*Nn*Cc;     // [B,N,Hd]

    prep_kernel<<<Bb*Nn, 128>>>(X, Hp, W_ha1, W_ha2, b_ha2);

    size_t smem = (size_t)(QT*KPAD + 2*KT*KPAD + 2*KT*VPAD + QT*PPAD) * sizeof(float);
    cudaFuncSetAttribute(attn_kernel, cudaFuncAttributeMaxDynamicSharedMemorySize, (int)smem);
    attn_kernel<<<dim3(Nn/QT, Bb), 256, smem>>>(X);

    gru_kernel<<<Bb*Nn, 128>>>(X, Hp,
                               W_xr, b_xr, W_xz, b_xz, W_xh, b_xh,
                               W_hh, b_hh, W_y, b_y, y_out, H_out);
}

// round 6
// speedup vs baseline: 8.2977x; 7.9269x over previous
#include <cuda_runtime.h>

#define Bb 8
#define Nn 2048
#define Cc 64
#define HD 128

#define QT 64
#define KT 32
#define KPAD 132   // 128 + 4: row stride 132 floats -> consecutive rows 4 banks apart
#define VPAD 68
#define PPAD 36

#define GR 4       // rows per block in prep/gru (weight-load amortization)

// scratch (allocation-free rule: __device__ globals)
__device__ float g_lhs[Bb*Nn*HD];
__device__ float g_rhs[Bb*Nn*HD];
__device__ float g_A[Bb*Nn*Cc];

// transposed weights (c-major so lane-consecutive h is coalesced)
__device__ float WT_xr[Cc*HD];    // [c][h]
__device__ float WT_xz[Cc*HD];
__device__ float WT_xh[Cc*HD];
__device__ float WT_hh[HD*HD];    // [g][h]
__device__ float WT_ha1[Cc*HD];   // [c][h]
__device__ float WT_ha2[HD*HD];   // [g][h]
__device__ float WT_y[HD*Cc];     // [g][c]

__device__ __forceinline__ void cp_async16(void* smem_dst, const void* gmem_src) {
    unsigned s = (unsigned)__cvta_generic_to_shared(smem_dst);
    asm volatile("cp.async.ca.shared.global [%0], [%1], 16;\n" :: "r"(s), "l"(gmem_src));
}
__device__ __forceinline__ void cp_commit() {
    asm volatile("cp.async.commit_group;\n");
}
__device__ __forceinline__ void cp_wait_all() {
    asm volatile("cp.async.wait_group 0;\n" ::: "memory");
}

// ---------------------------------------------------------------------------
// Kernel 0: generic transpose  dst[c*R + r] = src[r*C + c]   (tiny matrices)
// ---------------------------------------------------------------------------
__global__ void transpose_kernel(const float* __restrict__ src, float* __restrict__ dst,
                                 int R, int C) {
    int i = blockIdx.x * 256 + threadIdx.x;
    if (i < R*C) {
        int r = i / C, c = i - r*C;
        dst[c*R + r] = src[i];
    }
}

// ---------------------------------------------------------------------------
// Kernel 1: lhs = X @ W_ha1^T ; rhs = H_pre @ W_ha2^T + b_ha2
// GR rows per block, 128 threads (one output h each), coalesced WT loads.
// ---------------------------------------------------------------------------
__global__ void prep_kernel(const float* __restrict__ X,
                            const float* __restrict__ Hp,
                            const float* __restrict__ b_ha2) {
    const int n0 = blockIdx.x * GR;
    const int h  = threadIdx.x;
    __shared__ float xs[GR][Cc];
    __shared__ float hs[GR][HD];
#pragma unroll
    for (int r = 0; r < GR; r++) {
        if (h < Cc) xs[r][h] = X[(n0+r)*Cc + h];
        hs[r][h] = Hp[(size_t)(n0+r)*HD + h];
    }
    __syncthreads();

    float a1[GR], a2[GR];
    float b2 = b_ha2[h];
#pragma unroll
    for (int r = 0; r < GR; r++) { a1[r] = 0.f; a2[r] = b2; }

#pragma unroll
    for (int c = 0; c < Cc; c++) {
        float w = WT_ha1[c*HD + h];
#pragma unroll
        for (int r = 0; r < GR; r++) a1[r] += xs[r][c] * w;
    }
#pragma unroll
    for (int g = 0; g < HD; g++) {
        float w = WT_ha2[g*HD + h];
#pragma unroll
        for (int r = 0; r < GR; r++) a2[r] += hs[r][g] * w;
    }
#pragma unroll
    for (int r = 0; r < GR; r++) {
        g_lhs[(size_t)(n0+r)*HD + h] = a1[r];
        g_rhs[(size_t)(n0+r)*HD + h] = a2[r];
    }
}

// ---------------------------------------------------------------------------
// Kernel 2: flash attention.
// Thread owns S rows 4ti..4ti+3 and S cols {tj, tj+16}  (bank-conflict fix:
// row stride 132 floats -> 16 K-row addresses land on 8 bank-groups, degree 2,
// instead of 4 groups / degree 4 with the old {2tj,2tj+1} mapping).
// ---------------------------------------------------------------------------
__global__ void __launch_bounds__(256, 2) attn_kernel(const float* __restrict__ X) {
    extern __shared__ float sm[];
    float* Qs = sm;                       // QT*KPAD
    float* Ks = Qs + QT*KPAD;             // 2 * KT*KPAD
    float* Vs = Ks + 2*KT*KPAD;           // 2 * KT*VPAD
    float* Ps = Vs + 2*KT*VPAD;           // QT*PPAD

    const int b  = blockIdx.y;
    const int q0 = blockIdx.x * QT;
    const int t  = threadIdx.x;
    const int ti = t >> 4;
    const int tj = t & 15;

    const float* Qg = g_lhs + (size_t)(b*Nn + q0)*HD;
    for (int idx = t; idx < QT*(HD/4); idx += 256) {
        int r = idx >> 5, c4 = idx & 31;
        float4 v = ((const float4*)(Qg + r*HD))[c4];
        *(float4*)(&Qs[r*KPAD + c4*4]) = v;
    }

    const float* Kg = g_rhs + (size_t)b*Nn*HD;
    const float* Vg = X + (size_t)b*Nn*Cc;

    const int kr0 = t >> 5, kc4 = t & 31;
    const int vr0 = t >> 4, vc4 = t & 15;

    {
#pragma unroll
        for (int rr = 0; rr < 4; rr++)
            cp_async16(&Ks[(kr0 + 8*rr)*KPAD + kc4*4], Kg + (kr0 + 8*rr)*HD + kc4*4);
#pragma unroll
        for (int rr = 0; rr < 2; rr++)
            cp_async16(&Vs[(vr0 + 16*rr)*VPAD + vc4*4], Vg + (vr0 + 16*rr)*Cc + vc4*4);
        cp_commit();
    }

    float acc[4][4];
#pragma unroll
    for (int i = 0; i < 4; i++)
#pragma unroll
        for (int j = 0; j < 4; j++) acc[i][j] = 0.f;
    float m_run[4], l_run[4];
#pragma unroll
    for (int i = 0; i < 4; i++) { m_run[i] = -1e30f; l_run[i] = 0.f; }

    const int NT = Nn / KT;
    for (int it = 0; it < NT; it++) {
        const int buf = it & 1;
        float* KsB = Ks + buf*KT*KPAD;
        float* VsB = Vs + buf*KT*VPAD;

        cp_wait_all();
        __syncthreads();

        if (it + 1 < NT) {
            const int k1 = (it + 1) * KT;
            float* KsN = Ks + ((it+1)&1)*KT*KPAD;
            float* VsN = Vs + ((it+1)&1)*KT*VPAD;
#pragma unroll
            for (int rr = 0; rr < 4; rr++)
                cp_async16(&KsN[(kr0 + 8*rr)*KPAD + kc4*4], Kg + (k1 + kr0 + 8*rr)*HD + kc4*4);
#pragma unroll
            for (int rr = 0; rr < 2; rr++)
                cp_async16(&VsN[(vr0 + 16*rr)*VPAD + vc4*4], Vg + (k1 + vr0 + 16*rr)*Cc + vc4*4);
            cp_commit();
        }

        // ---- S tile: rows 4ti+i, cols {tj, tj+16}
        float s[4][2];
#pragma unroll
        for (int i = 0; i < 4; i++) { s[i][0] = 0.f; s[i][1] = 0.f; }

#pragma unroll
        for (int k = 0; k < HD; k += 4) {
            float4 qv[4], kv[2];
#pragma unroll
            for (int i = 0; i < 4; i++)
                qv[i] = *(const float4*)(&Qs[(4*ti + i)*KPAD + k]);
#pragma unroll
            for (int j = 0; j < 2; j++)
                kv[j] = *(const float4*)(&KsB[(tj + 16*j)*KPAD + k]);
#pragma unroll
            for (int i = 0; i < 4; i++) {
#pragma unroll
                for (int j = 0; j < 2; j++) {
                    s[i][j] += qv[i].x*kv[j].x + qv[i].y*kv[j].y
                             + qv[i].z*kv[j].z + qv[i].w*kv[j].w;
                }
            }
        }

#pragma unroll
        for (int i = 0; i < 4; i++) {
#pragma unroll
            for (int j = 0; j < 2; j++) {
                float v = s[i][j];
                s[i][j] = (v > 0.f) ? v : 0.01f*v;
            }
        }

        float mx[4];
#pragma unroll
        for (int i = 0; i < 4; i++) mx[i] = fmaxf(s[i][0], s[i][1]);
#pragma unroll
        for (int off = 1; off < 16; off <<= 1) {
#pragma unroll
            for (int i = 0; i < 4; i++)
                mx[i] = fmaxf(mx[i], __shfl_xor_sync(0xffffffffu, mx[i], off));
        }

        float al[4];
#pragma unroll
        for (int i = 0; i < 4; i++) {
            float mn = fmaxf(m_run[i], mx[i]);
            al[i] = __expf(m_run[i] - mn);
            m_run[i] = mn;
        }

        float rs[4];
#pragma unroll
        for (int i = 0; i < 4; i++) {
            s[i][0] = __expf(s[i][0] - m_run[i]);
            s[i][1] = __expf(s[i][1] - m_run[i]);
            rs[i] = s[i][0] + s[i][1];
        }
#pragma unroll
        for (int off = 1; off < 16; off <<= 1) {
#pragma unroll
            for (int i = 0; i < 4; i++)
                rs[i] += __shfl_xor_sync(0xffffffffu, rs[i], off);
        }
#pragma unroll
        for (int i = 0; i < 4; i++) l_run[i] = l_run[i]*al[i] + rs[i];

#pragma unroll
        for (int i = 0; i < 4; i++) {
#pragma unroll
            for (int j = 0; j < 4; j++) acc[i][j] *= al[i];
        }

        // stash P: col index == key index within tile
#pragma unroll
        for (int i = 0; i < 4; i++) {
            Ps[(4*ti + i)*PPAD + tj]      = s[i][0];
            Ps[(4*ti + i)*PPAD + tj + 16] = s[i][1];
        }
        __syncthreads();

        // ---- PV
#pragma unroll
        for (int j0 = 0; j0 < KT; j0 += 4) {
            float4 pv[4], vv[4];
#pragma unroll
            for (int i = 0; i < 4; i++)
                pv[i] = *(const float4*)(&Ps[(4*ti + i)*PPAD + j0]);
#pragma unroll
            for (int jj = 0; jj < 4; jj++)
                vv[jj] = *(const float4*)(&VsB[(j0 + jj)*VPAD + 4*tj]);
#pragma unroll
            for (int i = 0; i < 4; i++) {
                acc[i][0] += pv[i].x*vv[0].x + pv[i].y*vv[1].x + pv[i].z*vv[2].x + pv[i].w*vv[3].x;
                acc[i][1] += pv[i].x*vv[0].y + pv[i].y*vv[1].y + pv[i].z*vv[2].y + pv[i].w*vv[3].y;
                acc[i][2] += pv[i].x*vv[0].z + pv[i].y*vv[1].z + pv[i].z*vv[2].z + pv[i].w*vv[3].z;
                acc[i][3] += pv[i].x*vv[0].w + pv[i].y*vv[1].w + pv[i].z*vv[2].w + pv[i].w*vv[3].w;
            }
        }
        __syncthreads();
    }

#pragma unroll
    for (int i = 0; i < 4; i++) {
        int row = 4*ti + i;
        float inv = 1.f / l_run[i];
        float4 o;
        o.x = acc[i][0]*inv; o.y = acc[i][1]*inv; o.z = acc[i][2]*inv; o.w = acc[i][3]*inv;
        *(float4*)(&g_A[((size_t)(b*Nn + q0 + row))*Cc + 4*tj]) = o;
    }
}

// ---------------------------------------------------------------------------
// Kernel 3: fused GRU gates + output projection.
// GR rows per block, 128 threads, coalesced transposed-weight loads,
// each weight element reused for GR rows.
// ---------------------------------------------------------------------------
__global__ void gru_kernel(const float* __restrict__ X,
                           const float* __restrict__ Hp,
                           const float* __restrict__ b_xr,
                           const float* __restrict__ b_xz,
                           const float* __restrict__ b_xh,
                           const float* __restrict__ b_hh,
                           const float* __restrict__ b_y,
                           float* __restrict__ y_out, float* __restrict__ H_out) {
    const int n0 = blockIdx.x * GR;
    const int h  = threadIdx.x;   // 0..127
    __shared__ float as[GR][Cc], xs[GR][Cc], hps[GR][HD], rh[GR][HD], Hs[GR][HD];

#pragma unroll
    for (int r = 0; r < GR; r++) {
        if (h < Cc) {
            as[r][h] = g_A[(size_t)(n0+r)*Cc + h];
            xs[r][h] = X[(size_t)(n0+r)*Cc + h];
        }
        hps[r][h] = Hp[(size_t)(n0+r)*HD + h];
    }
    __syncthreads();

    float rr[GR], zz[GR], xh[GR];
    {
        float br = b_xr[h], bz = b_xz[h], bh = b_xh[h];
#pragma unroll
        for (int r = 0; r < GR; r++) { rr[r] = br; zz[r] = bz; xh[r] = bh; }
    }

#pragma unroll
    for (int c = 0; c < Cc; c++) {
        float wr = WT_xr[c*HD + h];
        float wz = WT_xz[c*HD + h];
        float wh = WT_xh[c*HD + h];
#pragma unroll
        for (int r = 0; r < GR; r++) {
            float a = as[r][c];
            rr[r] += a * wr;
            zz[r] += a * wz;
            xh[r] += xs[r][c] * wh;
        }
    }
#pragma unroll
    for (int r = 0; r < GR; r++) {
        float rv = 1.f / (1.f + __expf(-rr[r]));
        rh[r][h] = rv * hps[r][h];
    }
    __syncthreads();

    float hh[GR];
    {
        float bh = b_hh[h];
#pragma unroll
        for (int r = 0; r < GR; r++) hh[r] = bh;
    }
#pragma unroll
    for (int g = 0; g < HD; g++) {
        float w = WT_hh[g*HD + h];
#pragma unroll
        for (int r = 0; r < GR; r++) hh[r] += rh[r][g] * w;
    }
#pragma unroll
    for (int r = 0; r < GR; r++) {
        float z  = 1.f / (1.f + __expf(-zz[r]));
        float hc = tanhf(xh[r] + hh[r]);
        float Hn = z * hps[r][h] + (1.f - z) * hc;
        H_out[(size_t)(n0+r)*HD + h] = Hn;
        Hs[r][h] = Hn;
    }
    __syncthreads();

    if (h < Cc) {
        float yv[GR];
        float by = b_y[h];
#pragma unroll
        for (int r = 0; r < GR; r++) yv[r] = by;
#pragma unroll
        for (int g = 0; g < HD; g++) {
            float w = WT_y[g*Cc + h];
#pragma unroll
            for (int r = 0; r < GR; r++) yv[r] += Hs[r][g] * w;
        }
#pragma unroll
        for (int r = 0; r < GR; r++)
            y_out[(size_t)(n0+r)*Cc + h] = yv[r];
    }
}

// ---------------------------------------------------------------------------
extern "C" void kernel_launch(void* const* d_in, const int* in_sizes, int n_in,
                              void* d_out, int out_size) {
    const float* Hp    = (const float*)d_in[0];
    const float* X     = (const float*)d_in[1];
    const float* W_xr  = (const float*)d_in[2];
    const float* b_xr  = (const float*)d_in[3];
    const float* W_xz  = (const float*)d_in[4];
    const float* b_xz  = (const float*)d_in[5];
    const float* W_xh  = (const float*)d_in[6];
    const float* b_xh  = (const float*)d_in[7];
    const float* W_hh  = (const float*)d_in[8];
    const float* b_hh  = (const float*)d_in[9];
    const float* W_ha1 = (const float*)d_in[10];
    const float* W_ha2 = (const float*)d_in[11];
    const float* b_ha2 = (const float*)d_in[12];
    const float* W_y   = (const float*)d_in[13];
    const float* b_y   = (const float*)d_in[14];

    float* out = (float*)d_out;
    float* y_out = out;                        // [B,N,C]
    float* H_out = out + (size_t)Bb*Nn*Cc;     // [B,N,Hd]

    float *wt_xr, *wt_xz, *wt_xh, *wt_hh, *wt_ha1, *wt_ha2, *wt_y;
    cudaGetSymbolAddress((void**)&wt_xr,  WT_xr);
    cudaGetSymbolAddress((void**)&wt_xz,  WT_xz);
    cudaGetSymbolAddress((void**)&wt_xh,  WT_xh);
    cudaGetSymbolAddress((void**)&wt_hh,  WT_hh);
    cudaGetSymbolAddress((void**)&wt_ha1, WT_ha1);
    cudaGetSymbolAddress((void**)&wt_ha2, WT_ha2);
    cudaGetSymbolAddress((void**)&wt_y,   WT_y);

    // weights: W[out][in] row-major -> WT[in][out]
    transpose_kernel<<<(HD*Cc + 255)/256, 256>>>(W_xr,  wt_xr,  HD, Cc);
    transpose_kernel<<<(HD*Cc + 255)/256, 256>>>(W_xz,  wt_xz,  HD, Cc);
    transpose_kernel<<<(HD*Cc + 255)/256, 256>>>(W_xh,  wt_xh,  HD, Cc);
    transpose_kernel<<<(HD*HD + 255)/256, 256>>>(W_hh,  wt_hh,  HD, HD);
    transpose_kernel<<<(HD*Cc + 255)/256, 256>>>(W_ha1, wt_ha1, HD, Cc);
    transpose_kernel<<<(HD*HD + 255)/256, 256>>>(W_ha2, wt_ha2, HD, HD);
    transpose_kernel<<<(Cc*HD + 255)/256, 256>>>(W_y,   wt_y,   Cc, HD);

    prep_kernel<<<Bb*Nn/GR, 128>>>(X, Hp, b_ha2);

    size_t smem = (size_t)(QT*KPAD + 2*KT*KPAD + 2*KT*VPAD + QT*PPAD) * sizeof(float);
    cudaFuncSetAttribute(attn_kernel, cudaFuncAttributeMaxDynamicSharedMemorySize, (int)smem);
    attn_kernel<<<dim3(Nn/QT, Bb), 256, smem>>>(X);

    gru_kernel<<<Bb*Nn/GR, 128>>>(X, Hp, b_xr, b_xz, b_xh, b_hh, b_y, y_out, H_out);
}

// round 8
// speedup vs baseline: 18.8338x; 2.2698x over previous
#include <cuda_runtime.h>

#define Bb 8
#define Nn 2048
#define Cc 64
#define HD 128

#define QT 64      // queries per block (4 warps x 16 rows)
#define KT 32      // keys per tile
#define KPAD 132   // K/Q smem row stride (words): frag banks (4g+q) -> conflict-free
#define VPAD 72    // V smem row stride: frag banks (8q+g) -> conflict-free
#define PPAD 36    // P smem row stride: frag banks (4g+q) -> conflict-free

#define GR 4       // rows per block in prep/gru

// scratch (allocation-free rule: __device__ globals)
__device__ float g_lhs[Bb*Nn*HD];   // tf32-rounded Q
__device__ float g_rhs[Bb*Nn*HD];   // tf32-rounded K
__device__ float g_Xc[Bb*Nn*Cc];    // tf32-rounded X (V operand)
__device__ float g_A[Bb*Nn*Cc];

// transposed weights (in-major so lane-consecutive h is coalesced)
__device__ float WT_xr[Cc*HD];
__device__ float WT_xz[Cc*HD];
__device__ float WT_xh[Cc*HD];
__device__ float WT_hh[HD*HD];
__device__ float WT_ha1[Cc*HD];
__device__ float WT_ha2[HD*HD];
__device__ float WT_y[HD*Cc];

__device__ __forceinline__ void cp_async16(void* smem_dst, const void* gmem_src) {
    unsigned s = (unsigned)__cvta_generic_to_shared(smem_dst);
    asm volatile("cp.async.ca.shared.global [%0], [%1], 16;\n" :: "r"(s), "l"(gmem_src));
}
__device__ __forceinline__ void cp_commit() {
    asm volatile("cp.async.commit_group;\n");
}
__device__ __forceinline__ void cp_wait_all() {
    asm volatile("cp.async.wait_group 0;\n" ::: "memory");
}

__device__ __forceinline__ float to_tf32(float x) {
    unsigned u;
    asm("cvt.rna.tf32.f32 %0, %1;" : "=r"(u) : "f"(x));
    return __uint_as_float(u);
}

// D += A(16x8,row) * B(8x8,col)   tf32 inputs, f32 accum
__device__ __forceinline__ void mma8(float* c, const unsigned* a, unsigned b0, unsigned b1) {
    asm volatile(
        "mma.sync.aligned.m16n8k8.row.col.f32.tf32.tf32.f32 "
        "{%0,%1,%2,%3}, {%4,%5,%6,%7}, {%8,%9}, {%0,%1,%2,%3};\n"
        : "+f"(c[0]), "+f"(c[1]), "+f"(c[2]), "+f"(c[3])
        : "r"(a[0]), "r"(a[1]), "r"(a[2]), "r"(a[3]), "r"(b0), "r"(b1));
}

// ---------------------------------------------------------------------------
// Kernel 0: all 7 weight transposes in one launch.
// flat ranges: xr[0,8192) xz[8192,16384) xh[16384,24576) hh[24576,40960)
//              ha1[40960,49152) ha2[49152,65536) y[65536,73728)
// ---------------------------------------------------------------------------
__global__ void transpose_all(const float* __restrict__ W_xr, const float* __restrict__ W_xz,
                              const float* __restrict__ W_xh, const float* __restrict__ W_hh,
                              const float* __restrict__ W_ha1, const float* __restrict__ W_ha2,
                              const float* __restrict__ W_y) {
    int i = blockIdx.x * 256 + threadIdx.x;
    const float* src; float* dst; int R, C, off;
    if      (i < 8192)  { src = W_xr;  dst = WT_xr;  R = HD; C = Cc; off = 0; }
    else if (i < 16384) { src = W_xz;  dst = WT_xz;  R = HD; C = Cc; off = 8192; }
    else if (i < 24576) { src = W_xh;  dst = WT_xh;  R = HD; C = Cc; off = 16384; }
    else if (i < 40960) { src = W_hh;  dst = WT_hh;  R = HD; C = HD; off = 24576; }
    else if (i < 49152) { src = W_ha1; dst = WT_ha1; R = HD; C = Cc; off = 40960; }
    else if (i < 65536) { src = W_ha2; dst = WT_ha2; R = HD; C = HD; off = 49152; }
    else if (i < 73728) { src = W_y;   dst = WT_y;   R = Cc; C = HD; off = 65536; }
    else return;
    int j = i - off;
    int r = j / C, c = j - r*C;
    dst[c*R + r] = src[j];
}

// ---------------------------------------------------------------------------
// Kernel 1: lhs = tf32(X @ W_ha1^T) ; rhs = tf32(H_pre @ W_ha2^T + b_ha2)
//           g_Xc = tf32(X)
// ---------------------------------------------------------------------------
__global__ void prep_kernel(const float* __restrict__ X,
                            const float* __restrict__ Hp,
                            const float* __restrict__ b_ha2) {
    const int n0 = blockIdx.x * GR;
    const int h  = threadIdx.x;
    __shared__ float xs[GR][Cc];
    __shared__ float hs[GR][HD];
#pragma unroll
    for (int r = 0; r < GR; r++) {
        if (h < Cc) {
            float xv = X[(size_t)(n0+r)*Cc + h];
            xs[r][h] = xv;
            g_Xc[(size_t)(n0+r)*Cc + h] = to_tf32(xv);
        }
        hs[r][h] = Hp[(size_t)(n0+r)*HD + h];
    }
    __syncthreads();

    float a1[GR], a2[GR];
    float b2 = b_ha2[h];
#pragma unroll
    for (int r = 0; r < GR; r++) { a1[r] = 0.f; a2[r] = b2; }

#pragma unroll
    for (int c = 0; c < Cc; c++) {
        float w = WT_ha1[c*HD + h];
#pragma unroll
        for (int r = 0; r < GR; r++) a1[r] += xs[r][c] * w;
    }
#pragma unroll
    for (int g = 0; g < HD; g++) {
        float w = WT_ha2[g*HD + h];
#pragma unroll
        for (int r = 0; r < GR; r++) a2[r] += hs[r][g] * w;
    }
#pragma unroll
    for (int r = 0; r < GR; r++) {
        g_lhs[(size_t)(n0+r)*HD + h] = to_tf32(a1[r]);
        g_rhs[(size_t)(n0+r)*HD + h] = to_tf32(a2[r]);
    }
}

// ---------------------------------------------------------------------------
// Kernel 2: flash attention on mma.sync tf32.
// 128 threads = 4 warps; warp w owns Q rows 16w..16w+15.
// Q fragments register-resident (16 kchunks x 4 regs).
// Per KV tile (32 keys): S = Q@K^T (64 MMAs), reg softmax (quad shuffles),
// P via per-warp smem, O += P@V (32 MMAs). Double-buffered cp.async K/V.
// ---------------------------------------------------------------------------
__global__ void __launch_bounds__(128) attn_kernel() {
    extern __shared__ float sm[];
    float* Kb0 = sm;                    // 32*132 = 4224
    float* Vb0 = Kb0 + KT*KPAD;         // 32*72  = 2304
    float* Kb1 = Vb0 + KT*VPAD;         // 4224
    float* Vb1 = Kb1 + KT*KPAD;         // 2304
    float* Ps  = Vb1 + KT*VPAD;         // 64*36  = 2304   (total 15360 floats)
    float* Qstage = Kb1;                // 64*132 = 8448 <= 8832 (Kb1+Vb1+Ps region)

    const int b  = blockIdx.y;
    const int q0 = blockIdx.x * QT;
    const int t  = threadIdx.x;
    const int w  = t >> 5;
    const int lane = t & 31;
    const int g = lane >> 2;   // 0..7
    const int q = lane & 3;    // 0..3

    const float* Kg = g_rhs + (size_t)b*Nn*HD;
    const float* Vg = g_Xc  + (size_t)b*Nn*Cc;

    // ---- prefetch KV tile 0 into buffer 0
    {
        const int kr = t >> 2, kc = t & 3;      // K: 32 rows x 32 f4
#pragma unroll
        for (int i = 0; i < 8; i++)
            cp_async16(&Kb0[kr*KPAD + (kc + 4*i)*4], Kg + kr*HD + (kc + 4*i)*4);
#pragma unroll
        for (int i = 0; i < 4; i++)             // V: 32 rows x 16 f4
            cp_async16(&Vb0[kr*VPAD + (kc + 4*i)*4], Vg + kr*Cc + (kc + 4*i)*4);
        cp_commit();
    }

    // ---- stage Q tile and build register fragments
    {
        const float* Qg = g_lhs + (size_t)(b*Nn + q0)*HD;
        for (int idx = t; idx < QT*(HD/4); idx += 128) {
            int r = idx >> 5, c4 = idx & 31;
            float4 v = ((const float4*)(Qg + r*HD))[c4];
            *(float4*)(&Qstage[r*KPAD + c4*4]) = v;
        }
    }
    __syncthreads();

    unsigned qf[16][4];
#pragma unroll
    for (int kk = 0; kk < 16; kk++) {
        qf[kk][0] = __float_as_uint(Qstage[(16*w + g    )*KPAD + 8*kk + q    ]);
        qf[kk][1] = __float_as_uint(Qstage[(16*w + g + 8)*KPAD + 8*kk + q    ]);
        qf[kk][2] = __float_as_uint(Qstage[(16*w + g    )*KPAD + 8*kk + q + 4]);
        qf[kk][3] = __float_as_uint(Qstage[(16*w + g + 8)*KPAD + 8*kk + q + 4]);
    }
    __syncthreads();   // all warps done with Qstage before tile-1 prefetch reuses it

    float oacc[8][4];
#pragma unroll
    for (int c = 0; c < 8; c++)
#pragma unroll
        for (int j = 0; j < 4; j++) oacc[c][j] = 0.f;
    float m0 = -1e30f, m1 = -1e30f, l0 = 0.f, l1 = 0.f;

    float* Pw = Ps + 16*w*PPAD;   // per-warp P region (16 x 32)

    const int NT = Nn / KT;  // 64
    for (int it = 0; it < NT; it++) {
        float* KsB = (it & 1) ? Kb1 : Kb0;
        float* VsB = (it & 1) ? Vb1 : Vb0;

        cp_wait_all();
        __syncthreads();

        if (it + 1 < NT) {
            float* KsN = (it & 1) ? Kb0 : Kb1;
            float* VsN = (it & 1) ? Vb0 : Vb1;
            const int k1 = (it + 1) * KT;
            const int kr = t >> 2, kc = t & 3;
#pragma unroll
            for (int i = 0; i < 8; i++)
                cp_async16(&KsN[kr*KPAD + (kc + 4*i)*4], Kg + (k1 + kr)*HD + (kc + 4*i)*4);
#pragma unroll
            for (int i = 0; i < 4; i++)
                cp_async16(&VsN[kr*VPAD + (kc + 4*i)*4], Vg + (k1 + kr)*Cc + (kc + 4*i)*4);
            cp_commit();
        }

        // ---- S = Q @ K^T : sacc[cc] covers keys 8cc..8cc+7
        float sacc[4][4];
#pragma unroll
        for (int c = 0; c < 4; c++)
#pragma unroll
            for (int j = 0; j < 4; j++) sacc[c][j] = 0.f;

#pragma unroll
        for (int kk = 0; kk < 16; kk++) {
#pragma unroll
            for (int cc = 0; cc < 4; cc++) {
                unsigned b0 = __float_as_uint(KsB[(8*cc + g)*KPAD + 8*kk + q    ]);
                unsigned b1 = __float_as_uint(KsB[(8*cc + g)*KPAD + 8*kk + q + 4]);
                mma8(sacc[cc], qf[kk], b0, b1);
            }
        }

        // ---- leaky_relu + online softmax (rows g and g+8; cols 2q+8cc+{0,1})
#pragma unroll
        for (int c = 0; c < 4; c++)
#pragma unroll
            for (int j = 0; j < 4; j++) {
                float v = sacc[c][j];
                sacc[c][j] = (v > 0.f) ? v : 0.01f*v;
            }

        float mx0 = -1e30f, mx1 = -1e30f;
#pragma unroll
        for (int c = 0; c < 4; c++) {
            mx0 = fmaxf(mx0, fmaxf(sacc[c][0], sacc[c][1]));
            mx1 = fmaxf(mx1, fmaxf(sacc[c][2], sacc[c][3]));
        }
        mx0 = fmaxf(mx0, __shfl_xor_sync(0xffffffffu, mx0, 1));
        mx0 = fmaxf(mx0, __shfl_xor_sync(0xffffffffu, mx0, 2));
        mx1 = fmaxf(mx1, __shfl_xor_sync(0xffffffffu, mx1, 1));
        mx1 = fmaxf(mx1, __shfl_xor_sync(0xffffffffu, mx1, 2));

        float mn0 = fmaxf(m0, mx0), mn1 = fmaxf(m1, mx1);
        float al0 = __expf(m0 - mn0), al1 = __expf(m1 - mn1);
        m0 = mn0; m1 = mn1;

        float rs0 = 0.f, rs1 = 0.f;
#pragma unroll
        for (int c = 0; c < 4; c++) {
            sacc[c][0] = __expf(sacc[c][0] - m0);
            sacc[c][1] = __expf(sacc[c][1] - m0);
            sacc[c][2] = __expf(sacc[c][2] - m1);
            sacc[c][3] = __expf(sacc[c][3] - m1);
            rs0 += sacc[c][0] + sacc[c][1];
            rs1 += sacc[c][2] + sacc[c][3];
        }
        rs0 += __shfl_xor_sync(0xffffffffu, rs0, 1);
        rs0 += __shfl_xor_sync(0xffffffffu, rs0, 2);
        rs1 += __shfl_xor_sync(0xffffffffu, rs1, 1);
        rs1 += __shfl_xor_sync(0xffffffffu, rs1, 2);
        l0 = l0*al0 + rs0;
        l1 = l1*al1 + rs1;

#pragma unroll
        for (int c = 0; c < 8; c++) {
            oacc[c][0] *= al0; oacc[c][1] *= al0;
            oacc[c][2] *= al1; oacc[c][3] *= al1;
        }

        // ---- P -> per-warp smem (tf32-rounded)
#pragma unroll
        for (int c = 0; c < 4; c++) {
            *(float2*)(&Pw[(g    )*PPAD + 8*c + 2*q]) = make_float2(to_tf32(sacc[c][0]), to_tf32(sacc[c][1]));
            *(float2*)(&Pw[(g + 8)*PPAD + 8*c + 2*q]) = make_float2(to_tf32(sacc[c][2]), to_tf32(sacc[c][3]));
        }
        __syncwarp();

        // ---- O += P @ V
#pragma unroll
        for (int kk = 0; kk < 4; kk++) {
            unsigned pa[4];
            pa[0] = __float_as_uint(Pw[(g    )*PPAD + 8*kk + q    ]);
            pa[1] = __float_as_uint(Pw[(g + 8)*PPAD + 8*kk + q    ]);
            pa[2] = __float_as_uint(Pw[(g    )*PPAD + 8*kk + q + 4]);
            pa[3] = __float_as_uint(Pw[(g + 8)*PPAD + 8*kk + q + 4]);
#pragma unroll
            for (int cc = 0; cc < 8; cc++) {
                unsigned b0 = __float_as_uint(VsB[(8*kk + q    )*VPAD + 8*cc + g]);
                unsigned b1 = __float_as_uint(VsB[(8*kk + q + 4)*VPAD + 8*cc + g]);
                mma8(oacc[cc], pa, b0, b1);
            }
        }
    }

    // ---- normalize and write A
    float inv0 = 1.f / l0, inv1 = 1.f / l1;
    const int r0 = q0 + 16*w + g;
    const int r1 = r0 + 8;
#pragma unroll
    for (int cc = 0; cc < 8; cc++) {
        *(float2*)(&g_A[((size_t)(b*Nn + r0))*Cc + 8*cc + 2*q]) =
            make_float2(oacc[cc][0]*inv0, oacc[cc][1]*inv0);
        *(float2*)(&g_A[((size_t)(b*Nn + r1))*Cc + 8*cc + 2*q]) =
            make_float2(oacc[cc][2]*inv1, oacc[cc][3]*inv1);
    }
}

// ---------------------------------------------------------------------------
// Kernel 3: fused GRU gates + output projection.
// ---------------------------------------------------------------------------
__global__ void gru_kernel(const float* __restrict__ X,
                           const float* __restrict__ Hp,
                           const float* __restrict__ b_xr,
                           const float* __restrict__ b_xz,
                           const float* __restrict__ b_xh,
                           const float* __restrict__ b_hh,
                           const float* __restrict__ b_y,
                           float* __restrict__ y_out, float* __restrict__ H_out) {
    const int n0 = blockIdx.x * GR;
    const int h  = threadIdx.x;   // 0..127
    __shared__ float as[GR][Cc], xs[GR][Cc], hps[GR][HD], rh[GR][HD], Hs[GR][HD];

#pragma unroll
    for (int r = 0; r < GR; r++) {
        if (h < Cc) {
            as[r][h] = g_A[(size_t)(n0+r)*Cc + h];
            xs[r][h] = X[(size_t)(n0+r)*Cc + h];
        }
        hps[r][h] = Hp[(size_t)(n0+r)*HD + h];
    }
    __syncthreads();

    float rr[GR], zz[GR], xh[GR];
    {
        float br = b_xr[h], bz = b_xz[h], bh = b_xh[h];
#pragma unroll
        for (int r = 0; r < GR; r++) { rr[r] = br; zz[r] = bz; xh[r] = bh; }
    }

#pragma unroll
    for (int c = 0; c < Cc; c++) {
        float wr = WT_xr[c*HD + h];
        float wz = WT_xz[c*HD + h];
        float wh = WT_xh[c*HD + h];
#pragma unroll
        for (int r = 0; r < GR; r++) {
            float a = as[r][c];
            rr[r] += a * wr;
            zz[r] += a * wz;
            xh[r] += xs[r][c] * wh;
        }
    }
#pragma unroll
    for (int r = 0; r < GR; r++) {
        float rv = 1.f / (1.f + __expf(-rr[r]));
        rh[r][h] = rv * hps[r][h];
    }
    __syncthreads();

    float hh[GR];
    {
        float bh = b_hh[h];
#pragma unroll
        for (int r = 0; r < GR; r++) hh[r] = bh;
    }
#pragma unroll
    for (int g = 0; g < HD; g++) {
        float w = WT_hh[g*HD + h];
#pragma unroll
        for (int r = 0; r < GR; r++) hh[r] += rh[r][g] * w;
    }
#pragma unroll
    for (int r = 0; r < GR; r++) {
        float z  = 1.f / (1.f + __expf(-zz[r]));
        float hc = tanhf(xh[r] + hh[r]);
        float Hn = z * hps[r][h] + (1.f - z) * hc;
        H_out[(size_t)(n0+r)*HD + h] = Hn;
        Hs[r][h] = Hn;
    }
    __syncthreads();

    if (h < Cc) {
        float yv[GR];
        float by = b_y[h];
#pragma unroll
        for (int r = 0; r < GR; r++) yv[r] = by;
#pragma unroll
        for (int g = 0; g < HD; g++) {
            float w = WT_y[g*Cc + h];
#pragma unroll
            for (int r = 0; r < GR; r++) yv[r] += Hs[r][g] * w;
        }
#pragma unroll
        for (int r = 0; r < GR; r++)
            y_out[(size_t)(n0+r)*Cc + h] = yv[r];
    }
}

// ---------------------------------------------------------------------------
extern "C" void kernel_launch(void* const* d_in, const int* in_sizes, int n_in,
                              void* d_out, int out_size) {
    const float* Hp    = (const float*)d_in[0];
    const float* X     = (const float*)d_in[1];
    const float* W_xr  = (const float*)d_in[2];
    const float* b_xr  = (const float*)d_in[3];
    const float* W_xz  = (const float*)d_in[4];
    const float* b_xz  = (const float*)d_in[5];
    const float* W_xh  = (const float*)d_in[6];
    const float* b_xh  = (const float*)d_in[7];
    const float* W_hh  = (const float*)d_in[8];
    const float* b_hh  = (const float*)d_in[9];
    const float* W_ha1 = (const float*)d_in[10];
    const float* W_ha2 = (const float*)d_in[11];
    const float* b_ha2 = (const float*)d_in[12];
    const float* W_y   = (const float*)d_in[13];
    const float* b_y   = (const float*)d_in[14];

    float* out = (float*)d_out;
    float* y_out = out;                        // [B,N,C]
    float* H_out = out + (size_t)Bb*Nn*Cc;     // [B,N,Hd]

    transpose_all<<<(73728 + 255)/256, 256>>>(W_xr, W_xz, W_xh, W_hh, W_ha1, W_ha2, W_y);

    prep_kernel<<<Bb*Nn/GR, 128>>>(X, Hp, b_ha2);

    size_t smem = (size_t)(2*KT*KPAD + 2*KT*VPAD + QT*PPAD) * sizeof(float);  // 61440 B
    cudaFuncSetAttribute(attn_kernel, cudaFuncAttributeMaxDynamicSharedMemorySize, (int)smem);
    attn_kernel<<<dim3(Nn/QT, Bb), 128, smem>>>();

    gru_kernel<<<Bb*Nn/GR, 128>>>(X, Hp, b_xr, b_xz, b_xh, b_hh, b_y, y_out, H_out);
}

// round 9
// speedup vs baseline: 22.1265x; 1.1748x over previous
#include <cuda_runtime.h>

#define Bb 8
#define Nn 2048
#define Cc 64
#define HD 128

#define QT 64      // attn queries per block (4 warps x 16 rows)
#define KT 32      // attn keys per tile
#define KPAD 132   // stride 132: (4g+q) banks, conflict-free frag loads
#define VPAD 72
#define PPAD 36
#define PADA 68    // 64-col tiles: 68 mod 32 = 4 -> (4g+q) conflict-free
#define PADH 132   // 128-col tiles

// scratch (allocation-free rule: __device__ globals)
__device__ float g_lhs[Bb*Nn*HD];   // tf32 Q
__device__ float g_rhs[Bb*Nn*HD];   // tf32 K
__device__ float g_Xc[Bb*Nn*Cc];    // tf32 X
__device__ float g_A[Bb*Nn*Cc];

// transposed weights [in][out] (coalesced, 4-sector B-frag LDGs)
__device__ float WT_xr[Cc*HD];
__device__ float WT_xz[Cc*HD];
__device__ float WT_xh[Cc*HD];
__device__ float WT_hh[HD*HD];
__device__ float WT_ha1[Cc*HD];
__device__ float WT_ha2[HD*HD];
__device__ float WT_y[HD*Cc];

__device__ __forceinline__ void cp_async16(void* smem_dst, const void* gmem_src) {
    unsigned s = (unsigned)__cvta_generic_to_shared(smem_dst);
    asm volatile("cp.async.ca.shared.global [%0], [%1], 16;\n" :: "r"(s), "l"(gmem_src));
}
__device__ __forceinline__ void cp_commit() { asm volatile("cp.async.commit_group;\n"); }
__device__ __forceinline__ void cp_wait_all() { asm volatile("cp.async.wait_group 0;\n" ::: "memory"); }

__device__ __forceinline__ float to_tf32(float x) {
    unsigned u;
    asm("cvt.rna.tf32.f32 %0, %1;" : "=r"(u) : "f"(x));
    return __uint_as_float(u);
}
__device__ __forceinline__ float sigm(float x) { return 1.f / (1.f + __expf(-x)); }

// D += A(16x8,row) * B(8x8,col)   tf32 inputs, f32 accum
__device__ __forceinline__ void mma8(float* c, const unsigned* a, unsigned b0, unsigned b1) {
    asm volatile(
        "mma.sync.aligned.m16n8k8.row.col.f32.tf32.tf32.f32 "
        "{%0,%1,%2,%3}, {%4,%5,%6,%7}, {%8,%9}, {%0,%1,%2,%3};\n"
        : "+f"(c[0]), "+f"(c[1]), "+f"(c[2]), "+f"(c[3])
        : "r"(a[0]), "r"(a[1]), "r"(a[2]), "r"(a[3]), "r"(b0), "r"(b1));
}
__device__ __forceinline__ unsigned ldw(const float* p) { return __float_as_uint(__ldg(p)); }

// ---------------------------------------------------------------------------
// Kernel 0: all 7 weight transposes in one launch.
// ---------------------------------------------------------------------------
__global__ void transpose_all(const float* __restrict__ W_xr, const float* __restrict__ W_xz,
                              const float* __restrict__ W_xh, const float* __restrict__ W_hh,
                              const float* __restrict__ W_ha1, const float* __restrict__ W_ha2,
                              const float* __restrict__ W_y) {
    int i = blockIdx.x * 256 + threadIdx.x;
    const float* src; float* dst; int R, C, off;
    if      (i < 8192)  { src = W_xr;  dst = WT_xr;  R = HD; C = Cc; off = 0; }
    else if (i < 16384) { src = W_xz;  dst = WT_xz;  R = HD; C = Cc; off = 8192; }
    else if (i < 24576) { src = W_xh;  dst = WT_xh;  R = HD; C = Cc; off = 16384; }
    else if (i < 40960) { src = W_hh;  dst = WT_hh;  R = HD; C = HD; off = 24576; }
    else if (i < 49152) { src = W_ha1; dst = WT_ha1; R = HD; C = Cc; off = 40960; }
    else if (i < 65536) { src = W_ha2; dst = WT_ha2; R = HD; C = HD; off = 49152; }
    else if (i < 73728) { src = W_y;   dst = WT_y;   R = Cc; C = HD; off = 65536; }
    else return;
    int j = i - off;
    int r = j / C, c = j - r*C;
    dst[c*R + r] = src[j];
}

// ---------------------------------------------------------------------------
// Kernel 1: prep via mma. 64 rows/block (4 warps, 16 rows each).
//   g_Xc = tf32(X); g_lhs = tf32(X@WT_ha1); g_rhs = tf32(Hp@WT_ha2 + b)
// ---------------------------------------------------------------------------
__global__ void __launch_bounds__(128) prep_mma(const float* __restrict__ X,
                                                const float* __restrict__ Hp,
                                                const float* __restrict__ b_ha2) {
    extern __shared__ float sm[];
    float* Xs = sm;               // 64*PADA
    float* Hs = sm + 64*PADA;     // 64*PADH

    const int t = threadIdx.x;
    const int w = t >> 5, lane = t & 31;
    const int g = lane >> 2, q = lane & 3;
    const int R0 = blockIdx.x * 64 + 16*w;   // this warp's global row base
    const int sr = 16*w;                     // smem row base

    // stage X (tf32) -> Xs and g_Xc
#pragma unroll
    for (int i = 0; i < 8; i++) {
        int idx = lane + 32*i;          // 256 float4s
        int r = idx >> 4, c4 = idx & 15;
        float4 v = *(const float4*)(X + (size_t)(R0 + r)*Cc + 4*c4);
        v.x = to_tf32(v.x); v.y = to_tf32(v.y); v.z = to_tf32(v.z); v.w = to_tf32(v.w);
        *(float4*)(&Xs[(sr + r)*PADA + 4*c4]) = v;
        *(float4*)(&g_Xc[(size_t)(R0 + r)*Cc + 4*c4]) = v;
    }
    // stage Hp (tf32) -> Hs
#pragma unroll
    for (int i = 0; i < 16; i++) {
        int idx = lane + 32*i;          // 512 float4s
        int r = idx >> 5, c4 = idx & 31;
        float4 v = *(const float4*)(Hp + (size_t)(R0 + r)*HD + 4*c4);
        v.x = to_tf32(v.x); v.y = to_tf32(v.y); v.z = to_tf32(v.z); v.w = to_tf32(v.w);
        *(float4*)(&Hs[(sr + r)*PADH + 4*c4]) = v;
    }
    __syncwarp();

    // lhs = X @ WT_ha1  (K=64, N=128)
    unsigned af[8][4];
#pragma unroll
    for (int kk = 0; kk < 8; kk++) {
        af[kk][0] = __float_as_uint(Xs[(sr + g    )*PADA + 8*kk + q    ]);
        af[kk][1] = __float_as_uint(Xs[(sr + g + 8)*PADA + 8*kk + q    ]);
        af[kk][2] = __float_as_uint(Xs[(sr + g    )*PADA + 8*kk + q + 4]);
        af[kk][3] = __float_as_uint(Xs[(sr + g + 8)*PADA + 8*kk + q + 4]);
    }
    float acc[16][4];
#pragma unroll
    for (int c = 0; c < 16; c++) { acc[c][0]=0.f; acc[c][1]=0.f; acc[c][2]=0.f; acc[c][3]=0.f; }
#pragma unroll
    for (int kk = 0; kk < 8; kk++) {
#pragma unroll
        for (int cc = 0; cc < 16; cc++) {
            unsigned b0 = ldw(WT_ha1 + (8*kk + q    )*HD + 8*cc + g);
            unsigned b1 = ldw(WT_ha1 + (8*kk + q + 4)*HD + 8*cc + g);
            mma8(acc[cc], af[kk], b0, b1);
        }
    }
#pragma unroll
    for (int cc = 0; cc < 16; cc++) {
        int col = 8*cc + 2*q;
        *(float2*)(&g_lhs[(size_t)(R0 + g    )*HD + col]) = make_float2(to_tf32(acc[cc][0]), to_tf32(acc[cc][1]));
        *(float2*)(&g_lhs[(size_t)(R0 + g + 8)*HD + col]) = make_float2(to_tf32(acc[cc][2]), to_tf32(acc[cc][3]));
    }

    // rhs = Hp @ WT_ha2 + b_ha2  (K=128, N=128)
#pragma unroll
    for (int c = 0; c < 16; c++) { acc[c][0]=0.f; acc[c][1]=0.f; acc[c][2]=0.f; acc[c][3]=0.f; }
#pragma unroll
    for (int kk = 0; kk < 16; kk++) {
        unsigned a4[4];
        a4[0] = __float_as_uint(Hs[(sr + g    )*PADH + 8*kk + q    ]);
        a4[1] = __float_as_uint(Hs[(sr + g + 8)*PADH + 8*kk + q    ]);
        a4[2] = __float_as_uint(Hs[(sr + g    )*PADH + 8*kk + q + 4]);
        a4[3] = __float_as_uint(Hs[(sr + g + 8)*PADH + 8*kk + q + 4]);
#pragma unroll
        for (int cc = 0; cc < 16; cc++) {
            unsigned b0 = ldw(WT_ha2 + (8*kk + q    )*HD + 8*cc + g);
            unsigned b1 = ldw(WT_ha2 + (8*kk + q + 4)*HD + 8*cc + g);
            mma8(acc[cc], a4, b0, b1);
        }
    }
#pragma unroll
    for (int cc = 0; cc < 16; cc++) {
        int col = 8*cc + 2*q;
        float2 bv = __ldg((const float2*)(b_ha2 + col));
        *(float2*)(&g_rhs[(size_t)(R0 + g    )*HD + col]) =
            make_float2(to_tf32(acc[cc][0] + bv.x), to_tf32(acc[cc][1] + bv.y));
        *(float2*)(&g_rhs[(size_t)(R0 + g + 8)*HD + col]) =
            make_float2(to_tf32(acc[cc][2] + bv.x), to_tf32(acc[cc][3] + bv.y));
    }
}

// ---------------------------------------------------------------------------
// Kernel 2: flash attention on mma.sync tf32 (unchanged from R8 pass).
// ---------------------------------------------------------------------------
__global__ void __launch_bounds__(128) attn_kernel() {
    extern __shared__ float sm[];
    float* Kb0 = sm;
    float* Vb0 = Kb0 + KT*KPAD;
    float* Kb1 = Vb0 + KT*VPAD;
    float* Vb1 = Kb1 + KT*KPAD;
    float* Ps  = Vb1 + KT*VPAD;
    float* Qstage = Kb1;

    const int b  = blockIdx.y;
    const int q0 = blockIdx.x * QT;
    const int t  = threadIdx.x;
    const int w  = t >> 5;
    const int lane = t & 31;
    const int g = lane >> 2;
    const int q = lane & 3;

    const float* Kg = g_rhs + (size_t)b*Nn*HD;
    const float* Vg = g_Xc  + (size_t)b*Nn*Cc;

    {
        const int kr = t >> 2, kc = t & 3;
#pragma unroll
        for (int i = 0; i < 8; i++)
            cp_async16(&Kb0[kr*KPAD + (kc + 4*i)*4], Kg + kr*HD + (kc + 4*i)*4);
#pragma unroll
        for (int i = 0; i < 4; i++)
            cp_async16(&Vb0[kr*VPAD + (kc + 4*i)*4], Vg + kr*Cc + (kc + 4*i)*4);
        cp_commit();
    }

    {
        const float* Qg = g_lhs + (size_t)(b*Nn + q0)*HD;
        for (int idx = t; idx < QT*(HD/4); idx += 128) {
            int r = idx >> 5, c4 = idx & 31;
            float4 v = ((const float4*)(Qg + r*HD))[c4];
            *(float4*)(&Qstage[r*KPAD + c4*4]) = v;
        }
    }
    __syncthreads();

    unsigned qf[16][4];
#pragma unroll
    for (int kk = 0; kk < 16; kk++) {
        qf[kk][0] = __float_as_uint(Qstage[(16*w + g    )*KPAD + 8*kk + q    ]);
        qf[kk][1] = __float_as_uint(Qstage[(16*w + g + 8)*KPAD + 8*kk + q    ]);
        qf[kk][2] = __float_as_uint(Qstage[(16*w + g    )*KPAD + 8*kk + q + 4]);
        qf[kk][3] = __float_as_uint(Qstage[(16*w + g + 8)*KPAD + 8*kk + q + 4]);
    }
    __syncthreads();

    float oacc[8][4];
#pragma unroll
    for (int c = 0; c < 8; c++)
#pragma unroll
        for (int j = 0; j < 4; j++) oacc[c][j] = 0.f;
    float m0 = -1e30f, m1 = -1e30f, l0 = 0.f, l1 = 0.f;

    float* Pw = Ps + 16*w*PPAD;

    const int NT = Nn / KT;
    for (int it = 0; it < NT; it++) {
        float* KsB = (it & 1) ? Kb1 : Kb0;
        float* VsB = (it & 1) ? Vb1 : Vb0;

        cp_wait_all();
        __syncthreads();

        if (it + 1 < NT) {
            float* KsN = (it & 1) ? Kb0 : Kb1;
            float* VsN = (it & 1) ? Vb0 : Vb1;
            const int k1 = (it + 1) * KT;
            const int kr = t >> 2, kc = t & 3;
#pragma unroll
            for (int i = 0; i < 8; i++)
                cp_async16(&KsN[kr*KPAD + (kc + 4*i)*4], Kg + (k1 + kr)*HD + (kc + 4*i)*4);
#pragma unroll
            for (int i = 0; i < 4; i++)
                cp_async16(&VsN[kr*VPAD + (kc + 4*i)*4], Vg + (k1 + kr)*Cc + (kc + 4*i)*4);
            cp_commit();
        }

        float sacc[4][4];
#pragma unroll
        for (int c = 0; c < 4; c++)
#pragma unroll
            for (int j = 0; j < 4; j++) sacc[c][j] = 0.f;

#pragma unroll
        for (int kk = 0; kk < 16; kk++) {
#pragma unroll
            for (int cc = 0; cc < 4; cc++) {
                unsigned b0 = __float_as_uint(KsB[(8*cc + g)*KPAD + 8*kk + q    ]);
                unsigned b1 = __float_as_uint(KsB[(8*cc + g)*KPAD + 8*kk + q + 4]);
                mma8(sacc[cc], qf[kk], b0, b1);
            }
        }

#pragma unroll
        for (int c = 0; c < 4; c++)
#pragma unroll
            for (int j = 0; j < 4; j++) {
                float v = sacc[c][j];
                sacc[c][j] = (v > 0.f) ? v : 0.01f*v;
            }

        float mx0 = -1e30f, mx1 = -1e30f;
#pragma unroll
        for (int c = 0; c < 4; c++) {
            mx0 = fmaxf(mx0, fmaxf(sacc[c][0], sacc[c][1]));
            mx1 = fmaxf(mx1, fmaxf(sacc[c][2], sacc[c][3]));
        }
        mx0 = fmaxf(mx0, __shfl_xor_sync(0xffffffffu, mx0, 1));
        mx0 = fmaxf(mx0, __shfl_xor_sync(0xffffffffu, mx0, 2));
        mx1 = fmaxf(mx1, __shfl_xor_sync(0xffffffffu, mx1, 1));
        mx1 = fmaxf(mx1, __shfl_xor_sync(0xffffffffu, mx1, 2));

        float mn0 = fmaxf(m0, mx0), mn1 = fmaxf(m1, mx1);
        float al0 = __expf(m0 - mn0), al1 = __expf(m1 - mn1);
        m0 = mn0; m1 = mn1;

        float rs0 = 0.f, rs1 = 0.f;
#pragma unroll
        for (int c = 0; c < 4; c++) {
            sacc[c][0] = __expf(sacc[c][0] - m0);
            sacc[c][1] = __expf(sacc[c][1] - m0);
            sacc[c][2] = __expf(sacc[c][2] - m1);
            sacc[c][3] = __expf(sacc[c][3] - m1);
            rs0 += sacc[c][0] + sacc[c][1];
            rs1 += sacc[c][2] + sacc[c][3];
        }
        rs0 += __shfl_xor_sync(0xffffffffu, rs0, 1);
        rs0 += __shfl_xor_sync(0xffffffffu, rs0, 2);
        rs1 += __shfl_xor_sync(0xffffffffu, rs1, 1);
        rs1 += __shfl_xor_sync(0xffffffffu, rs1, 2);
        l0 = l0*al0 + rs0;
        l1 = l1*al1 + rs1;

#pragma unroll
        for (int c = 0; c < 8; c++) {
            oacc[c][0] *= al0; oacc[c][1] *= al0;
            oacc[c][2] *= al1; oacc[c][3] *= al1;
        }

#pragma unroll
        for (int c = 0; c < 4; c++) {
            *(float2*)(&Pw[(g    )*PPAD + 8*c + 2*q]) = make_float2(to_tf32(sacc[c][0]), to_tf32(sacc[c][1]));
            *(float2*)(&Pw[(g + 8)*PPAD + 8*c + 2*q]) = make_float2(to_tf32(sacc[c][2]), to_tf32(sacc[c][3]));
        }
        __syncwarp();

#pragma unroll
        for (int kk = 0; kk < 4; kk++) {
            unsigned pa[4];
            pa[0] = __float_as_uint(Pw[(g    )*PPAD + 8*kk + q    ]);
            pa[1] = __float_as_uint(Pw[(g + 8)*PPAD + 8*kk + q    ]);
            pa[2] = __float_as_uint(Pw[(g    )*PPAD + 8*kk + q + 4]);
            pa[3] = __float_as_uint(Pw[(g + 8)*PPAD + 8*kk + q + 4]);
#pragma unroll
            for (int cc = 0; cc < 8; cc++) {
                unsigned b0 = __float_as_uint(VsB[(8*kk + q    )*VPAD + 8*cc + g]);
                unsigned b1 = __float_as_uint(VsB[(8*kk + q + 4)*VPAD + 8*cc + g]);
                mma8(oacc[cc], pa, b0, b1);
            }
        }
    }

    float inv0 = 1.f / l0, inv1 = 1.f / l1;
    const int r0 = q0 + 16*w + g;
    const int r1 = r0 + 8;
#pragma unroll
    for (int cc = 0; cc < 8; cc++) {
        *(float2*)(&g_A[((size_t)(b*Nn + r0))*Cc + 8*cc + 2*q]) =
            make_float2(oacc[cc][0]*inv0, oacc[cc][1]*inv0);
        *(float2*)(&g_A[((size_t)(b*Nn + r1))*Cc + 8*cc + 2*q]) =
            make_float2(oacc[cc][2]*inv1, oacc[cc][3]*inv1);
    }
}

// ---------------------------------------------------------------------------
// Kernel 3: GRU via mma. 64 rows/block (4 warps, 16 rows each), warp-independent.
// Phases: r (full N) -> rh smem; halves {z, xh, hh, Hn}; y-projection.
// Hn staged into the dead As+Xs region (stride PADH) for the y gemm.
// ---------------------------------------------------------------------------
__global__ void __launch_bounds__(128) gru_mma(const float* __restrict__ Hp,
                                               const float* __restrict__ b_xr,
                                               const float* __restrict__ b_xz,
                                               const float* __restrict__ b_xh,
                                               const float* __restrict__ b_hh,
                                               const float* __restrict__ b_y,
                                               float* __restrict__ y_out,
                                               float* __restrict__ H_out) {
    extern __shared__ float sm[];
    float* As  = sm;                      // 64*PADA (A tf32) ; later Hns (stride PADH)
    float* Xs  = sm + 64*PADA;            // 64*PADA (X tf32)
    float* RHs = sm + 2*64*PADA;          // 64*PADH (rh tf32)
    float* Hns = As;                      // 64*PADH spans As+Xs (8448 <= 8704)

    const int t = threadIdx.x;
    const int w = t >> 5, lane = t & 31;
    const int g = lane >> 2, q = lane & 3;
    const int R0 = blockIdx.x * 64 + 16*w;
    const int sr = 16*w;

    // stage A (tf32) and X (already tf32)
#pragma unroll
    for (int i = 0; i < 8; i++) {
        int idx = lane + 32*i;
        int r = idx >> 4, c4 = idx & 15;
        float4 a = *(const float4*)(g_A + (size_t)(R0 + r)*Cc + 4*c4);
        a.x = to_tf32(a.x); a.y = to_tf32(a.y); a.z = to_tf32(a.z); a.w = to_tf32(a.w);
        *(float4*)(&As[(sr + r)*PADA + 4*c4]) = a;
        float4 x = *(const float4*)(g_Xc + (size_t)(R0 + r)*Cc + 4*c4);
        *(float4*)(&Xs[(sr + r)*PADA + 4*c4]) = x;
    }
    __syncwarp();

    unsigned af[8][4], afx[8][4];
#pragma unroll
    for (int kk = 0; kk < 8; kk++) {
        af[kk][0]  = __float_as_uint(As[(sr + g    )*PADA + 8*kk + q    ]);
        af[kk][1]  = __float_as_uint(As[(sr + g + 8)*PADA + 8*kk + q    ]);
        af[kk][2]  = __float_as_uint(As[(sr + g    )*PADA + 8*kk + q + 4]);
        af[kk][3]  = __float_as_uint(As[(sr + g + 8)*PADA + 8*kk + q + 4]);
        afx[kk][0] = __float_as_uint(Xs[(sr + g    )*PADA + 8*kk + q    ]);
        afx[kk][1] = __float_as_uint(Xs[(sr + g + 8)*PADA + 8*kk + q    ]);
        afx[kk][2] = __float_as_uint(Xs[(sr + g    )*PADA + 8*kk + q + 4]);
        afx[kk][3] = __float_as_uint(Xs[(sr + g + 8)*PADA + 8*kk + q + 4]);
    }

    // ---- r = sigmoid(A@WT_xr + b_xr);  rh = r * Hp -> RHs (tf32)
    {
        float racc[16][4];
#pragma unroll
        for (int c = 0; c < 16; c++) { racc[c][0]=0.f; racc[c][1]=0.f; racc[c][2]=0.f; racc[c][3]=0.f; }
#pragma unroll
        for (int kk = 0; kk < 8; kk++) {
#pragma unroll
            for (int cc = 0; cc < 16; cc++) {
                unsigned b0 = ldw(WT_xr + (8*kk + q    )*HD + 8*cc + g);
                unsigned b1 = ldw(WT_xr + (8*kk + q + 4)*HD + 8*cc + g);
                mma8(racc[cc], af[kk], b0, b1);
            }
        }
#pragma unroll
        for (int cc = 0; cc < 16; cc++) {
            int col = 8*cc + 2*q;
            float2 br = __ldg((const float2*)(b_xr + col));
            float2 h0 = __ldg((const float2*)(Hp + (size_t)(R0 + g    )*HD + col));
            float2 h1 = __ldg((const float2*)(Hp + (size_t)(R0 + g + 8)*HD + col));
            *(float2*)(&RHs[(sr + g    )*PADH + col]) =
                make_float2(to_tf32(sigm(racc[cc][0] + br.x) * h0.x),
                            to_tf32(sigm(racc[cc][1] + br.y) * h0.y));
            *(float2*)(&RHs[(sr + g + 8)*PADH + col]) =
                make_float2(to_tf32(sigm(racc[cc][2] + br.x) * h1.x),
                            to_tf32(sigm(racc[cc][3] + br.y) * h1.y));
        }
    }
    __syncwarp();

    // ---- halves: z, xh, hh -> Hn
#pragma unroll
    for (int hf = 0; hf < 2; hf++) {
        const int C0 = 64*hf;
        float zac[8][4], xac[8][4], hac[8][4];
#pragma unroll
        for (int c = 0; c < 8; c++) {
            zac[c][0]=0.f; zac[c][1]=0.f; zac[c][2]=0.f; zac[c][3]=0.f;
            xac[c][0]=0.f; xac[c][1]=0.f; xac[c][2]=0.f; xac[c][3]=0.f;
            hac[c][0]=0.f; hac[c][1]=0.f; hac[c][2]=0.f; hac[c][3]=0.f;
        }
#pragma unroll
        for (int kk = 0; kk < 8; kk++) {
#pragma unroll
            for (int cc = 0; cc < 8; cc++) {
                unsigned b0 = ldw(WT_xz + (8*kk + q    )*HD + C0 + 8*cc + g);
                unsigned b1 = ldw(WT_xz + (8*kk + q + 4)*HD + C0 + 8*cc + g);
                mma8(zac[cc], af[kk], b0, b1);
                unsigned c0 = ldw(WT_xh + (8*kk + q    )*HD + C0 + 8*cc + g);
                unsigned c1 = ldw(WT_xh + (8*kk + q + 4)*HD + C0 + 8*cc + g);
                mma8(xac[cc], afx[kk], c0, c1);
            }
        }
#pragma unroll
        for (int kk = 0; kk < 16; kk++) {
            unsigned a4[4];
            a4[0] = __float_as_uint(RHs[(sr + g    )*PADH + 8*kk + q    ]);
            a4[1] = __float_as_uint(RHs[(sr + g + 8)*PADH + 8*kk + q    ]);
            a4[2] = __float_as_uint(RHs[(sr + g    )*PADH + 8*kk + q + 4]);
            a4[3] = __float_as_uint(RHs[(sr + g + 8)*PADH + 8*kk + q + 4]);
#pragma unroll
            for (int cc = 0; cc < 8; cc++) {
                unsigned b0 = ldw(WT_hh + (8*kk + q    )*HD + C0 + 8*cc + g);
                unsigned b1 = ldw(WT_hh + (8*kk + q + 4)*HD + C0 + 8*cc + g);
                mma8(hac[cc], a4, b0, b1);
            }
        }
#pragma unroll
        for (int cc = 0; cc < 8; cc++) {
            int col = C0 + 8*cc + 2*q;
            float2 bz = __ldg((const float2*)(b_xz + col));
            float2 bh = __ldg((const float2*)(b_xh + col));
            float2 bg = __ldg((const float2*)(b_hh + col));
            float2 h0 = __ldg((const float2*)(Hp + (size_t)(R0 + g    )*HD + col));
            float2 h1 = __ldg((const float2*)(Hp + (size_t)(R0 + g + 8)*HD + col));
            float z00 = sigm(zac[cc][0] + bz.x), z01 = sigm(zac[cc][1] + bz.y);
            float z10 = sigm(zac[cc][2] + bz.x), z11 = sigm(zac[cc][3] + bz.y);
            float c00 = tanhf(xac[cc][0] + bh.x + hac[cc][0] + bg.x);
            float c01 = tanhf(xac[cc][1] + bh.y + hac[cc][1] + bg.y);
            float c10 = tanhf(xac[cc][2] + bh.x + hac[cc][2] + bg.x);
            float c11 = tanhf(xac[cc][3] + bh.y + hac[cc][3] + bg.y);
            float H00 = z00*h0.x + (1.f - z00)*c00;
            float H01 = z01*h0.y + (1.f - z01)*c01;
            float H10 = z10*h1.x + (1.f - z10)*c10;
            float H11 = z11*h1.y + (1.f - z11)*c11;
            *(float2*)(&H_out[(size_t)(R0 + g    )*HD + col]) = make_float2(H00, H01);
            *(float2*)(&H_out[(size_t)(R0 + g + 8)*HD + col]) = make_float2(H10, H11);
            *(float2*)(&Hns[(sr + g    )*PADH + col]) = make_float2(to_tf32(H00), to_tf32(H01));
            *(float2*)(&Hns[(sr + g + 8)*PADH + col]) = make_float2(to_tf32(H10), to_tf32(H11));
        }
    }
    __syncwarp();

    // ---- y = Hn @ WT_y + b_y  (K=128, N=64)
    {
        float yac[8][4];
#pragma unroll
        for (int c = 0; c < 8; c++) { yac[c][0]=0.f; yac[c][1]=0.f; yac[c][2]=0.f; yac[c][3]=0.f; }
#pragma unroll
        for (int kk = 0; kk < 16; kk++) {
            unsigned a4[4];
            a4[0] = __float_as_uint(Hns[(sr + g    )*PADH + 8*kk + q    ]);
            a4[1] = __float_as_uint(Hns[(sr + g + 8)*PADH + 8*kk + q    ]);
            a4[2] = __float_as_uint(Hns[(sr + g    )*PADH + 8*kk + q + 4]);
            a4[3] = __float_as_uint(Hns[(sr + g + 8)*PADH + 8*kk + q + 4]);
#pragma unroll
            for (int cc = 0; cc < 8; cc++) {
                unsigned b0 = ldw(WT_y + (8*kk + q    )*Cc + 8*cc + g);
                unsigned b1 = ldw(WT_y + (8*kk + q + 4)*Cc + 8*cc + g);
                mma8(yac[cc], a4, b0, b1);
            }
        }
#pragma unroll
        for (int cc = 0; cc < 8; cc++) {
            int col = 8*cc + 2*q;
            float2 by = __ldg((const float2*)(b_y + col));
            *(float2*)(&y_out[(size_t)(R0 + g    )*Cc + col]) =
                make_float2(yac[cc][0] + by.x, yac[cc][1] + by.y);
            *(float2*)(&y_out[(size_t)(R0 + g + 8)*Cc + col]) =
                make_float2(yac[cc][2] + by.x, yac[cc][3] + by.y);
        }
    }
}

// ---------------------------------------------------------------------------
extern "C" void kernel_launch(void* const* d_in, const int* in_sizes, int n_in,
                              void* d_out, int out_size) {
    const float* Hp    = (const float*)d_in[0];
    const float* X     = (const float*)d_in[1];
    const float* W_xr  = (const float*)d_in[2];
    const float* b_xr  = (const float*)d_in[3];
    const float* W_xz  = (const float*)d_in[4];
    const float* b_xz  = (const float*)d_in[5];
    const float* W_xh  = (const float*)d_in[6];
    const float* b_xh  = (const float*)d_in[7];
    const float* W_hh  = (const float*)d_in[8];
    const float* b_hh  = (const float*)d_in[9];
    const float* W_ha1 = (const float*)d_in[10];
    const float* W_ha2 = (const float*)d_in[11];
    const float* b_ha2 = (const float*)d_in[12];
    const float* W_y   = (const float*)d_in[13];
    const float* b_y   = (const float*)d_in[14];

    float* out = (float*)d_out;
    float* y_out = out;                        // [B,N,C]
    float* H_out = out + (size_t)Bb*Nn*Cc;     // [B,N,Hd]

    transpose_all<<<(73728 + 255)/256, 256>>>(W_xr, W_xz, W_xh, W_hh, W_ha1, W_ha2, W_y);

    size_t smem_prep = (size_t)(64*PADA + 64*PADH) * sizeof(float);   // 51200
    cudaFuncSetAttribute(prep_mma, cudaFuncAttributeMaxDynamicSharedMemorySize, (int)smem_prep);
    prep_mma<<<Bb*Nn/64, 128, smem_prep>>>(X, Hp, b_ha2);

    size_t smem_attn = (size_t)(2*KT*KPAD + 2*KT*VPAD + QT*PPAD) * sizeof(float);  // 61440
    cudaFuncSetAttribute(attn_kernel, cudaFuncAttributeMaxDynamicSharedMemorySize, (int)smem_attn);
    attn_kernel<<<dim3(Nn/QT, Bb), 128, smem_attn>>>();

    size_t smem_gru = (size_t)(2*64*PADA + 64*PADH) * sizeof(float);  // 68608
    cudaFuncSetAttribute(gru_mma, cudaFuncAttributeMaxDynamicSharedMemorySize, (int)smem_gru);
    gru_mma<<<Bb*Nn/64, 128, smem_gru>>>(Hp, b_xr, b_xz, b_xh, b_hh, b_y, y_out, H_out);
}

// round 12
// speedup vs baseline: 23.7151x; 1.0718x over previous
#include <cuda_runtime.h>

#define Bb 8
#define Nn 2048
#define Cc 64
#define HD 128

#define QT 64      // attn queries per block (4 warps x 16 rows)
#define KT 32      // attn keys per tile
#define KPAD 132   // (4g+q) banks, conflict-free frag loads
#define VPAD 72
#define PPAD 36
#define PADA 68    // 64-col activation tiles
#define PADH 132   // 128-col activation tiles
#define PADW 136   // weight chunks: B-frag bank (8q+8cc+g)%32 all-distinct

// scratch (allocation-free rule: __device__ globals)
__device__ float g_lhs[Bb*Nn*HD];   // tf32 Q
__device__ float g_rhs[Bb*Nn*HD];   // tf32 K
__device__ float g_Xc[Bb*Nn*Cc];    // tf32 X
__device__ float g_A[Bb*Nn*Cc];

// transposed weights [in][out]
__device__ float WT_xr[Cc*HD];
__device__ float WT_xz[Cc*HD];
__device__ float WT_xh[Cc*HD];
__device__ float WT_hh[HD*HD];
__device__ float WT_ha1[Cc*HD];
__device__ float WT_ha2[HD*HD];
__device__ float WT_y[HD*Cc];

__device__ __forceinline__ void cp_async16(void* smem_dst, const void* gmem_src) {
    unsigned s = (unsigned)__cvta_generic_to_shared(smem_dst);
    asm volatile("cp.async.ca.shared.global [%0], [%1], 16;\n" :: "r"(s), "l"(gmem_src));
}
__device__ __forceinline__ void cp_commit() { asm volatile("cp.async.commit_group;\n"); }
__device__ __forceinline__ void cp_wait_all() { asm volatile("cp.async.wait_group 0;\n" ::: "memory"); }
__device__ __forceinline__ void cp_wait1()   { asm volatile("cp.async.wait_group 1;\n" ::: "memory"); }

__device__ __forceinline__ float to_tf32(float x) {
    unsigned u;
    asm("cvt.rna.tf32.f32 %0, %1;" : "=r"(u) : "f"(x));
    return __uint_as_float(u);
}
__device__ __forceinline__ float sigm(float x) { return 1.f / (1.f + __expf(-x)); }

// D += A(16x8,row) * B(8x8,col)   tf32 inputs, f32 accum
__device__ __forceinline__ void mma8(float* c, const unsigned* a, unsigned b0, unsigned b1) {
    asm volatile(
        "mma.sync.aligned.m16n8k8.row.col.f32.tf32.tf32.f32 "
        "{%0,%1,%2,%3}, {%4,%5,%6,%7}, {%8,%9}, {%0,%1,%2,%3};\n"
        : "+f"(c[0]), "+f"(c[1]), "+f"(c[2]), "+f"(c[3])
        : "r"(a[0]), "r"(a[1]), "r"(a[2]), "r"(a[3]), "r"(b0), "r"(b1));
}

// stage 64 rows x 128 cols of a row-major [*][128] weight into WB (stride PADW)
__device__ __forceinline__ void stage_w128(float* dst, const float* src, int t) {
#pragma unroll
    for (int i = 0; i < 16; i++) {
        int idx = t + 128*i;                 // 2048 float4s
        int r = idx >> 5, c4 = idx & 31;
        cp_async16(dst + r*PADW + 4*c4, src + r*HD + 4*c4);
    }
}
// stage 64 rows x 64 cols of a row-major [*][64] weight into WB (stride PADW)
__device__ __forceinline__ void stage_w64(float* dst, const float* src, int t) {
#pragma unroll
    for (int i = 0; i < 8; i++) {
        int idx = t + 128*i;                 // 1024 float4s
        int r = idx >> 4, c4 = idx & 15;
        cp_async16(dst + r*PADW + 4*c4, src + r*Cc + 4*c4);
    }
}

// ---------------------------------------------------------------------------
// Kernel 0: all 7 weight transposes in one launch.
// ---------------------------------------------------------------------------
__global__ void transpose_all(const float* __restrict__ W_xr, const float* __restrict__ W_xz,
                              const float* __restrict__ W_xh, const float* __restrict__ W_hh,
                              const float* __restrict__ W_ha1, const float* __restrict__ W_ha2,
                              const float* __restrict__ W_y) {
    int i = blockIdx.x * 256 + threadIdx.x;
    const float* src; float* dst; int R, C, off;
    if      (i < 8192)  { src = W_xr;  dst = WT_xr;  R = HD; C = Cc; off = 0; }
    else if (i < 16384) { src = W_xz;  dst = WT_xz;  R = HD; C = Cc; off = 8192; }
    else if (i < 24576) { src = W_xh;  dst = WT_xh;  R = HD; C = Cc; off = 16384; }
    else if (i < 40960) { src = W_hh;  dst = WT_hh;  R = HD; C = HD; off = 24576; }
    else if (i < 49152) { src = W_ha1; dst = WT_ha1; R = HD; C = Cc; off = 40960; }
    else if (i < 65536) { src = W_ha2; dst = WT_ha2; R = HD; C = HD; off = 49152; }
    else if (i < 73728) { src = W_y;   dst = WT_y;   R = Cc; C = HD; off = 65536; }
    else return;
    int j = i - off;
    int r = j / C, c = j - r*C;
    dst[c*R + r] = src[j];
}

// ---------------------------------------------------------------------------
// Kernel 1: prep via mma with smem-staged weights.
// 64 rows/block (4 warps x 16 rows). Chunks: ha1 | ha2[0:64] | ha2[64:128]
// ---------------------------------------------------------------------------
__global__ void __launch_bounds__(128) prep_mma(const float* __restrict__ X,
                                                const float* __restrict__ Hp,
                                                const float* __restrict__ b_ha2) {
    extern __shared__ float sm[];
    float* Xs  = sm;                      // 64*PADA = 4352
    float* Hs  = Xs + 64*PADA;            // 64*PADH = 8448
    float* WB0 = Hs + 64*PADH;            // 64*PADW = 8704
    float* WB1 = WB0 + 64*PADW;           // 8704  (total 30208 floats)

    const int t = threadIdx.x;
    const int w = t >> 5, lane = t & 31;
    const int g = lane >> 2, q = lane & 3;
    const int R0 = blockIdx.x * 64 + 16*w;
    const int sr = 16*w;

    stage_w128(WB0, WT_ha1, t); cp_commit();          // c0
    stage_w128(WB1, WT_ha2, t); cp_commit();          // c1

    // stage X (tf32) -> Xs and g_Xc ; Hp (tf32) -> Hs  (own warp's rows)
#pragma unroll
    for (int i = 0; i < 8; i++) {
        int idx = lane + 32*i;
        int r = idx >> 4, c4 = idx & 15;
        float4 v = *(const float4*)(X + (size_t)(R0 + r)*Cc + 4*c4);
        v.x = to_tf32(v.x); v.y = to_tf32(v.y); v.z = to_tf32(v.z); v.w = to_tf32(v.w);
        *(float4*)(&Xs[(sr + r)*PADA + 4*c4]) = v;
        *(float4*)(&g_Xc[(size_t)(R0 + r)*Cc + 4*c4]) = v;
    }
#pragma unroll
    for (int i = 0; i < 16; i++) {
        int idx = lane + 32*i;
        int r = idx >> 5, c4 = idx & 31;
        float4 v = *(const float4*)(Hp + (size_t)(R0 + r)*HD + 4*c4);
        v.x = to_tf32(v.x); v.y = to_tf32(v.y); v.z = to_tf32(v.z); v.w = to_tf32(v.w);
        *(float4*)(&Hs[(sr + r)*PADH + 4*c4]) = v;
    }
    __syncwarp();

    unsigned af[8][4];
#pragma unroll
    for (int kk = 0; kk < 8; kk++) {
        af[kk][0] = __float_as_uint(Xs[(sr + g    )*PADA + 8*kk + q    ]);
        af[kk][1] = __float_as_uint(Xs[(sr + g + 8)*PADA + 8*kk + q    ]);
        af[kk][2] = __float_as_uint(Xs[(sr + g    )*PADA + 8*kk + q + 4]);
        af[kk][3] = __float_as_uint(Xs[(sr + g + 8)*PADA + 8*kk + q + 4]);
    }

    float acc[16][4];

    // ---- lhs = X @ WT_ha1 (K=64) using WB0
    cp_wait1(); __syncthreads();
#pragma unroll
    for (int c = 0; c < 16; c++) { acc[c][0]=0.f; acc[c][1]=0.f; acc[c][2]=0.f; acc[c][3]=0.f; }
#pragma unroll
    for (int kk = 0; kk < 8; kk++) {
#pragma unroll
        for (int cc = 0; cc < 16; cc++) {
            unsigned b0 = __float_as_uint(WB0[(8*kk + q    )*PADW + 8*cc + g]);
            unsigned b1 = __float_as_uint(WB0[(8*kk + q + 4)*PADW + 8*cc + g]);
            mma8(acc[cc], af[kk], b0, b1);
        }
    }
#pragma unroll
    for (int cc = 0; cc < 16; cc++) {
        int col = 8*cc + 2*q;
        *(float2*)(&g_lhs[(size_t)(R0 + g    )*HD + col]) = make_float2(to_tf32(acc[cc][0]), to_tf32(acc[cc][1]));
        *(float2*)(&g_lhs[(size_t)(R0 + g + 8)*HD + col]) = make_float2(to_tf32(acc[cc][2]), to_tf32(acc[cc][3]));
    }
    __syncthreads();
    stage_w128(WB0, WT_ha2 + 64*HD, t); cp_commit();  // c2

    // ---- rhs = Hp @ WT_ha2 + b (K=128): lo half (WB1)
    cp_wait1(); __syncthreads();
#pragma unroll
    for (int c = 0; c < 16; c++) { acc[c][0]=0.f; acc[c][1]=0.f; acc[c][2]=0.f; acc[c][3]=0.f; }
#pragma unroll
    for (int kk = 0; kk < 8; kk++) {
        unsigned a4[4];
        a4[0] = __float_as_uint(Hs[(sr + g    )*PADH + 8*kk + q    ]);
        a4[1] = __float_as_uint(Hs[(sr + g + 8)*PADH + 8*kk + q    ]);
        a4[2] = __float_as_uint(Hs[(sr + g    )*PADH + 8*kk + q + 4]);
        a4[3] = __float_as_uint(Hs[(sr + g + 8)*PADH + 8*kk + q + 4]);
#pragma unroll
        for (int cc = 0; cc < 16; cc++) {
            unsigned b0 = __float_as_uint(WB1[(8*kk + q    )*PADW + 8*cc + g]);
            unsigned b1 = __float_as_uint(WB1[(8*kk + q + 4)*PADW + 8*cc + g]);
            mma8(acc[cc], a4, b0, b1);
        }
    }
    // hi half (WB0)
    cp_wait_all(); __syncthreads();
#pragma unroll
    for (int kk = 0; kk < 8; kk++) {
        unsigned a4[4];
        a4[0] = __float_as_uint(Hs[(sr + g    )*PADH + 64 + 8*kk + q    ]);
        a4[1] = __float_as_uint(Hs[(sr + g + 8)*PADH + 64 + 8*kk + q    ]);
        a4[2] = __float_as_uint(Hs[(sr + g    )*PADH + 64 + 8*kk + q + 4]);
        a4[3] = __float_as_uint(Hs[(sr + g + 8)*PADH + 64 + 8*kk + q + 4]);
#pragma unroll
        for (int cc = 0; cc < 16; cc++) {
            unsigned b0 = __float_as_uint(WB0[(8*kk + q    )*PADW + 8*cc + g]);
            unsigned b1 = __float_as_uint(WB0[(8*kk + q + 4)*PADW + 8*cc + g]);
            mma8(acc[cc], a4, b0, b1);
        }
    }
#pragma unroll
    for (int cc = 0; cc < 16; cc++) {
        int col = 8*cc + 2*q;
        float2 bv = __ldg((const float2*)(b_ha2 + col));
        *(float2*)(&g_rhs[(size_t)(R0 + g    )*HD + col]) =
            make_float2(to_tf32(acc[cc][0] + bv.x), to_tf32(acc[cc][1] + bv.y));
        *(float2*)(&g_rhs[(size_t)(R0 + g + 8)*HD + col]) =
            make_float2(to_tf32(acc[cc][2] + bv.x), to_tf32(acc[cc][3] + bv.y));
    }
}

// ---------------------------------------------------------------------------
// Kernel 2: flash attention on mma.sync tf32 (R8/R9 structure; 3 CTAs/SM).
// ---------------------------------------------------------------------------
__global__ void __launch_bounds__(128, 3) attn_kernel() {
    extern __shared__ float sm[];
    float* Kb0 = sm;
    float* Vb0 = Kb0 + KT*KPAD;
    float* Kb1 = Vb0 + KT*VPAD;
    float* Vb1 = Kb1 + KT*KPAD;
    float* Ps  = Vb1 + KT*VPAD;
    float* Qstage = Kb1;

    const int b  = blockIdx.y;
    const int q0 = blockIdx.x * QT;
    const int t  = threadIdx.x;
    const int w  = t >> 5;
    const int lane = t & 31;
    const int g = lane >> 2;
    const int q = lane & 3;

    const float* Kg = g_rhs + (size_t)b*Nn*HD;
    const float* Vg = g_Xc  + (size_t)b*Nn*Cc;

    {
        const int kr = t >> 2, kc = t & 3;
#pragma unroll
        for (int i = 0; i < 8; i++)
            cp_async16(&Kb0[kr*KPAD + (kc + 4*i)*4], Kg + kr*HD + (kc + 4*i)*4);
#pragma unroll
        for (int i = 0; i < 4; i++)
            cp_async16(&Vb0[kr*VPAD + (kc + 4*i)*4], Vg + kr*Cc + (kc + 4*i)*4);
        cp_commit();
    }

    {
        const float* Qg = g_lhs + (size_t)(b*Nn + q0)*HD;
        for (int idx = t; idx < QT*(HD/4); idx += 128) {
            int r = idx >> 5, c4 = idx & 31;
            float4 v = ((const float4*)(Qg + r*HD))[c4];
            *(float4*)(&Qstage[r*KPAD + c4*4]) = v;
        }
    }
    __syncthreads();

    unsigned qf[16][4];
#pragma unroll
    for (int kk = 0; kk < 16; kk++) {
        qf[kk][0] = __float_as_uint(Qstage[(16*w + g    )*KPAD + 8*kk + q    ]);
        qf[kk][1] = __float_as_uint(Qstage[(16*w + g + 8)*KPAD + 8*kk + q    ]);
        qf[kk][2] = __float_as_uint(Qstage[(16*w + g    )*KPAD + 8*kk + q + 4]);
        qf[kk][3] = __float_as_uint(Qstage[(16*w + g + 8)*KPAD + 8*kk + q + 4]);
    }
    __syncthreads();

    float oacc[8][4];
#pragma unroll
    for (int c = 0; c < 8; c++)
#pragma unroll
        for (int j = 0; j < 4; j++) oacc[c][j] = 0.f;
    float m0 = -1e30f, m1 = -1e30f, l0 = 0.f, l1 = 0.f;

    float* Pw = Ps + 16*w*PPAD;

    const int NT = Nn / KT;
    for (int it = 0; it < NT; it++) {
        float* KsB = (it & 1) ? Kb1 : Kb0;
        float* VsB = (it & 1) ? Vb1 : Vb0;

        cp_wait_all();
        __syncthreads();

        if (it + 1 < NT) {
            float* KsN = (it & 1) ? Kb0 : Kb1;
            float* VsN = (it & 1) ? Vb0 : Vb1;
            const int k1 = (it + 1) * KT;
            const int kr = t >> 2, kc = t & 3;
#pragma unroll
            for (int i = 0; i < 8; i++)
                cp_async16(&KsN[kr*KPAD + (kc + 4*i)*4], Kg + (k1 + kr)*HD + (kc + 4*i)*4);
#pragma unroll
            for (int i = 0; i < 4; i++)
                cp_async16(&VsN[kr*VPAD + (kc + 4*i)*4], Vg + (k1 + kr)*Cc + (kc + 4*i)*4);
            cp_commit();
        }

        float sacc[4][4];
#pragma unroll
        for (int c = 0; c < 4; c++)
#pragma unroll
            for (int j = 0; j < 4; j++) sacc[c][j] = 0.f;

#pragma unroll
        for (int kk = 0; kk < 16; kk++) {
#pragma unroll
            for (int cc = 0; cc < 4; cc++) {
                unsigned b0 = __float_as_uint(KsB[(8*cc + g)*KPAD + 8*kk + q    ]);
                unsigned b1 = __float_as_uint(KsB[(8*cc + g)*KPAD + 8*kk + q + 4]);
                mma8(sacc[cc], qf[kk], b0, b1);
            }
        }

#pragma unroll
        for (int c = 0; c < 4; c++)
#pragma unroll
            for (int j = 0; j < 4; j++) {
                float v = sacc[c][j];
                sacc[c][j] = (v > 0.f) ? v : 0.01f*v;
            }

        float mx0 = -1e30f, mx1 = -1e30f;
#pragma unroll
        for (int c = 0; c < 4; c++) {
            mx0 = fmaxf(mx0, fmaxf(sacc[c][0], sacc[c][1]));
            mx1 = fmaxf(mx1, fmaxf(sacc[c][2], sacc[c][3]));
        }
        mx0 = fmaxf(mx0, __shfl_xor_sync(0xffffffffu, mx0, 1));
        mx0 = fmaxf(mx0, __shfl_xor_sync(0xffffffffu, mx0, 2));
        mx1 = fmaxf(mx1, __shfl_xor_sync(0xffffffffu, mx1, 1));
        mx1 = fmaxf(mx1, __shfl_xor_sync(0xffffffffu, mx1, 2));

        float mn0 = fmaxf(m0, mx0), mn1 = fmaxf(m1, mx1);
        float al0 = __expf(m0 - mn0), al1 = __expf(m1 - mn1);
        m0 = mn0; m1 = mn1;

        float rs0 = 0.f, rs1 = 0.f;
#pragma unroll
        for (int c = 0; c < 4; c++) {
            sacc[c][0] = __expf(sacc[c][0] - m0);
            sacc[c][1] = __expf(sacc[c][1] - m0);
            sacc[c][2] = __expf(sacc[c][2] - m1);
            sacc[c][3] = __expf(sacc[c][3] - m1);
            rs0 += sacc[c][0] + sacc[c][1];
            rs1 += sacc[c][2] + sacc[c][3];
        }
        rs0 += __shfl_xor_sync(0xffffffffu, rs0, 1);
        rs0 += __shfl_xor_sync(0xffffffffu, rs0, 2);
        rs1 += __shfl_xor_sync(0xffffffffu, rs1, 1);
        rs1 += __shfl_xor_sync(0xffffffffu, rs1, 2);
        l0 = l0*al0 + rs0;
        l1 = l1*al1 + rs1;

#pragma unroll
        for (int c = 0; c < 8; c++) {
            oacc[c][0] *= al0; oacc[c][1] *= al0;
            oacc[c][2] *= al1; oacc[c][3] *= al1;
        }

#pragma unroll
        for (int c = 0; c < 4; c++) {
            *(float2*)(&Pw[(g    )*PPAD + 8*c + 2*q]) = make_float2(to_tf32(sacc[c][0]), to_tf32(sacc[c][1]));
            *(float2*)(&Pw[(g + 8)*PPAD + 8*c + 2*q]) = make_float2(to_tf32(sacc[c][2]), to_tf32(sacc[c][3]));
        }
        __syncwarp();

#pragma unroll
        for (int kk = 0; kk < 4; kk++) {
            unsigned pa[4];
            pa[0] = __float_as_uint(Pw[(g    )*PPAD + 8*kk + q    ]);
            pa[1] = __float_as_uint(Pw[(g + 8)*PPAD + 8*kk + q    ]);
            pa[2] = __float_as_uint(Pw[(g    )*PPAD + 8*kk + q + 4]);
            pa[3] = __float_as_uint(Pw[(g + 8)*PPAD + 8*kk + q + 4]);
#pragma unroll
            for (int cc = 0; cc < 8; cc++) {
                unsigned b0 = __float_as_uint(VsB[(8*kk + q    )*VPAD + 8*cc + g]);
                unsigned b1 = __float_as_uint(VsB[(8*kk + q + 4)*VPAD + 8*cc + g]);
                mma8(oacc[cc], pa, b0, b1);
            }
        }
    }

    float inv0 = 1.f / l0, inv1 = 1.f / l1;
    const int r0 = q0 + 16*w + g;
    const int r1 = r0 + 8;
#pragma unroll
    for (int cc = 0; cc < 8; cc++) {
        *(float2*)(&g_A[((size_t)(b*Nn + r0))*Cc + 8*cc + 2*q]) =
            make_float2(oacc[cc][0]*inv0, oacc[cc][1]*inv0);
        *(float2*)(&g_A[((size_t)(b*Nn + r1))*Cc + 8*cc + 2*q]) =
            make_float2(oacc[cc][2]*inv1, oacc[cc][3]*inv1);
    }
}

// ---------------------------------------------------------------------------
// Kernel 3: GRU via mma, smem-staged weights (7 chunks, double-buffered).
// Phases: r -> z -> xh -> hh(2, accum into xh's acc) -> Hn -> y(2).
// ---------------------------------------------------------------------------
__global__ void __launch_bounds__(128) gru_mma(const float* __restrict__ Hp,
                                               const float* __restrict__ b_xr,
                                               const float* __restrict__ b_xz,
                                               const float* __restrict__ b_xh,
                                               const float* __restrict__ b_hh,
                                               const float* __restrict__ b_y,
                                               float* __restrict__ y_out,
                                               float* __restrict__ H_out) {
    extern __shared__ float sm[];
    float* As  = sm;                      // 64*PADA = 4352
    float* Xs  = As + 64*PADA;            // 4352
    float* RHs = Xs + 64*PADA;            // 64*PADH = 8448
    float* Zs  = RHs + 64*PADH;           // 8448
    float* WB0 = Zs + 64*PADH;            // 64*PADW = 8704
    float* WB1 = WB0 + 64*PADW;           // 8704   (total 43008 floats = 168KB)
    float* Hns = As;                      // 64*PADH = 8448 over As+Xs (8704) — safe after xh

    const int t = threadIdx.x;
    const int w = t >> 5, lane = t & 31;
    const int g = lane >> 2, q = lane & 3;
    const int R0 = blockIdx.x * 64 + 16*w;
    const int sr = 16*w;

    stage_w128(WB0, WT_xr, t); cp_commit();   // c0
    stage_w128(WB1, WT_xz, t); cp_commit();   // c1

    // stage A (tf32) and X (already tf32) — own warp's rows
#pragma unroll
    for (int i = 0; i < 8; i++) {
        int idx = lane + 32*i;
        int r = idx >> 4, c4 = idx & 15;
        float4 a = *(const float4*)(g_A + (size_t)(R0 + r)*Cc + 4*c4);
        a.x = to_tf32(a.x); a.y = to_tf32(a.y); a.z = to_tf32(a.z); a.w = to_tf32(a.w);
        *(float4*)(&As[(sr + r)*PADA + 4*c4]) = a;
        float4 x = *(const float4*)(g_Xc + (size_t)(R0 + r)*Cc + 4*c4);
        *(float4*)(&Xs[(sr + r)*PADA + 4*c4]) = x;
    }
    __syncwarp();

    unsigned af[8][4];
#pragma unroll
    for (int kk = 0; kk < 8; kk++) {
        af[kk][0] = __float_as_uint(As[(sr + g    )*PADA + 8*kk + q    ]);
        af[kk][1] = __float_as_uint(As[(sr + g + 8)*PADA + 8*kk + q    ]);
        af[kk][2] = __float_as_uint(As[(sr + g    )*PADA + 8*kk + q + 4]);
        af[kk][3] = __float_as_uint(As[(sr + g + 8)*PADA + 8*kk + q + 4]);
    }

    // ---- phase r (WB0): rh = tf32(sigm(A@Wxr + b) * Hp) -> RHs
    cp_wait1(); __syncthreads();
    {
        float racc[16][4];
#pragma unroll
        for (int c = 0; c < 16; c++) { racc[c][0]=0.f; racc[c][1]=0.f; racc[c][2]=0.f; racc[c][3]=0.f; }
#pragma unroll
        for (int kk = 0; kk < 8; kk++) {
#pragma unroll
            for (int cc = 0; cc < 16; cc++) {
                unsigned b0 = __float_as_uint(WB0[(8*kk + q    )*PADW + 8*cc + g]);
                unsigned b1 = __float_as_uint(WB0[(8*kk + q + 4)*PADW + 8*cc + g]);
                mma8(racc[cc], af[kk], b0, b1);
            }
        }
#pragma unroll
        for (int cc = 0; cc < 16; cc++) {
            int col = 8*cc + 2*q;
            float2 br = __ldg((const float2*)(b_xr + col));
            float2 h0 = __ldg((const float2*)(Hp + (size_t)(R0 + g    )*HD + col));
            float2 h1 = __ldg((const float2*)(Hp + (size_t)(R0 + g + 8)*HD + col));
            *(float2*)(&RHs[(sr + g    )*PADH + col]) =
                make_float2(to_tf32(sigm(racc[cc][0] + br.x) * h0.x),
                            to_tf32(sigm(racc[cc][1] + br.y) * h0.y));
            *(float2*)(&RHs[(sr + g + 8)*PADH + col]) =
                make_float2(to_tf32(sigm(racc[cc][2] + br.x) * h1.x),
                            to_tf32(sigm(racc[cc][3] + br.y) * h1.y));
        }
    }
    __syncthreads();
    stage_w128(WB0, WT_xh, t); cp_commit();   // c2

    // ---- phase z (WB1): Zs = sigm(A@Wxz + b)
    cp_wait1(); __syncthreads();
    {
        float zacc[16][4];
#pragma unroll
        for (int c = 0; c < 16; c++) { zacc[c][0]=0.f; zacc[c][1]=0.f; zacc[c][2]=0.f; zacc[c][3]=0.f; }
#pragma unroll
        for (int kk = 0; kk < 8; kk++) {
#pragma unroll
            for (int cc = 0; cc < 16; cc++) {
                unsigned b0 = __float_as_uint(WB1[(8*kk + q    )*PADW + 8*cc + g]);
                unsigned b1 = __float_as_uint(WB1[(8*kk + q + 4)*PADW + 8*cc + g]);
                mma8(zacc[cc], af[kk], b0, b1);
            }
        }
#pragma unroll
        for (int cc = 0; cc < 16; cc++) {
            int col = 8*cc + 2*q;
            float2 bz = __ldg((const float2*)(b_xz + col));
            *(float2*)(&Zs[(sr + g    )*PADH + col]) =
                make_float2(sigm(zacc[cc][0] + bz.x), sigm(zacc[cc][1] + bz.y));
            *(float2*)(&Zs[(sr + g + 8)*PADH + col]) =
                make_float2(sigm(zacc[cc][2] + bz.x), sigm(zacc[cc][3] + bz.y));
        }
    }
    __syncthreads();
    stage_w128(WB1, WT_hh, t); cp_commit();   // c3 (hh rows 0-63)

    // ---- phase xh (WB0): xacc = X@Wxh  (accumulator persists through hh)
    float xacc[16][4];
#pragma unroll
    for (int c = 0; c < 16; c++) { xacc[c][0]=0.f; xacc[c][1]=0.f; xacc[c][2]=0.f; xacc[c][3]=0.f; }
    cp_wait1(); __syncthreads();
    {
#pragma unroll
        for (int kk = 0; kk < 8; kk++) {
            unsigned a4[4];
            a4[0] = __float_as_uint(Xs[(sr + g    )*PADA + 8*kk + q    ]);
            a4[1] = __float_as_uint(Xs[(sr + g + 8)*PADA + 8*kk + q    ]);
            a4[2] = __float_as_uint(Xs[(sr + g    )*PADA + 8*kk + q + 4]);
            a4[3] = __float_as_uint(Xs[(sr + g + 8)*PADA + 8*kk + q + 4]);
#pragma unroll
            for (int cc = 0; cc < 16; cc++) {
                unsigned b0 = __float_as_uint(WB0[(8*kk + q    )*PADW + 8*cc + g]);
                unsigned b1 = __float_as_uint(WB0[(8*kk + q + 4)*PADW + 8*cc + g]);
                mma8(xacc[cc], a4, b0, b1);
            }
        }
    }
    __syncthreads();
    stage_w128(WB0, WT_hh + 64*HD, t); cp_commit();   // c4 (hh rows 64-127)

    // ---- phase hh-lo (WB1): xacc += rh[:,0:64] @ Whh[0:64,:]
    cp_wait1(); __syncthreads();
#pragma unroll
    for (int kk = 0; kk < 8; kk++) {
        unsigned a4[4];
        a4[0] = __float_as_uint(RHs[(sr + g    )*PADH + 8*kk + q    ]);
        a4[1] = __float_as_uint(RHs[(sr + g + 8)*PADH + 8*kk + q    ]);
        a4[2] = __float_as_uint(RHs[(sr + g    )*PADH + 8*kk + q + 4]);
        a4[3] = __float_as_uint(RHs[(sr + g + 8)*PADH + 8*kk + q + 4]);
#pragma unroll
        for (int cc = 0; cc < 16; cc++) {
            unsigned b0 = __float_as_uint(WB1[(8*kk + q    )*PADW + 8*cc + g]);
            unsigned b1 = __float_as_uint(WB1[(8*kk + q + 4)*PADW + 8*cc + g]);
            mma8(xacc[cc], a4, b0, b1);
        }
    }
    __syncthreads();
    stage_w64(WB1, WT_y, t); cp_commit();     // c5 (y rows 0-63)

    // ---- phase hh-hi (WB0): xacc += rh[:,64:128] @ Whh[64:128,:]
    cp_wait1(); __syncthreads();
#pragma unroll
    for (int kk = 0; kk < 8; kk++) {
        unsigned a4[4];
        a4[0] = __float_as_uint(RHs[(sr + g    )*PADH + 64 + 8*kk + q    ]);
        a4[1] = __float_as_uint(RHs[(sr + g + 8)*PADH + 64 + 8*kk + q    ]);
        a4[2] = __float_as_uint(RHs[(sr + g    )*PADH + 64 + 8*kk + q + 4]);
        a4[3] = __float_as_uint(RHs[(sr + g + 8)*PADH + 64 + 8*kk + q + 4]);
#pragma unroll
        for (int cc = 0; cc < 16; cc++) {
            unsigned b0 = __float_as_uint(WB0[(8*kk + q    )*PADW + 8*cc + g]);
            unsigned b1 = __float_as_uint(WB0[(8*kk + q + 4)*PADW + 8*cc + g]);
            mma8(xacc[cc], a4, b0, b1);
        }
    }
    __syncthreads();
    stage_w64(WB0, WT_y + 64*Cc, t); cp_commit();   // c6 (y rows 64-127)

    // ---- phase Hn: Hn = z*Hp + (1-z)*tanh(xacc + b_xh + b_hh) -> H_out, Hns
    // (As/Xs dead for ALL warps since the barrier before hh-lo; Hns overlays them)
#pragma unroll
    for (int cc = 0; cc < 16; cc++) {
        int col = 8*cc + 2*q;
        float2 bh = __ldg((const float2*)(b_xh + col));
        float2 bg = __ldg((const float2*)(b_hh + col));
        float2 h0 = __ldg((const float2*)(Hp + (size_t)(R0 + g    )*HD + col));
        float2 h1 = __ldg((const float2*)(Hp + (size_t)(R0 + g + 8)*HD + col));
        float2 z0 = *(const float2*)(&Zs[(sr + g    )*PADH + col]);
        float2 z1 = *(const float2*)(&Zs[(sr + g + 8)*PADH + col]);
        float c00 = tanhf(xacc[cc][0] + bh.x + bg.x);
        float c01 = tanhf(xacc[cc][1] + bh.y + bg.y);
        float c10 = tanhf(xacc[cc][2] + bh.x + bg.x);
        float c11 = tanhf(xacc[cc][3] + bh.y + bg.y);
        float H00 = z0.x*h0.x + (1.f - z0.x)*c00;
        float H01 = z0.y*h0.y + (1.f - z0.y)*c01;
        float H10 = z1.x*h1.x + (1.f - z1.x)*c10;
        float H11 = z1.y*h1.y + (1.f - z1.y)*c11;
        *(float2*)(&H_out[(size_t)(R0 + g    )*HD + col]) = make_float2(H00, H01);
        *(float2*)(&H_out[(size_t)(R0 + g + 8)*HD + col]) = make_float2(H10, H11);
        *(float2*)(&Hns[(sr + g    )*PADH + col]) = make_float2(to_tf32(H00), to_tf32(H01));
        *(float2*)(&Hns[(sr + g + 8)*PADH + col]) = make_float2(to_tf32(H10), to_tf32(H11));
    }
    __syncwarp();

    // ---- phase y (2 chunks): y = Hn @ WT_y + b_y
    float yac[8][4];
#pragma unroll
    for (int c = 0; c < 8; c++) { yac[c][0]=0.f; yac[c][1]=0.f; yac[c][2]=0.f; yac[c][3]=0.f; }
    cp_wait1(); __syncthreads();      // c5 ready (y-lo, WB1)
#pragma unroll
    for (int kk = 0; kk < 8; kk++) {
        unsigned a4[4];
        a4[0] = __float_as_uint(Hns[(sr + g    )*PADH + 8*kk + q    ]);
        a4[1] = __float_as_uint(Hns[(sr + g + 8)*PADH + 8*kk + q    ]);
        a4[2] = __float_as_uint(Hns[(sr + g    )*PADH + 8*kk + q + 4]);
        a4[3] = __float_as_uint(Hns[(sr + g + 8)*PADH + 8*kk + q + 4]);
#pragma unroll
        for (int cc = 0; cc < 8; cc++) {
            unsigned b0 = __float_as_uint(WB1[(8*kk + q    )*PADW + 8*cc + g]);
            unsigned b1 = __float_as_uint(WB1[(8*kk + q + 4)*PADW + 8*cc + g]);
            mma8(yac[cc], a4, b0, b1);
        }
    }
    cp_wait_all(); __syncthreads();   // c6 ready (y-hi, WB0)
#pragma unroll
    for (int kk = 0; kk < 8; kk++) {
        unsigned a4[4];
        a4[0] = __float_as_uint(Hns[(sr + g    )*PADH + 64 + 8*kk + q    ]);
        a4[1] = __float_as_uint(Hns[(sr + g + 8)*PADH + 64 + 8*kk + q    ]);
        a4[2] = __float_as_uint(Hns[(sr + g    )*PADH + 64 + 8*kk + q + 4]);
        a4[3] = __float_as_uint(Hns[(sr + g + 8)*PADH + 64 + 8*kk + q + 4]);
#pragma unroll
        for (int cc = 0; cc < 8; cc++) {
            unsigned b0 = __float_as_uint(WB0[(8*kk + q    )*PADW + 8*cc + g]);
            unsigned b1 = __float_as_uint(WB0[(8*kk + q + 4)*PADW + 8*cc + g]);
            mma8(yac[cc], a4, b0, b1);
        }
    }
#pragma unroll
    for (int cc = 0; cc < 8; cc++) {
        int col = 8*cc + 2*q;
        float2 by = __ldg((const float2*)(b_y + col));
        *(float2*)(&y_out[(size_t)(R0 + g    )*Cc + col]) =
            make_float2(yac[cc][0] + by.x, yac[cc][1] + by.y);
        *(float2*)(&y_out[(size_t)(R0 + g + 8)*Cc + col]) =
            make_float2(yac[cc][2] + by.x, yac[cc][3] + by.y);
    }
}

// ---------------------------------------------------------------------------
extern "C" void kernel_launch(void* const* d_in, const int* in_sizes, int n_in,
                              void* d_out, int out_size) {
    const float* Hp    = (const float*)d_in[0];
    const float* X     = (const float*)d_in[1];
    const float* W_xr  = (const float*)d_in[2];
    const float* b_xr  = (const float*)d_in[3];
    const float* W_xz  = (const float*)d_in[4];
    const float* b_xz  = (const float*)d_in[5];
    const float* W_xh  = (const float*)d_in[6];
    const float* b_xh  = (const float*)d_in[7];
    const float* W_hh  = (const float*)d_in[8];
    const float* b_hh  = (const float*)d_in[9];
    const float* W_ha1 = (const float*)d_in[10];
    const float* W_ha2 = (const float*)d_in[11];
    const float* b_ha2 = (const float*)d_in[12];
    const float* W_y   = (const float*)d_in[13];
    const float* b_y   = (const float*)d_in[14];

    float* out = (float*)d_out;
    float* y_out = out;                        // [B,N,C]
    float* H_out = out + (size_t)Bb*Nn*Cc;     // [B,N,Hd]

    transpose_all<<<(73728 + 255)/256, 256>>>(W_xr, W_xz, W_xh, W_hh, W_ha1, W_ha2, W_y);

    size_t smem_prep = (size_t)(64*PADA + 64*PADH + 2*64*PADW) * sizeof(float);   // 120832
    cudaFuncSetAttribute(prep_mma, cudaFuncAttributeMaxDynamicSharedMemorySize, (int)smem_prep);
    prep_mma<<<Bb*Nn/64, 128, smem_prep>>>(X, Hp, b_ha2);

    size_t smem_attn = (size_t)(2*KT*KPAD + 2*KT*VPAD + QT*PPAD) * sizeof(float);  // 61440
    cudaFuncSetAttribute(attn_kernel, cudaFuncAttributeMaxDynamicSharedMemorySize, (int)smem_attn);
    attn_kernel<<<dim3(Nn/QT, Bb), 128, smem_attn>>>();

    size_t smem_gru = (size_t)(2*64*PADA + 2*64*PADH + 2*64*PADW) * sizeof(float); // 172032
    cudaFuncSetAttribute(gru_mma, cudaFuncAttributeMaxDynamicSharedMemorySize, (int)smem_gru);
    gru_mma<<<Bb*Nn/64, 128, smem_gru>>>(Hp, b_xr, b_xz, b_xh, b_hh, b_y, y_out, H_out);
}

// round 14
// speedup vs baseline: 24.5121x; 1.0336x over previous
#include <cuda_runtime.h>

#define Bb 8
#define Nn 2048
#define Cc 64
#define HD 128

#define QT 64      // attn queries per block (4 warps x 16 rows)
#define KT 32      // attn keys per tile
#define KPAD 132   // (4g+q) banks, conflict-free frag loads
#define VPAD 72
#define PPAD 36
#define PADA 68    // 64-col activation tiles
#define PADH 132   // 128-col activation tiles
#define PADW 136   // weight chunks: B-frag bank (8q+8cc+g)%32 all-distinct

// scratch (allocation-free rule: __device__ globals)
__device__ float g_lhs[Bb*Nn*HD];   // tf32 Q
__device__ float g_rhs[Bb*Nn*HD];   // tf32 K
__device__ float g_Xc[Bb*Nn*Cc];    // tf32 X
__device__ float g_A[Bb*Nn*Cc];

// transposed weights [in][out]
__device__ float WT_xr[Cc*HD];
__device__ float WT_xz[Cc*HD];
__device__ float WT_xh[Cc*HD];
__device__ float WT_hh[HD*HD];
__device__ float WT_ha1[Cc*HD];
__device__ float WT_ha2[HD*HD];
__device__ float WT_y[HD*Cc];

__device__ __forceinline__ void cp_async16(void* smem_dst, const void* gmem_src) {
    unsigned s = (unsigned)__cvta_generic_to_shared(smem_dst);
    asm volatile("cp.async.ca.shared.global [%0], [%1], 16;\n" :: "r"(s), "l"(gmem_src));
}
__device__ __forceinline__ void cp_commit() { asm volatile("cp.async.commit_group;\n"); }
__device__ __forceinline__ void cp_wait_all() { asm volatile("cp.async.wait_group 0;\n" ::: "memory"); }
__device__ __forceinline__ void cp_wait1()   { asm volatile("cp.async.wait_group 1;\n" ::: "memory"); }

__device__ __forceinline__ float to_tf32(float x) {
    unsigned u;
    asm("cvt.rna.tf32.f32 %0, %1;" : "=r"(u) : "f"(x));
    return __uint_as_float(u);
}
__device__ __forceinline__ float sigm(float x) { return 1.f / (1.f + __expf(-x)); }

// D += A(16x8,row) * B(8x8,col)   tf32 inputs, f32 accum
__device__ __forceinline__ void mma8(float* c, const unsigned* a, unsigned b0, unsigned b1) {
    asm volatile(
        "mma.sync.aligned.m16n8k8.row.col.f32.tf32.tf32.f32 "
        "{%0,%1,%2,%3}, {%4,%5,%6,%7}, {%8,%9}, {%0,%1,%2,%3};\n"
        : "+f"(c[0]), "+f"(c[1]), "+f"(c[2]), "+f"(c[3])
        : "r"(a[0]), "r"(a[1]), "r"(a[2]), "r"(a[3]), "r"(b0), "r"(b1));
}
__device__ __forceinline__ unsigned ldw(const float* p) { return __float_as_uint(__ldg(p)); }

// stage 64 rows x 128 cols of a row-major [*][128] weight into WB (stride PADW)
__device__ __forceinline__ void stage_w128(float* dst, const float* src, int t) {
#pragma unroll
    for (int i = 0; i < 16; i++) {
        int idx = t + 128*i;
        int r = idx >> 5, c4 = idx & 31;
        cp_async16(dst + r*PADW + 4*c4, src + r*HD + 4*c4);
    }
}

// ---------------------------------------------------------------------------
// Kernel 0: all 7 weight transposes in one launch.
// ---------------------------------------------------------------------------
__global__ void transpose_all(const float* __restrict__ W_xr, const float* __restrict__ W_xz,
                              const float* __restrict__ W_xh, const float* __restrict__ W_hh,
                              const float* __restrict__ W_ha1, const float* __restrict__ W_ha2,
                              const float* __restrict__ W_y) {
    int i = blockIdx.x * 256 + threadIdx.x;
    const float* src; float* dst; int R, C, off;
    if      (i < 8192)  { src = W_xr;  dst = WT_xr;  R = HD; C = Cc; off = 0; }
    else if (i < 16384) { src = W_xz;  dst = WT_xz;  R = HD; C = Cc; off = 8192; }
    else if (i < 24576) { src = W_xh;  dst = WT_xh;  R = HD; C = Cc; off = 16384; }
    else if (i < 40960) { src = W_hh;  dst = WT_hh;  R = HD; C = HD; off = 24576; }
    else if (i < 49152) { src = W_ha1; dst = WT_ha1; R = HD; C = Cc; off = 40960; }
    else if (i < 65536) { src = W_ha2; dst = WT_ha2; R = HD; C = HD; off = 49152; }
    else if (i < 73728) { src = W_y;   dst = WT_y;   R = Cc; C = HD; off = 65536; }
    else return;
    int j = i - off;
    int r = j / C, c = j - r*C;
    dst[c*R + r] = src[j];
}

// ---------------------------------------------------------------------------
// Kernel 1: prep via mma with smem-staged weights (unchanged from R12).
// ---------------------------------------------------------------------------
__global__ void __launch_bounds__(128) prep_mma(const float* __restrict__ X,
                                                const float* __restrict__ Hp,
                                                const float* __restrict__ b_ha2) {
    extern __shared__ float sm[];
    float* Xs  = sm;
    float* Hs  = Xs + 64*PADA;
    float* WB0 = Hs + 64*PADH;
    float* WB1 = WB0 + 64*PADW;

    const int t = threadIdx.x;
    const int w = t >> 5, lane = t & 31;
    const int g = lane >> 2, q = lane & 3;
    const int R0 = blockIdx.x * 64 + 16*w;
    const int sr = 16*w;

    stage_w128(WB0, WT_ha1, t); cp_commit();
    stage_w128(WB1, WT_ha2, t); cp_commit();

#pragma unroll
    for (int i = 0; i < 8; i++) {
        int idx = lane + 32*i;
        int r = idx >> 4, c4 = idx & 15;
        float4 v = *(const float4*)(X + (size_t)(R0 + r)*Cc + 4*c4);
        v.x = to_tf32(v.x); v.y = to_tf32(v.y); v.z = to_tf32(v.z); v.w = to_tf32(v.w);
        *(float4*)(&Xs[(sr + r)*PADA + 4*c4]) = v;
        *(float4*)(&g_Xc[(size_t)(R0 + r)*Cc + 4*c4]) = v;
    }
#pragma unroll
    for (int i = 0; i < 16; i++) {
        int idx = lane + 32*i;
        int r = idx >> 5, c4 = idx & 31;
        float4 v = *(const float4*)(Hp + (size_t)(R0 + r)*HD + 4*c4);
        v.x = to_tf32(v.x); v.y = to_tf32(v.y); v.z = to_tf32(v.z); v.w = to_tf32(v.w);
        *(float4*)(&Hs[(sr + r)*PADH + 4*c4]) = v;
    }
    __syncwarp();

    unsigned af[8][4];
#pragma unroll
    for (int kk = 0; kk < 8; kk++) {
        af[kk][0] = __float_as_uint(Xs[(sr + g    )*PADA + 8*kk + q    ]);
        af[kk][1] = __float_as_uint(Xs[(sr + g + 8)*PADA + 8*kk + q    ]);
        af[kk][2] = __float_as_uint(Xs[(sr + g    )*PADA + 8*kk + q + 4]);
        af[kk][3] = __float_as_uint(Xs[(sr + g + 8)*PADA + 8*kk + q + 4]);
    }

    float acc[16][4];

    cp_wait1(); __syncthreads();
#pragma unroll
    for (int c = 0; c < 16; c++) { acc[c][0]=0.f; acc[c][1]=0.f; acc[c][2]=0.f; acc[c][3]=0.f; }
#pragma unroll
    for (int kk = 0; kk < 8; kk++) {
#pragma unroll
        for (int cc = 0; cc < 16; cc++) {
            unsigned b0 = __float_as_uint(WB0[(8*kk + q    )*PADW + 8*cc + g]);
            unsigned b1 = __float_as_uint(WB0[(8*kk + q + 4)*PADW + 8*cc + g]);
            mma8(acc[cc], af[kk], b0, b1);
        }
    }
#pragma unroll
    for (int cc = 0; cc < 16; cc++) {
        int col = 8*cc + 2*q;
        *(float2*)(&g_lhs[(size_t)(R0 + g    )*HD + col]) = make_float2(to_tf32(acc[cc][0]), to_tf32(acc[cc][1]));
        *(float2*)(&g_lhs[(size_t)(R0 + g + 8)*HD + col]) = make_float2(to_tf32(acc[cc][2]), to_tf32(acc[cc][3]));
    }
    __syncthreads();
    stage_w128(WB0, WT_ha2 + 64*HD, t); cp_commit();

    cp_wait1(); __syncthreads();
#pragma unroll
    for (int c = 0; c < 16; c++) { acc[c][0]=0.f; acc[c][1]=0.f; acc[c][2]=0.f; acc[c][3]=0.f; }
#pragma unroll
    for (int kk = 0; kk < 8; kk++) {
        unsigned a4[4];
        a4[0] = __float_as_uint(Hs[(sr + g    )*PADH + 8*kk + q    ]);
        a4[1] = __float_as_uint(Hs[(sr + g + 8)*PADH + 8*kk + q    ]);
        a4[2] = __float_as_uint(Hs[(sr + g    )*PADH + 8*kk + q + 4]);
        a4[3] = __float_as_uint(Hs[(sr + g + 8)*PADH + 8*kk + q + 4]);
#pragma unroll
        for (int cc = 0; cc < 16; cc++) {
            unsigned b0 = __float_as_uint(WB1[(8*kk + q    )*PADW + 8*cc + g]);
            unsigned b1 = __float_as_uint(WB1[(8*kk + q + 4)*PADW + 8*cc + g]);
            mma8(acc[cc], a4, b0, b1);
        }
    }
    cp_wait_all(); __syncthreads();
#pragma unroll
    for (int kk = 0; kk < 8; kk++) {
        unsigned a4[4];
        a4[0] = __float_as_uint(Hs[(sr + g    )*PADH + 64 + 8*kk + q    ]);
        a4[1] = __float_as_uint(Hs[(sr + g + 8)*PADH + 64 + 8*kk + q    ]);
        a4[2] = __float_as_uint(Hs[(sr + g    )*PADH + 64 + 8*kk + q + 4]);
        a4[3] = __float_as_uint(Hs[(sr + g + 8)*PADH + 64 + 8*kk + q + 4]);
#pragma unroll
        for (int cc = 0; cc < 16; cc++) {
            unsigned b0 = __float_as_uint(WB0[(8*kk + q    )*PADW + 8*cc + g]);
            unsigned b1 = __float_as_uint(WB0[(8*kk + q + 4)*PADW + 8*cc + g]);
            mma8(acc[cc], a4, b0, b1);
        }
    }
#pragma unroll
    for (int cc = 0; cc < 16; cc++) {
        int col = 8*cc + 2*q;
        float2 bv = __ldg((const float2*)(b_ha2 + col));
        *(float2*)(&g_rhs[(size_t)(R0 + g    )*HD + col]) =
            make_float2(to_tf32(acc[cc][0] + bv.x), to_tf32(acc[cc][1] + bv.y));
        *(float2*)(&g_rhs[(size_t)(R0 + g + 8)*HD + col]) =
            make_float2(to_tf32(acc[cc][2] + bv.x), to_tf32(acc[cc][3] + bv.y));
    }
}

// ---------------------------------------------------------------------------
// Kernel 2: flash attention on mma.sync tf32 (unchanged; 3 CTAs/SM).
// ---------------------------------------------------------------------------
__global__ void __launch_bounds__(128, 3) attn_kernel() {
    extern __shared__ float sm[];
    float* Kb0 = sm;
    float* Vb0 = Kb0 + KT*KPAD;
    float* Kb1 = Vb0 + KT*VPAD;
    float* Vb1 = Kb1 + KT*KPAD;
    float* Ps  = Vb1 + KT*VPAD;
    float* Qstage = Kb1;

    const int b  = blockIdx.y;
    const int q0 = blockIdx.x * QT;
    const int t  = threadIdx.x;
    const int w  = t >> 5;
    const int lane = t & 31;
    const int g = lane >> 2;
    const int q = lane & 3;

    const float* Kg = g_rhs + (size_t)b*Nn*HD;
    const float* Vg = g_Xc  + (size_t)b*Nn*Cc;

    {
        const int kr = t >> 2, kc = t & 3;
#pragma unroll
        for (int i = 0; i < 8; i++)
            cp_async16(&Kb0[kr*KPAD + (kc + 4*i)*4], Kg + kr*HD + (kc + 4*i)*4);
#pragma unroll
        for (int i = 0; i < 4; i++)
            cp_async16(&Vb0[kr*VPAD + (kc + 4*i)*4], Vg + kr*Cc + (kc + 4*i)*4);
        cp_commit();
    }

    {
        const float* Qg = g_lhs + (size_t)(b*Nn + q0)*HD;
        for (int idx = t; idx < QT*(HD/4); idx += 128) {
            int r = idx >> 5, c4 = idx & 31;
            float4 v = ((const float4*)(Qg + r*HD))[c4];
            *(float4*)(&Qstage[r*KPAD + c4*4]) = v;
        }
    }
    __syncthreads();

    unsigned qf[16][4];
#pragma unroll
    for (int kk = 0; kk < 16; kk++) {
        qf[kk][0] = __float_as_uint(Qstage[(16*w + g    )*KPAD + 8*kk + q    ]);
        qf[kk][1] = __float_as_uint(Qstage[(16*w + g + 8)*KPAD + 8*kk + q    ]);
        qf[kk][2] = __float_as_uint(Qstage[(16*w + g    )*KPAD + 8*kk + q + 4]);
        qf[kk][3] = __float_as_uint(Qstage[(16*w + g + 8)*KPAD + 8*kk + q + 4]);
    }
    __syncthreads();

    float oacc[8][4];
#pragma unroll
    for (int c = 0; c < 8; c++)
#pragma unroll
        for (int j = 0; j < 4; j++) oacc[c][j] = 0.f;
    float m0 = -1e30f, m1 = -1e30f, l0 = 0.f, l1 = 0.f;

    float* Pw = Ps + 16*w*PPAD;

    const int NT = Nn / KT;
    for (int it = 0; it < NT; it++) {
        float* KsB = (it & 1) ? Kb1 : Kb0;
        float* VsB = (it & 1) ? Vb1 : Vb0;

        cp_wait_all();
        __syncthreads();

        if (it + 1 < NT) {
            float* KsN = (it & 1) ? Kb0 : Kb1;
            float* VsN = (it & 1) ? Vb0 : Vb1;
            const int k1 = (it + 1) * KT;
            const int kr = t >> 2, kc = t & 3;
#pragma unroll
            for (int i = 0; i < 8; i++)
                cp_async16(&KsN[kr*KPAD + (kc + 4*i)*4], Kg + (k1 + kr)*HD + (kc + 4*i)*4);
#pragma unroll
            for (int i = 0; i < 4; i++)
                cp_async16(&VsN[kr*VPAD + (kc + 4*i)*4], Vg + (k1 + kr)*Cc + (kc + 4*i)*4);
            cp_commit();
        }

        float sacc[4][4];
#pragma unroll
        for (int c = 0; c < 4; c++)
#pragma unroll
            for (int j = 0; j < 4; j++) sacc[c][j] = 0.f;

#pragma unroll
        for (int kk = 0; kk < 16; kk++) {
#pragma unroll
            for (int cc = 0; cc < 4; cc++) {
                unsigned b0 = __float_as_uint(KsB[(8*cc + g)*KPAD + 8*kk + q    ]);
                unsigned b1 = __float_as_uint(KsB[(8*cc + g)*KPAD + 8*kk + q + 4]);
                mma8(sacc[cc], qf[kk], b0, b1);
            }
        }

#pragma unroll
        for (int c = 0; c < 4; c++)
#pragma unroll
            for (int j = 0; j < 4; j++) {
                float v = sacc[c][j];
                sacc[c][j] = (v > 0.f) ? v : 0.01f*v;
            }

        float mx0 = -1e30f, mx1 = -1e30f;
#pragma unroll
        for (int c = 0; c < 4; c++) {
            mx0 = fmaxf(mx0, fmaxf(sacc[c][0], sacc[c][1]));
            mx1 = fmaxf(mx1, fmaxf(sacc[c][2], sacc[c][3]));
        }
        mx0 = fmaxf(mx0, __shfl_xor_sync(0xffffffffu, mx0, 1));
        mx0 = fmaxf(mx0, __shfl_xor_sync(0xffffffffu, mx0, 2));
        mx1 = fmaxf(mx1, __shfl_xor_sync(0xffffffffu, mx1, 1));
        mx1 = fmaxf(mx1, __shfl_xor_sync(0xffffffffu, mx1, 2));

        float mn0 = fmaxf(m0, mx0), mn1 = fmaxf(m1, mx1);
        float al0 = __expf(m0 - mn0), al1 = __expf(m1 - mn1);
        m0 = mn0; m1 = mn1;

        float rs0 = 0.f, rs1 = 0.f;
#pragma unroll
        for (int c = 0; c < 4; c++) {
            sacc[c][0] = __expf(sacc[c][0] - m0);
            sacc[c][1] = __expf(sacc[c][1] - m0);
            sacc[c][2] = __expf(sacc[c][2] - m1);
            sacc[c][3] = __expf(sacc[c][3] - m1);
            rs0 += sacc[c][0] + sacc[c][1];
            rs1 += sacc[c][2] + sacc[c][3];
        }
        rs0 += __shfl_xor_sync(0xffffffffu, rs0, 1);
        rs0 += __shfl_xor_sync(0xffffffffu, rs0, 2);
        rs1 += __shfl_xor_sync(0xffffffffu, rs1, 1);
        rs1 += __shfl_xor_sync(0xffffffffu, rs1, 2);
        l0 = l0*al0 + rs0;
        l1 = l1*al1 + rs1;

#pragma unroll
        for (int c = 0; c < 8; c++) {
            oacc[c][0] *= al0; oacc[c][1] *= al0;
            oacc[c][2] *= al1; oacc[c][3] *= al1;
        }

#pragma unroll
        for (int c = 0; c < 4; c++) {
            *(float2*)(&Pw[(g    )*PPAD + 8*c + 2*q]) = make_float2(to_tf32(sacc[c][0]), to_tf32(sacc[c][1]));
            *(float2*)(&Pw[(g + 8)*PPAD + 8*c + 2*q]) = make_float2(to_tf32(sacc[c][2]), to_tf32(sacc[c][3]));
        }
        __syncwarp();

#pragma unroll
        for (int kk = 0; kk < 4; kk++) {
            unsigned pa[4];
            pa[0] = __float_as_uint(Pw[(g    )*PPAD + 8*kk + q    ]);
            pa[1] = __float_as_uint(Pw[(g + 8)*PPAD + 8*kk + q    ]);
            pa[2] = __float_as_uint(Pw[(g    )*PPAD + 8*kk + q + 4]);
            pa[3] = __float_as_uint(Pw[(g + 8)*PPAD + 8*kk + q + 4]);
#pragma unroll
            for (int cc = 0; cc < 8; cc++) {
                unsigned b0 = __float_as_uint(VsB[(8*kk + q    )*VPAD + 8*cc + g]);
                unsigned b1 = __float_as_uint(VsB[(8*kk + q + 4)*VPAD + 8*cc + g]);
                mma8(oacc[cc], pa, b0, b1);
            }
        }
    }

    float inv0 = 1.f / l0, inv1 = 1.f / l1;
    const int r0 = q0 + 16*w + g;
    const int r1 = r0 + 8;
#pragma unroll
    for (int cc = 0; cc < 8; cc++) {
        *(float2*)(&g_A[((size_t)(b*Nn + r0))*Cc + 8*cc + 2*q]) =
            make_float2(oacc[cc][0]*inv0, oacc[cc][1]*inv0);
        *(float2*)(&g_A[((size_t)(b*Nn + r1))*Cc + 8*cc + 2*q]) =
            make_float2(oacc[cc][2]*inv1, oacc[cc][3]*inv1);
    }
}

// ---------------------------------------------------------------------------
// Kernel 3 (v4): GRU via mma. Warp-independent, 16 rows/warp, 64 rows/CTA.
// A/X fragments direct from gmem (__ldg + to_tf32); weights direct L2 B-frag
// LDGs; only RHs+Zs in smem (67.6KB -> 3 CTAs/SM, whole grid resident).
// Phases per warp: r -> z -> xh -> hh(into xacc) -> Hn (overlay RHs) -> y.
// ---------------------------------------------------------------------------
__global__ void __launch_bounds__(128, 3) gru_mma(const float* __restrict__ Hp,
                                                  const float* __restrict__ b_xr,
                                                  const float* __restrict__ b_xz,
                                                  const float* __restrict__ b_xh,
                                                  const float* __restrict__ b_hh,
                                                  const float* __restrict__ b_y,
                                                  float* __restrict__ y_out,
                                                  float* __restrict__ H_out) {
    extern __shared__ float sm[];
    float* RHs = sm;                 // 64*PADH = 8448 floats
    float* Zs  = RHs + 64*PADH;      // 8448   (total 16896 floats = 67.6KB)
    float* Hns = RHs;                // overlays RHs after hh (per-warp rows only)

    const int t = threadIdx.x;
    const int w = t >> 5, lane = t & 31;
    const int g = lane >> 2, q = lane & 3;
    const int R0 = blockIdx.x * 64 + 16*w;
    const int sr = 16*w;

    // A fragments (rows R0+g / R0+g+8), tf32-rounded, cached for r and z
    unsigned af[8][4];
#pragma unroll
    for (int kk = 0; kk < 8; kk++) {
        af[kk][0] = __float_as_uint(to_tf32(__ldg(g_A + (size_t)(R0 + g    )*Cc + 8*kk + q    )));
        af[kk][1] = __float_as_uint(to_tf32(__ldg(g_A + (size_t)(R0 + g + 8)*Cc + 8*kk + q    )));
        af[kk][2] = __float_as_uint(to_tf32(__ldg(g_A + (size_t)(R0 + g    )*Cc + 8*kk + q + 4)));
        af[kk][3] = __float_as_uint(to_tf32(__ldg(g_A + (size_t)(R0 + g + 8)*Cc + 8*kk + q + 4)));
    }

    // ---- phase r: rh = tf32(sigm(A@Wxr + b) * Hp) -> RHs
    {
        float acc[16][4];
#pragma unroll
        for (int c = 0; c < 16; c++) { acc[c][0]=0.f; acc[c][1]=0.f; acc[c][2]=0.f; acc[c][3]=0.f; }
#pragma unroll
        for (int kk = 0; kk < 8; kk++) {
#pragma unroll
            for (int cc = 0; cc < 16; cc++) {
                unsigned b0 = ldw(WT_xr + (8*kk + q    )*HD + 8*cc + g);
                unsigned b1 = ldw(WT_xr + (8*kk + q + 4)*HD + 8*cc + g);
                mma8(acc[cc], af[kk], b0, b1);
            }
        }
#pragma unroll
        for (int cc = 0; cc < 16; cc++) {
            int col = 8*cc + 2*q;
            float2 br = __ldg((const float2*)(b_xr + col));
            float2 h0 = __ldg((const float2*)(Hp + (size_t)(R0 + g    )*HD + col));
            float2 h1 = __ldg((const float2*)(Hp + (size_t)(R0 + g + 8)*HD + col));
            *(float2*)(&RHs[(sr + g    )*PADH + col]) =
                make_float2(to_tf32(sigm(acc[cc][0] + br.x) * h0.x),
                            to_tf32(sigm(acc[cc][1] + br.y) * h0.y));
            *(float2*)(&RHs[(sr + g + 8)*PADH + col]) =
                make_float2(to_tf32(sigm(acc[cc][2] + br.x) * h1.x),
                            to_tf32(sigm(acc[cc][3] + br.y) * h1.y));
        }
    }

    // ---- phase z: Zs = sigm(A@Wxz + b)
    {
        float acc[16][4];
#pragma unroll
        for (int c = 0; c < 16; c++) { acc[c][0]=0.f; acc[c][1]=0.f; acc[c][2]=0.f; acc[c][3]=0.f; }
#pragma unroll
        for (int kk = 0; kk < 8; kk++) {
#pragma unroll
            for (int cc = 0; cc < 16; cc++) {
                unsigned b0 = ldw(WT_xz + (8*kk + q    )*HD + 8*cc + g);
                unsigned b1 = ldw(WT_xz + (8*kk + q + 4)*HD + 8*cc + g);
                mma8(acc[cc], af[kk], b0, b1);
            }
        }
#pragma unroll
        for (int cc = 0; cc < 16; cc++) {
            int col = 8*cc + 2*q;
            float2 bz = __ldg((const float2*)(b_xz + col));
            *(float2*)(&Zs[(sr + g    )*PADH + col]) =
                make_float2(sigm(acc[cc][0] + bz.x), sigm(acc[cc][1] + bz.y));
            *(float2*)(&Zs[(sr + g + 8)*PADH + col]) =
                make_float2(sigm(acc[cc][2] + bz.x), sigm(acc[cc][3] + bz.y));
        }
    }

    // ---- phase xh: xacc = X@Wxh  (X frags direct from g_Xc, already tf32)
    float xacc[16][4];
#pragma unroll
    for (int c = 0; c < 16; c++) { xacc[c][0]=0.f; xacc[c][1]=0.f; xacc[c][2]=0.f; xacc[c][3]=0.f; }
#pragma unroll
    for (int kk = 0; kk < 8; kk++) {
        unsigned a4[4];
        a4[0] = __float_as_uint(__ldg(g_Xc + (size_t)(R0 + g    )*Cc + 8*kk + q    ));
        a4[1] = __float_as_uint(__ldg(g_Xc + (size_t)(R0 + g + 8)*Cc + 8*kk + q    ));
        a4[2] = __float_as_uint(__ldg(g_Xc + (size_t)(R0 + g    )*Cc + 8*kk + q + 4));
        a4[3] = __float_as_uint(__ldg(g_Xc + (size_t)(R0 + g + 8)*Cc + 8*kk + q + 4));
#pragma unroll
        for (int cc = 0; cc < 16; cc++) {
            unsigned b0 = ldw(WT_xh + (8*kk + q    )*HD + 8*cc + g);
            unsigned b1 = ldw(WT_xh + (8*kk + q + 4)*HD + 8*cc + g);
            mma8(xacc[cc], a4, b0, b1);
        }
    }

    // ---- phase hh: xacc += rh @ Whh  (K=128 from RHs)
    __syncwarp();
#pragma unroll
    for (int kk = 0; kk < 16; kk++) {
        unsigned a4[4];
        a4[0] = __float_as_uint(RHs[(sr + g    )*PADH + 8*kk + q    ]);
        a4[1] = __float_as_uint(RHs[(sr + g + 8)*PADH + 8*kk + q    ]);
        a4[2] = __float_as_uint(RHs[(sr + g    )*PADH + 8*kk + q + 4]);
        a4[3] = __float_as_uint(RHs[(sr + g + 8)*PADH + 8*kk + q + 4]);
#pragma unroll
        for (int cc = 0; cc < 16; cc++) {
            unsigned b0 = ldw(WT_hh + (8*kk + q    )*HD + 8*cc + g);
            unsigned b1 = ldw(WT_hh + (8*kk + q + 4)*HD + 8*cc + g);
            mma8(xacc[cc], a4, b0, b1);
        }
    }
    __syncwarp();   // all lanes done reading RHs before Hns overlays it

    // ---- phase Hn: Hn = z*Hp + (1-z)*tanh(xacc + b_xh + b_hh)
#pragma unroll
    for (int cc = 0; cc < 16; cc++) {
        int col = 8*cc + 2*q;
        float2 bh = __ldg((const float2*)(b_xh + col));
        float2 bg = __ldg((const float2*)(b_hh + col));
        float2 h0 = __ldg((const float2*)(Hp + (size_t)(R0 + g    )*HD + col));
        float2 h1 = __ldg((const float2*)(Hp + (size_t)(R0 + g + 8)*HD + col));
        float2 z0 = *(const float2*)(&Zs[(sr + g    )*PADH + col]);
        float2 z1 = *(const float2*)(&Zs[(sr + g + 8)*PADH + col]);
        float c00 = tanhf(xacc[cc][0] + bh.x + bg.x);
        float c01 = tanhf(xacc[cc][1] + bh.y + bg.y);
        float c10 = tanhf(xacc[cc][2] + bh.x + bg.x);
        float c11 = tanhf(xacc[cc][3] + bh.y + bg.y);
        float H00 = z0.x*h0.x + (1.f - z0.x)*c00;
        float H01 = z0.y*h0.y + (1.f - z0.y)*c01;
        float H10 = z1.x*h1.x + (1.f - z1.x)*c10;
        float H11 = z1.y*h1.y + (1.f - z1.y)*c11;
        *(float2*)(&H_out[(size_t)(R0 + g    )*HD + col]) = make_float2(H00, H01);
        *(float2*)(&H_out[(size_t)(R0 + g + 8)*HD + col]) = make_float2(H10, H11);
        *(float2*)(&Hns[(sr + g    )*PADH + col]) = make_float2(to_tf32(H00), to_tf32(H01));
        *(float2*)(&Hns[(sr + g + 8)*PADH + col]) = make_float2(to_tf32(H10), to_tf32(H11));
    }
    __syncwarp();

    // ---- phase y: y = Hn @ WT_y + b_y  (K=128, N=64)
    {
        float yac[8][4];
#pragma unroll
        for (int c = 0; c < 8; c++) { yac[c][0]=0.f; yac[c][1]=0.f; yac[c][2]=0.f; yac[c][3]=0.f; }
#pragma unroll
        for (int kk = 0; kk < 16; kk++) {
            unsigned a4[4];
            a4[0] = __float_as_uint(Hns[(sr + g    )*PADH + 8*kk + q    ]);
            a4[1] = __float_as_uint(Hns[(sr + g + 8)*PADH + 8*kk + q    ]);
            a4[2] = __float_as_uint(Hns[(sr + g    )*PADH + 8*kk + q + 4]);
            a4[3] = __float_as_uint(Hns[(sr + g + 8)*PADH + 8*kk + q + 4]);
#pragma unroll
            for (int cc = 0; cc < 8; cc++) {
                unsigned b0 = ldw(WT_y + (8*kk + q    )*Cc + 8*cc + g);
                unsigned b1 = ldw(WT_y + (8*kk + q + 4)*Cc + 8*cc + g);
                mma8(yac[cc], a4, b0, b1);
            }
        }
#pragma unroll
        for (int cc = 0; cc < 8; cc++) {
            int col = 8*cc + 2*q;
            float2 by = __ldg((const float2*)(b_y + col));
            *(float2*)(&y_out[(size_t)(R0 + g    )*Cc + col]) =
                make_float2(yac[cc][0] + by.x, yac[cc][1] + by.y);
            *(float2*)(&y_out[(size_t)(R0 + g + 8)*Cc + col]) =
                make_float2(yac[cc][2] + by.x, yac[cc][3] + by.y);
        }
    }
}

// ---------------------------------------------------------------------------
extern "C" void kernel_launch(void* const* d_in, const int* in_sizes, int n_in,
                              void* d_out, int out_size) {
    const float* Hp    = (const float*)d_in[0];
    const float* X     = (const float*)d_in[1];
    const float* W_xr  = (const float*)d_in[2];
    const float* b_xr  = (const float*)d_in[3];
    const float* W_xz  = (const float*)d_in[4];
    const float* b_xz  = (const float*)d_in[5];
    const float* W_xh  = (const float*)d_in[6];
    const float* b_xh  = (const float*)d_in[7];
    const float* W_hh  = (const float*)d_in[8];
    const float* b_hh  = (const float*)d_in[9];
    const float* W_ha1 = (const float*)d_in[10];
    const float* W_ha2 = (const float*)d_in[11];
    const float* b_ha2 = (const float*)d_in[12];
    const float* W_y   = (const float*)d_in[13];
    const float* b_y   = (const float*)d_in[14];

    float* out = (float*)d_out;
    float* y_out = out;                        // [B,N,C]
    float* H_out = out + (size_t)Bb*Nn*Cc;     // [B,N,Hd]

    transpose_all<<<(73728 + 255)/256, 256>>>(W_xr, W_xz, W_xh, W_hh, W_ha1, W_ha2, W_y);

    size_t smem_prep = (size_t)(64*PADA + 64*PADH + 2*64*PADW) * sizeof(float);   // 120832
    cudaFuncSetAttribute(prep_mma, cudaFuncAttributeMaxDynamicSharedMemorySize, (int)smem_prep);
    prep_mma<<<Bb*Nn/64, 128, smem_prep>>>(X, Hp, b_ha2);

    size_t smem_attn = (size_t)(2*KT*KPAD + 2*KT*VPAD + QT*PPAD) * sizeof(float);  // 61440
    cudaFuncSetAttribute(attn_kernel, cudaFuncAttributeMaxDynamicSharedMemorySize, (int)smem_attn);
    attn_kernel<<<dim3(Nn/QT, Bb), 128, smem_attn>>>();

    size_t smem_gru = (size_t)(2*64*PADH) * sizeof(float);                         // 67584
    cudaFuncSetAttribute(gru_mma, cudaFuncAttributeMaxDynamicSharedMemorySize, (int)smem_gru);
    gru_mma<<<Bb*Nn/64, 128, smem_gru>>>(Hp, b_xr, b_xz, b_xh, b_hh, b_y, y_out, H_out);
}

// round 15
// speedup vs baseline: 24.9522x; 1.0180x over previous
#include <cuda_runtime.h>

#define Bb 8
#define Nn 2048
#define Cc 64
#define HD 128

#define QT 64      // attn queries per block (4 warps x 16 rows)
#define KT 32      // attn keys per tile
#define KPAD 132   // (4g+q) banks, conflict-free frag loads
#define VPAD 72
#define PPAD 36
#define PADA 68    // 64-col activation tiles
#define PADH 132   // 128-col activation tiles
#define PADW 136   // weight chunks in smem (prep)
#define WBLK 4224  // per-warp gru scratch block (floats) = 16*PADH*2

// scratch (allocation-free rule: __device__ globals)
__device__ float g_lhs[Bb*Nn*HD];   // tf32 Q
__device__ float g_rhs[Bb*Nn*HD];   // tf32 K
__device__ float g_Xc[Bb*Nn*Cc];    // tf32 X

// transposed weights [in][out]
__device__ float WT_xr[Cc*HD];
__device__ float WT_xz[Cc*HD];
__device__ float WT_xh[Cc*HD];
__device__ float WT_hh[HD*HD];
__device__ float WT_ha1[Cc*HD];
__device__ float WT_ha2[HD*HD];
__device__ float WT_y[HD*Cc];

__device__ __forceinline__ void cp_async16(void* smem_dst, const void* gmem_src) {
    unsigned s = (unsigned)__cvta_generic_to_shared(smem_dst);
    asm volatile("cp.async.ca.shared.global [%0], [%1], 16;\n" :: "r"(s), "l"(gmem_src));
}
__device__ __forceinline__ void cp_commit() { asm volatile("cp.async.commit_group;\n"); }
__device__ __forceinline__ void cp_wait_all() { asm volatile("cp.async.wait_group 0;\n" ::: "memory"); }
__device__ __forceinline__ void cp_wait1()   { asm volatile("cp.async.wait_group 1;\n" ::: "memory"); }

__device__ __forceinline__ float to_tf32(float x) {
    unsigned u;
    asm("cvt.rna.tf32.f32 %0, %1;" : "=r"(u) : "f"(x));
    return __uint_as_float(u);
}
__device__ __forceinline__ float sigm(float x) { return 1.f / (1.f + __expf(-x)); }

// D += A(16x8,row) * B(8x8,col)   tf32 inputs, f32 accum
__device__ __forceinline__ void mma8(float* c, const unsigned* a, unsigned b0, unsigned b1) {
    asm volatile(
        "mma.sync.aligned.m16n8k8.row.col.f32.tf32.tf32.f32 "
        "{%0,%1,%2,%3}, {%4,%5,%6,%7}, {%8,%9}, {%0,%1,%2,%3};\n"
        : "+f"(c[0]), "+f"(c[1]), "+f"(c[2]), "+f"(c[3])
        : "r"(a[0]), "r"(a[1]), "r"(a[2]), "r"(a[3]), "r"(b0), "r"(b1));
}
__device__ __forceinline__ unsigned ldw(const float* p) { return __float_as_uint(__ldg(p)); }

// stage 64 rows x 128 cols of a row-major [*][128] weight into WB (stride PADW)
__device__ __forceinline__ void stage_w128(float* dst, const float* src, int t) {
#pragma unroll
    for (int i = 0; i < 16; i++) {
        int idx = t + 128*i;
        int r = idx >> 5, c4 = idx & 31;
        cp_async16(dst + r*PADW + 4*c4, src + r*HD + 4*c4);
    }
}

// ---------------------------------------------------------------------------
// Kernel 0: all 7 weight transposes in one launch.
// ---------------------------------------------------------------------------
__global__ void transpose_all(const float* __restrict__ W_xr, const float* __restrict__ W_xz,
                              const float* __restrict__ W_xh, const float* __restrict__ W_hh,
                              const float* __restrict__ W_ha1, const float* __restrict__ W_ha2,
                              const float* __restrict__ W_y) {
    int i = blockIdx.x * 256 + threadIdx.x;
    const float* src; float* dst; int R, C, off;
    if      (i < 8192)  { src = W_xr;  dst = WT_xr;  R = HD; C = Cc; off = 0; }
    else if (i < 16384) { src = W_xz;  dst = WT_xz;  R = HD; C = Cc; off = 8192; }
    else if (i < 24576) { src = W_xh;  dst = WT_xh;  R = HD; C = Cc; off = 16384; }
    else if (i < 40960) { src = W_hh;  dst = WT_hh;  R = HD; C = HD; off = 24576; }
    else if (i < 49152) { src = W_ha1; dst = WT_ha1; R = HD; C = Cc; off = 40960; }
    else if (i < 65536) { src = W_ha2; dst = WT_ha2; R = HD; C = HD; off = 49152; }
    else if (i < 73728) { src = W_y;   dst = WT_y;   R = Cc; C = HD; off = 65536; }
    else return;
    int j = i - off;
    int r = j / C, c = j - r*C;
    dst[c*R + r] = src[j];
}

// ---------------------------------------------------------------------------
// Kernel 1: prep via mma with smem-staged weights (unchanged).
// ---------------------------------------------------------------------------
__global__ void __launch_bounds__(128) prep_mma(const float* __restrict__ X,
                                                const float* __restrict__ Hp,
                                                const float* __restrict__ b_ha2) {
    extern __shared__ float sm[];
    float* Xs  = sm;
    float* Hs  = Xs + 64*PADA;
    float* WB0 = Hs + 64*PADH;
    float* WB1 = WB0 + 64*PADW;

    const int t = threadIdx.x;
    const int w = t >> 5, lane = t & 31;
    const int g = lane >> 2, q = lane & 3;
    const int R0 = blockIdx.x * 64 + 16*w;
    const int sr = 16*w;

    stage_w128(WB0, WT_ha1, t); cp_commit();
    stage_w128(WB1, WT_ha2, t); cp_commit();

#pragma unroll
    for (int i = 0; i < 8; i++) {
        int idx = lane + 32*i;
        int r = idx >> 4, c4 = idx & 15;
        float4 v = *(const float4*)(X + (size_t)(R0 + r)*Cc + 4*c4);
        v.x = to_tf32(v.x); v.y = to_tf32(v.y); v.z = to_tf32(v.z); v.w = to_tf32(v.w);
        *(float4*)(&Xs[(sr + r)*PADA + 4*c4]) = v;
        *(float4*)(&g_Xc[(size_t)(R0 + r)*Cc + 4*c4]) = v;
    }
#pragma unroll
    for (int i = 0; i < 16; i++) {
        int idx = lane + 32*i;
        int r = idx >> 5, c4 = idx & 31;
        float4 v = *(const float4*)(Hp + (size_t)(R0 + r)*HD + 4*c4);
        v.x = to_tf32(v.x); v.y = to_tf32(v.y); v.z = to_tf32(v.z); v.w = to_tf32(v.w);
        *(float4*)(&Hs[(sr + r)*PADH + 4*c4]) = v;
    }
    __syncwarp();

    unsigned af[8][4];
#pragma unroll
    for (int kk = 0; kk < 8; kk++) {
        af[kk][0] = __float_as_uint(Xs[(sr + g    )*PADA + 8*kk + q    ]);
        af[kk][1] = __float_as_uint(Xs[(sr + g + 8)*PADA + 8*kk + q    ]);
        af[kk][2] = __float_as_uint(Xs[(sr + g    )*PADA + 8*kk + q + 4]);
        af[kk][3] = __float_as_uint(Xs[(sr + g + 8)*PADA + 8*kk + q + 4]);
    }

    float acc[16][4];

    cp_wait1(); __syncthreads();
#pragma unroll
    for (int c = 0; c < 16; c++) { acc[c][0]=0.f; acc[c][1]=0.f; acc[c][2]=0.f; acc[c][3]=0.f; }
#pragma unroll
    for (int kk = 0; kk < 8; kk++) {
#pragma unroll
        for (int cc = 0; cc < 16; cc++) {
            unsigned b0 = __float_as_uint(WB0[(8*kk + q    )*PADW + 8*cc + g]);
            unsigned b1 = __float_as_uint(WB0[(8*kk + q + 4)*PADW + 8*cc + g]);
            mma8(acc[cc], af[kk], b0, b1);
        }
    }
#pragma unroll
    for (int cc = 0; cc < 16; cc++) {
        int col = 8*cc + 2*q;
        *(float2*)(&g_lhs[(size_t)(R0 + g    )*HD + col]) = make_float2(to_tf32(acc[cc][0]), to_tf32(acc[cc][1]));
        *(float2*)(&g_lhs[(size_t)(R0 + g + 8)*HD + col]) = make_float2(to_tf32(acc[cc][2]), to_tf32(acc[cc][3]));
    }
    __syncthreads();
    stage_w128(WB0, WT_ha2 + 64*HD, t); cp_commit();

    cp_wait1(); __syncthreads();
#pragma unroll
    for (int c = 0; c < 16; c++) { acc[c][0]=0.f; acc[c][1]=0.f; acc[c][2]=0.f; acc[c][3]=0.f; }
#pragma unroll
    for (int kk = 0; kk < 8; kk++) {
        unsigned a4[4];
        a4[0] = __float_as_uint(Hs[(sr + g    )*PADH + 8*kk + q    ]);
        a4[1] = __float_as_uint(Hs[(sr + g + 8)*PADH + 8*kk + q    ]);
        a4[2] = __float_as_uint(Hs[(sr + g    )*PADH + 8*kk + q + 4]);
        a4[3] = __float_as_uint(Hs[(sr + g + 8)*PADH + 8*kk + q + 4]);
#pragma unroll
        for (int cc = 0; cc < 16; cc++) {
            unsigned b0 = __float_as_uint(WB1[(8*kk + q    )*PADW + 8*cc + g]);
            unsigned b1 = __float_as_uint(WB1[(8*kk + q + 4)*PADW + 8*cc + g]);
            mma8(acc[cc], a4, b0, b1);
        }
    }
    cp_wait_all(); __syncthreads();
#pragma unroll
    for (int kk = 0; kk < 8; kk++) {
        unsigned a4[4];
        a4[0] = __float_as_uint(Hs[(sr + g    )*PADH + 64 + 8*kk + q    ]);
        a4[1] = __float_as_uint(Hs[(sr + g + 8)*PADH + 64 + 8*kk + q    ]);
        a4[2] = __float_as_uint(Hs[(sr + g    )*PADH + 64 + 8*kk + q + 4]);
        a4[3] = __float_as_uint(Hs[(sr + g + 8)*PADH + 64 + 8*kk + q + 4]);
#pragma unroll
        for (int cc = 0; cc < 16; cc++) {
            unsigned b0 = __float_as_uint(WB0[(8*kk + q    )*PADW + 8*cc + g]);
            unsigned b1 = __float_as_uint(WB0[(8*kk + q + 4)*PADW + 8*cc + g]);
            mma8(acc[cc], a4, b0, b1);
        }
    }
#pragma unroll
    for (int cc = 0; cc < 16; cc++) {
        int col = 8*cc + 2*q;
        float2 bv = __ldg((const float2*)(b_ha2 + col));
        *(float2*)(&g_rhs[(size_t)(R0 + g    )*HD + col]) =
            make_float2(to_tf32(acc[cc][0] + bv.x), to_tf32(acc[cc][1] + bv.y));
        *(float2*)(&g_rhs[(size_t)(R0 + g + 8)*HD + col]) =
            make_float2(to_tf32(acc[cc][2] + bv.x), to_tf32(acc[cc][3] + bv.y));
    }
}

// ---------------------------------------------------------------------------
// Kernel 2: FUSED flash attention + GRU epilogue. 128 threads, 3 CTAs/SM.
// Attention identical to R14. After the KV loop each warp re-fragments its A
// tile through a private smem block and runs the full GRU for its 16 rows,
// overlapping other CTAs' attention mainloops.
// Per-warp block (WBLK=4224 floats at sm + w*WBLK):
//   As (stride PADA, dead after frag build) -> RHs [0,2112) / Zs [2112,4224)
//   -> Hns overlays RHs.
// ---------------------------------------------------------------------------
__global__ void __launch_bounds__(128, 3) attn_gru_kernel(
    const float* __restrict__ Hp,
    const float* __restrict__ b_xr, const float* __restrict__ b_xz,
    const float* __restrict__ b_xh, const float* __restrict__ b_hh,
    const float* __restrict__ b_y,
    float* __restrict__ y_out, float* __restrict__ H_out) {
    extern __shared__ float sm[];
    float* Kb0 = sm;
    float* Vb0 = Kb0 + KT*KPAD;
    float* Kb1 = Vb0 + KT*VPAD;
    float* Vb1 = Kb1 + KT*KPAD;
    float* Ps  = Vb1 + KT*VPAD;
    float* Qstage = Kb1;

    const int b  = blockIdx.y;
    const int q0 = blockIdx.x * QT;
    const int t  = threadIdx.x;
    const int w  = t >> 5;
    const int lane = t & 31;
    const int g = lane >> 2;
    const int q = lane & 3;

    const float* Kg = g_rhs + (size_t)b*Nn*HD;
    const float* Vg = g_Xc  + (size_t)b*Nn*Cc;

    {
        const int kr = t >> 2, kc = t & 3;
#pragma unroll
        for (int i = 0; i < 8; i++)
            cp_async16(&Kb0[kr*KPAD + (kc + 4*i)*4], Kg + kr*HD + (kc + 4*i)*4);
#pragma unroll
        for (int i = 0; i < 4; i++)
            cp_async16(&Vb0[kr*VPAD + (kc + 4*i)*4], Vg + kr*Cc + (kc + 4*i)*4);
        cp_commit();
    }

    {
        const float* Qg = g_lhs + (size_t)(b*Nn + q0)*HD;
        for (int idx = t; idx < QT*(HD/4); idx += 128) {
            int r = idx >> 5, c4 = idx & 31;
            float4 v = ((const float4*)(Qg + r*HD))[c4];
            *(float4*)(&Qstage[r*KPAD + c4*4]) = v;
        }
    }
    __syncthreads();

    unsigned qf[16][4];
#pragma unroll
    for (int kk = 0; kk < 16; kk++) {
        qf[kk][0] = __float_as_uint(Qstage[(16*w + g    )*KPAD + 8*kk + q    ]);
        qf[kk][1] = __float_as_uint(Qstage[(16*w + g + 8)*KPAD + 8*kk + q    ]);
        qf[kk][2] = __float_as_uint(Qstage[(16*w + g    )*KPAD + 8*kk + q + 4]);
        qf[kk][3] = __float_as_uint(Qstage[(16*w + g + 8)*KPAD + 8*kk + q + 4]);
    }
    __syncthreads();

    float oacc[8][4];
#pragma unroll
    for (int c = 0; c < 8; c++)
#pragma unroll
        for (int j = 0; j < 4; j++) oacc[c][j] = 0.f;
    float m0 = -1e30f, m1 = -1e30f, l0 = 0.f, l1 = 0.f;

    float* Pw = Ps + 16*w*PPAD;

    const int NT = Nn / KT;
    for (int it = 0; it < NT; it++) {
        float* KsB = (it & 1) ? Kb1 : Kb0;
        float* VsB = (it & 1) ? Vb1 : Vb0;

        cp_wait_all();
        __syncthreads();

        if (it + 1 < NT) {
            float* KsN = (it & 1) ? Kb0 : Kb1;
            float* VsN = (it & 1) ? Vb0 : Vb1;
            const int k1 = (it + 1) * KT;
            const int kr = t >> 2, kc = t & 3;
#pragma unroll
            for (int i = 0; i < 8; i++)
                cp_async16(&KsN[kr*KPAD + (kc + 4*i)*4], Kg + (k1 + kr)*HD + (kc + 4*i)*4);
#pragma unroll
            for (int i = 0; i < 4; i++)
                cp_async16(&VsN[kr*VPAD + (kc + 4*i)*4], Vg + (k1 + kr)*Cc + (kc + 4*i)*4);
            cp_commit();
        }

        float sacc[4][4];
#pragma unroll
        for (int c = 0; c < 4; c++)
#pragma unroll
            for (int j = 0; j < 4; j++) sacc[c][j] = 0.f;

#pragma unroll
        for (int kk = 0; kk < 16; kk++) {
#pragma unroll
            for (int cc = 0; cc < 4; cc++) {
                unsigned b0 = __float_as_uint(KsB[(8*cc + g)*KPAD + 8*kk + q    ]);
                unsigned b1 = __float_as_uint(KsB[(8*cc + g)*KPAD + 8*kk + q + 4]);
                mma8(sacc[cc], qf[kk], b0, b1);
            }
        }

#pragma unroll
        for (int c = 0; c < 4; c++)
#pragma unroll
            for (int j = 0; j < 4; j++) {
                float v = sacc[c][j];
                sacc[c][j] = (v > 0.f) ? v : 0.01f*v;
            }

        float mx0 = -1e30f, mx1 = -1e30f;
#pragma unroll
        for (int c = 0; c < 4; c++) {
            mx0 = fmaxf(mx0, fmaxf(sacc[c][0], sacc[c][1]));
            mx1 = fmaxf(mx1, fmaxf(sacc[c][2], sacc[c][3]));
        }
        mx0 = fmaxf(mx0, __shfl_xor_sync(0xffffffffu, mx0, 1));
        mx0 = fmaxf(mx0, __shfl_xor_sync(0xffffffffu, mx0, 2));
        mx1 = fmaxf(mx1, __shfl_xor_sync(0xffffffffu, mx1, 1));
        mx1 = fmaxf(mx1, __shfl_xor_sync(0xffffffffu, mx1, 2));

        float mn0 = fmaxf(m0, mx0), mn1 = fmaxf(m1, mx1);
        float al0 = __expf(m0 - mn0), al1 = __expf(m1 - mn1);
        m0 = mn0; m1 = mn1;

        float rs0 = 0.f, rs1 = 0.f;
#pragma unroll
        for (int c = 0; c < 4; c++) {
            sacc[c][0] = __expf(sacc[c][0] - m0);
            sacc[c][1] = __expf(sacc[c][1] - m0);
            sacc[c][2] = __expf(sacc[c][2] - m1);
            sacc[c][3] = __expf(sacc[c][3] - m1);
            rs0 += sacc[c][0] + sacc[c][1];
            rs1 += sacc[c][2] + sacc[c][3];
        }
        rs0 += __shfl_xor_sync(0xffffffffu, rs0, 1);
        rs0 += __shfl_xor_sync(0xffffffffu, rs0, 2);
        rs1 += __shfl_xor_sync(0xffffffffu, rs1, 1);
        rs1 += __shfl_xor_sync(0xffffffffu, rs1, 2);
        l0 = l0*al0 + rs0;
        l1 = l1*al1 + rs1;

#pragma unroll
        for (int c = 0; c < 8; c++) {
            oacc[c][0] *= al0; oacc[c][1] *= al0;
            oacc[c][2] *= al1; oacc[c][3] *= al1;
        }

#pragma unroll
        for (int c = 0; c < 4; c++) {
            *(float2*)(&Pw[(g    )*PPAD + 8*c + 2*q]) = make_float2(to_tf32(sacc[c][0]), to_tf32(sacc[c][1]));
            *(float2*)(&Pw[(g + 8)*PPAD + 8*c + 2*q]) = make_float2(to_tf32(sacc[c][2]), to_tf32(sacc[c][3]));
        }
        __syncwarp();

#pragma unroll
        for (int kk = 0; kk < 4; kk++) {
            unsigned pa[4];
            pa[0] = __float_as_uint(Pw[(g    )*PPAD + 8*kk + q    ]);
            pa[1] = __float_as_uint(Pw[(g + 8)*PPAD + 8*kk + q    ]);
            pa[2] = __float_as_uint(Pw[(g    )*PPAD + 8*kk + q + 4]);
            pa[3] = __float_as_uint(Pw[(g + 8)*PPAD + 8*kk + q + 4]);
#pragma unroll
            for (int cc = 0; cc < 8; cc++) {
                unsigned b0 = __float_as_uint(VsB[(8*kk + q    )*VPAD + 8*cc + g]);
                unsigned b1 = __float_as_uint(VsB[(8*kk + q + 4)*VPAD + 8*cc + g]);
                mma8(oacc[cc], pa, b0, b1);
            }
        }
    }

    // ============== GRU epilogue (per-warp, 16 rows) ==============
    __syncthreads();   // all warps done with K/V/P buffers before overlay

    float* Wb  = sm + w*WBLK;       // per-warp private block
    float* RHs = Wb;                // 16 rows x PADH  [0,2112)
    float* Zs  = Wb + 16*PADH;      // 16 rows x PADH  [2112,4224)
    float* Hns = Wb;                // overlays RHs after hh

    const size_t R0g = (size_t)(b*Nn + q0 + 16*w);   // warp's global row base

    // normalized A -> per-warp smem (stride PADA), tf32
    {
        float inv0 = 1.f / l0, inv1 = 1.f / l1;
#pragma unroll
        for (int cc = 0; cc < 8; cc++) {
            *(float2*)(&Wb[(g    )*PADA + 8*cc + 2*q]) =
                make_float2(to_tf32(oacc[cc][0]*inv0), to_tf32(oacc[cc][1]*inv0));
            *(float2*)(&Wb[(g + 8)*PADA + 8*cc + 2*q]) =
                make_float2(to_tf32(oacc[cc][2]*inv1), to_tf32(oacc[cc][3]*inv1));
        }
    }
    __syncwarp();

    unsigned af[8][4];
#pragma unroll
    for (int kk = 0; kk < 8; kk++) {
        af[kk][0] = __float_as_uint(Wb[(g    )*PADA + 8*kk + q    ]);
        af[kk][1] = __float_as_uint(Wb[(g + 8)*PADA + 8*kk + q    ]);
        af[kk][2] = __float_as_uint(Wb[(g    )*PADA + 8*kk + q + 4]);
        af[kk][3] = __float_as_uint(Wb[(g + 8)*PADA + 8*kk + q + 4]);
    }
    __syncwarp();   // all lanes fragged before RHs overwrites the As region

    // ---- phase r: rh = tf32(sigm(A@Wxr + b) * Hp) -> RHs
    {
        float acc[16][4];
#pragma unroll
        for (int c = 0; c < 16; c++) { acc[c][0]=0.f; acc[c][1]=0.f; acc[c][2]=0.f; acc[c][3]=0.f; }
#pragma unroll
        for (int kk = 0; kk < 8; kk++) {
#pragma unroll
            for (int cc = 0; cc < 16; cc++) {
                unsigned b0 = ldw(WT_xr + (8*kk + q    )*HD + 8*cc + g);
                unsigned b1 = ldw(WT_xr + (8*kk + q + 4)*HD + 8*cc + g);
                mma8(acc[cc], af[kk], b0, b1);
            }
        }
#pragma unroll
        for (int cc = 0; cc < 16; cc++) {
            int col = 8*cc + 2*q;
            float2 br = __ldg((const float2*)(b_xr + col));
            float2 h0 = __ldg((const float2*)(Hp + (R0g + g    )*HD + col));
            float2 h1 = __ldg((const float2*)(Hp + (R0g + g + 8)*HD + col));
            *(float2*)(&RHs[(g    )*PADH + col]) =
                make_float2(to_tf32(sigm(acc[cc][0] + br.x) * h0.x),
                            to_tf32(sigm(acc[cc][1] + br.y) * h0.y));
            *(float2*)(&RHs[(g + 8)*PADH + col]) =
                make_float2(to_tf32(sigm(acc[cc][2] + br.x) * h1.x),
                            to_tf32(sigm(acc[cc][3] + br.y) * h1.y));
        }
    }

    // ---- phase z: Zs = sigm(A@Wxz + b)
    {
        float acc[16][4];
#pragma unroll
        for (int c = 0; c < 16; c++) { acc[c][0]=0.f; acc[c][1]=0.f; acc[c][2]=0.f; acc[c][3]=0.f; }
#pragma unroll
        for (int kk = 0; kk < 8; kk++) {
#pragma unroll
            for (int cc = 0; cc < 16; cc++) {
                unsigned b0 = ldw(WT_xz + (8*kk + q    )*HD + 8*cc + g);
                unsigned b1 = ldw(WT_xz + (8*kk + q + 4)*HD + 8*cc + g);
                mma8(acc[cc], af[kk], b0, b1);
            }
        }
#pragma unroll
        for (int cc = 0; cc < 16; cc++) {
            int col = 8*cc + 2*q;
            float2 bz = __ldg((const float2*)(b_xz + col));
            *(float2*)(&Zs[(g    )*PADH + col]) =
                make_float2(sigm(acc[cc][0] + bz.x), sigm(acc[cc][1] + bz.y));
            *(float2*)(&Zs[(g + 8)*PADH + col]) =
                make_float2(sigm(acc[cc][2] + bz.x), sigm(acc[cc][3] + bz.y));
        }
    }

    // ---- phase xh: xacc = X@Wxh
    float xacc[16][4];
#pragma unroll
    for (int c = 0; c < 16; c++) { xacc[c][0]=0.f; xacc[c][1]=0.f; xacc[c][2]=0.f; xacc[c][3]=0.f; }
#pragma unroll
    for (int kk = 0; kk < 8; kk++) {
        unsigned a4[4];
        a4[0] = __float_as_uint(__ldg(g_Xc + (R0g + g    )*Cc + 8*kk + q    ));
        a4[1] = __float_as_uint(__ldg(g_Xc + (R0g + g + 8)*Cc + 8*kk + q    ));
        a4[2] = __float_as_uint(__ldg(g_Xc + (R0g + g    )*Cc + 8*kk + q + 4));
        a4[3] = __float_as_uint(__ldg(g_Xc + (R0g + g + 8)*Cc + 8*kk + q + 4));
#pragma unroll
        for (int cc = 0; cc < 16; cc++) {
            unsigned b0 = ldw(WT_xh + (8*kk + q    )*HD + 8*cc + g);
            unsigned b1 = ldw(WT_xh + (8*kk + q + 4)*HD + 8*cc + g);
            mma8(xacc[cc], a4, b0, b1);
        }
    }

    // ---- phase hh: xacc += rh @ Whh
    __syncwarp();
#pragma unroll
    for (int kk = 0; kk < 16; kk++) {
        unsigned a4[4];
        a4[0] = __float_as_uint(RHs[(g    )*PADH + 8*kk + q    ]);
        a4[1] = __float_as_uint(RHs[(g + 8)*PADH + 8*kk + q    ]);
        a4[2] = __float_as_uint(RHs[(g    )*PADH + 8*kk + q + 4]);
        a4[3] = __float_as_uint(RHs[(g + 8)*PADH + 8*kk + q + 4]);
#pragma unroll
        for (int cc = 0; cc < 16; cc++) {
            unsigned b0 = ldw(WT_hh + (8*kk + q    )*HD + 8*cc + g);
            unsigned b1 = ldw(WT_hh + (8*kk + q + 4)*HD + 8*cc + g);
            mma8(xacc[cc], a4, b0, b1);
        }
    }
    __syncwarp();   // RHs fully read before Hns overlays

    // ---- phase Hn
#pragma unroll
    for (int cc = 0; cc < 16; cc++) {
        int col = 8*cc + 2*q;
        float2 bh = __ldg((const float2*)(b_xh + col));
        float2 bg = __ldg((const float2*)(b_hh + col));
        float2 h0 = __ldg((const float2*)(Hp + (R0g + g    )*HD + col));
        float2 h1 = __ldg((const float2*)(Hp + (R0g + g + 8)*HD + col));
        float2 z0 = *(const float2*)(&Zs[(g    )*PADH + col]);
        float2 z1 = *(const float2*)(&Zs[(g + 8)*PADH + col]);
        float c00 = tanhf(xacc[cc][0] + bh.x + bg.x);
        float c01 = tanhf(xacc[cc][1] + bh.y + bg.y);
        float c10 = tanhf(xacc[cc][2] + bh.x + bg.x);
        float c11 = tanhf(xacc[cc][3] + bh.y + bg.y);
        float H00 = z0.x*h0.x + (1.f - z0.x)*c00;
        float H01 = z0.y*h0.y + (1.f - z0.y)*c01;
        float H10 = z1.x*h1.x + (1.f - z1.x)*c10;
        float H11 = z1.y*h1.y + (1.f - z1.y)*c11;
        *(float2*)(&H_out[(R0g + g    )*HD + col]) = make_float2(H00, H01);
        *(float2*)(&H_out[(R0g + g + 8)*HD + col]) = make_float2(H10, H11);
        *(float2*)(&Hns[(g    )*PADH + col]) = make_float2(to_tf32(H00), to_tf32(H01));
        *(float2*)(&Hns[(g + 8)*PADH + col]) = make_float2(to_tf32(H10), to_tf32(H11));
    }
    __syncwarp();

    // ---- phase y: y = Hn @ WT_y + b_y
    {
        float yac[8][4];
#pragma unroll
        for (int c = 0; c < 8; c++) { yac[c][0]=0.f; yac[c][1]=0.f; yac[c][2]=0.f; yac[c][3]=0.f; }
#pragma unroll
        for (int kk = 0; kk < 16; kk++) {
            unsigned a4[4];
            a4[0] = __float_as_uint(Hns[(g    )*PADH + 8*kk + q    ]);
            a4[1] = __float_as_uint(Hns[(g + 8)*PADH + 8*kk + q    ]);
            a4[2] = __float_as_uint(Hns[(g    )*PADH + 8*kk + q + 4]);
            a4[3] = __float_as_uint(Hns[(g + 8)*PADH + 8*kk + q + 4]);
#pragma unroll
            for (int cc = 0; cc < 8; cc++) {
                unsigned b0 = ldw(WT_y + (8*kk + q    )*Cc + 8*cc + g);
                unsigned b1 = ldw(WT_y + (8*kk + q + 4)*Cc + 8*cc + g);
                mma8(yac[cc], a4, b0, b1);
            }
        }
#pragma unroll
        for (int cc = 0; cc < 8; cc++) {
            int col = 8*cc + 2*q;
            float2 by = __ldg((const float2*)(b_y + col));
            *(float2*)(&y_out[(R0g + g    )*Cc + col]) =
                make_float2(yac[cc][0] + by.x, yac[cc][1] + by.y);
            *(float2*)(&y_out[(R0g + g + 8)*Cc + col]) =
                make_float2(yac[cc][2] + by.x, yac[cc][3] + by.y);
        }
    }
}

// ---------------------------------------------------------------------------
extern "C" void kernel_launch(void* const* d_in, const int* in_sizes, int n_in,
                              void* d_out, int out_size) {
    const float* Hp    = (const float*)d_in[0];
    const float* X     = (const float*)d_in[1];
    const float* W_xr  = (const float*)d_in[2];
    const float* b_xr  = (const float*)d_in[3];
    const float* W_xz  = (const float*)d_in[4];
    const float* b_xz  = (const float*)d_in[5];
    const float* W_xh  = (const float*)d_in[6];
    const float* b_xh  = (const float*)d_in[7];
    const float* W_hh  = (const float*)d_in[8];
    const float* b_hh  = (const float*)d_in[9];
    const float* W_ha1 = (const float*)d_in[10];
    const float* W_ha2 = (const float*)d_in[11];
    const float* b_ha2 = (const float*)d_in[12];
    const float* W_y   = (const float*)d_in[13];
    const float* b_y   = (const float*)d_in[14];

    float* out = (float*)d_out;
    float* y_out = out;                        // [B,N,C]
    float* H_out = out + (size_t)Bb*Nn*Cc;     // [B,N,Hd]

    transpose_all<<<(73728 + 255)/256, 256>>>(W_xr, W_xz, W_xh, W_hh, W_ha1, W_ha2, W_y);

    size_t smem_prep = (size_t)(64*PADA + 64*PADH + 2*64*PADW) * sizeof(float);   // 120832
    cudaFuncSetAttribute(prep_mma, cudaFuncAttributeMaxDynamicSharedMemorySize, (int)smem_prep);
    prep_mma<<<Bb*Nn/64, 128, smem_prep>>>(X, Hp, b_ha2);

    size_t smem_attn = (size_t)(4*WBLK) * sizeof(float);                           // 67584
    cudaFuncSetAttribute(attn_gru_kernel, cudaFuncAttributeMaxDynamicSharedMemorySize, (int)smem_attn);
    attn_gru_kernel<<<dim3(Nn/QT, Bb), 128, smem_attn>>>(Hp, b_xr, b_xz, b_xh, b_hh, b_y,
                                                         y_out, H_out);
}

// round 16
// speedup vs baseline: 26.1480x; 1.0479x over previous
#include <cuda_runtime.h>

#define Bb 8
#define Nn 2048
#define Cc 64
#define HD 128

#define QT 64      // attn queries per block (4 warps x 16 rows)
#define KT 32      // attn keys per tile
#define KPAD 132   // (4g+q) banks, conflict-free frag loads
#define VPAD 72
#define PPAD 36
#define PADA 68    // 64-col activation tiles
#define PADH 132   // 128-col activation tiles
#define PADW 136   // weight chunks: B-frag bank (8q+8cc+g)%32 all-distinct
#define GWC  (64*PADW)   // 8704 floats: one 64-row weight chunk
#define GSCR (16*PADH)   // 2112 floats: per-warp scratch (16 rows x 128)

// scratch (allocation-free rule: __device__ globals)
__device__ float g_lhs[Bb*Nn*HD];   // tf32 Q
__device__ float g_rhs[Bb*Nn*HD];   // tf32 K
__device__ float g_Xc[Bb*Nn*Cc];    // tf32 X

// transposed weights [in][out]
__device__ float WT_xr[Cc*HD];
__device__ float WT_xz[Cc*HD];
__device__ float WT_xh[Cc*HD];
__device__ float WT_hh[HD*HD];
__device__ float WT_ha1[Cc*HD];
__device__ float WT_ha2[HD*HD];
__device__ float WT_y[HD*Cc];

__device__ __forceinline__ void cp_async16(void* smem_dst, const void* gmem_src) {
    unsigned s = (unsigned)__cvta_generic_to_shared(smem_dst);
    asm volatile("cp.async.ca.shared.global [%0], [%1], 16;\n" :: "r"(s), "l"(gmem_src));
}
__device__ __forceinline__ void cp_commit() { asm volatile("cp.async.commit_group;\n"); }
__device__ __forceinline__ void cp_wait_all() { asm volatile("cp.async.wait_group 0;\n" ::: "memory"); }
__device__ __forceinline__ void cp_wait1()   { asm volatile("cp.async.wait_group 1;\n" ::: "memory"); }

__device__ __forceinline__ float to_tf32(float x) {
    unsigned u;
    asm("cvt.rna.tf32.f32 %0, %1;" : "=r"(u) : "f"(x));
    return __uint_as_float(u);
}
__device__ __forceinline__ float sigm(float x) { return 1.f / (1.f + __expf(-x)); }

// D += A(16x8,row) * B(8x8,col)   tf32 inputs, f32 accum
__device__ __forceinline__ void mma8(float* c, const unsigned* a, unsigned b0, unsigned b1) {
    asm volatile(
        "mma.sync.aligned.m16n8k8.row.col.f32.tf32.tf32.f32 "
        "{%0,%1,%2,%3}, {%4,%5,%6,%7}, {%8,%9}, {%0,%1,%2,%3};\n"
        : "+f"(c[0]), "+f"(c[1]), "+f"(c[2]), "+f"(c[3])
        : "r"(a[0]), "r"(a[1]), "r"(a[2]), "r"(a[3]), "r"(b0), "r"(b1));
}
__device__ __forceinline__ unsigned ldw(const float* p) { return __float_as_uint(__ldg(p)); }

// stage 64 rows x 128 cols of a row-major [*][128] weight into dst (stride PADW)
__device__ __forceinline__ void stage_w128(float* dst, const float* src, int t) {
#pragma unroll
    for (int i = 0; i < 16; i++) {
        int idx = t + 128*i;
        int r = idx >> 5, c4 = idx & 31;
        cp_async16(dst + r*PADW + 4*c4, src + r*HD + 4*c4);
    }
}
// stage 64 rows x 64 cols of a row-major [*][64] weight into dst (stride PADW)
__device__ __forceinline__ void stage_w64(float* dst, const float* src, int t) {
#pragma unroll
    for (int i = 0; i < 8; i++) {
        int idx = t + 128*i;
        int r = idx >> 4, c4 = idx & 15;
        cp_async16(dst + r*PADW + 4*c4, src + r*Cc + 4*c4);
    }
}

// ---------------------------------------------------------------------------
// Kernel 0: all 7 weight transposes in one launch.
// ---------------------------------------------------------------------------
__global__ void transpose_all(const float* __restrict__ W_xr, const float* __restrict__ W_xz,
                              const float* __restrict__ W_xh, const float* __restrict__ W_hh,
                              const float* __restrict__ W_ha1, const float* __restrict__ W_ha2,
                              const float* __restrict__ W_y) {
    int i = blockIdx.x * 256 + threadIdx.x;
    const float* src; float* dst; int R, C, off;
    if      (i < 8192)  { src = W_xr;  dst = WT_xr;  R = HD; C = Cc; off = 0; }
    else if (i < 16384) { src = W_xz;  dst = WT_xz;  R = HD; C = Cc; off = 8192; }
    else if (i < 24576) { src = W_xh;  dst = WT_xh;  R = HD; C = Cc; off = 16384; }
    else if (i < 40960) { src = W_hh;  dst = WT_hh;  R = HD; C = HD; off = 24576; }
    else if (i < 49152) { src = W_ha1; dst = WT_ha1; R = HD; C = Cc; off = 40960; }
    else if (i < 65536) { src = W_ha2; dst = WT_ha2; R = HD; C = HD; off = 49152; }
    else if (i < 73728) { src = W_y;   dst = WT_y;   R = Cc; C = HD; off = 65536; }
    else return;
    int j = i - off;
    int r = j / C, c = j - r*C;
    dst[c*R + r] = src[j];
}

// ---------------------------------------------------------------------------
// Kernel 1: prep via mma with smem-staged weights (unchanged).
// ---------------------------------------------------------------------------
__global__ void __launch_bounds__(128) prep_mma(const float* __restrict__ X,
                                                const float* __restrict__ Hp,
                                                const float* __restrict__ b_ha2) {
    extern __shared__ float sm[];
    float* Xs  = sm;
    float* Hs  = Xs + 64*PADA;
    float* WB0 = Hs + 64*PADH;
    float* WB1 = WB0 + GWC;

    const int t = threadIdx.x;
    const int w = t >> 5, lane = t & 31;
    const int g = lane >> 2, q = lane & 3;
    const int R0 = blockIdx.x * 64 + 16*w;
    const int sr = 16*w;

    stage_w128(WB0, WT_ha1, t); cp_commit();
    stage_w128(WB1, WT_ha2, t); cp_commit();

#pragma unroll
    for (int i = 0; i < 8; i++) {
        int idx = lane + 32*i;
        int r = idx >> 4, c4 = idx & 15;
        float4 v = *(const float4*)(X + (size_t)(R0 + r)*Cc + 4*c4);
        v.x = to_tf32(v.x); v.y = to_tf32(v.y); v.z = to_tf32(v.z); v.w = to_tf32(v.w);
        *(float4*)(&Xs[(sr + r)*PADA + 4*c4]) = v;
        *(float4*)(&g_Xc[(size_t)(R0 + r)*Cc + 4*c4]) = v;
    }
#pragma unroll
    for (int i = 0; i < 16; i++) {
        int idx = lane + 32*i;
        int r = idx >> 5, c4 = idx & 31;
        float4 v = *(const float4*)(Hp + (size_t)(R0 + r)*HD + 4*c4);
        v.x = to_tf32(v.x); v.y = to_tf32(v.y); v.z = to_tf32(v.z); v.w = to_tf32(v.w);
        *(float4*)(&Hs[(sr + r)*PADH + 4*c4]) = v;
    }
    __syncwarp();

    unsigned af[8][4];
#pragma unroll
    for (int kk = 0; kk < 8; kk++) {
        af[kk][0] = __float_as_uint(Xs[(sr + g    )*PADA + 8*kk + q    ]);
        af[kk][1] = __float_as_uint(Xs[(sr + g + 8)*PADA + 8*kk + q    ]);
        af[kk][2] = __float_as_uint(Xs[(sr + g    )*PADA + 8*kk + q + 4]);
        af[kk][3] = __float_as_uint(Xs[(sr + g + 8)*PADA + 8*kk + q + 4]);
    }

    float acc[16][4];

    cp_wait1(); __syncthreads();
#pragma unroll
    for (int c = 0; c < 16; c++) { acc[c][0]=0.f; acc[c][1]=0.f; acc[c][2]=0.f; acc[c][3]=0.f; }
#pragma unroll
    for (int kk = 0; kk < 8; kk++) {
#pragma unroll
        for (int cc = 0; cc < 16; cc++) {
            unsigned b0 = __float_as_uint(WB0[(8*kk + q    )*PADW + 8*cc + g]);
            unsigned b1 = __float_as_uint(WB0[(8*kk + q + 4)*PADW + 8*cc + g]);
            mma8(acc[cc], af[kk], b0, b1);
        }
    }
#pragma unroll
    for (int cc = 0; cc < 16; cc++) {
        int col = 8*cc + 2*q;
        *(float2*)(&g_lhs[(size_t)(R0 + g    )*HD + col]) = make_float2(to_tf32(acc[cc][0]), to_tf32(acc[cc][1]));
        *(float2*)(&g_lhs[(size_t)(R0 + g + 8)*HD + col]) = make_float2(to_tf32(acc[cc][2]), to_tf32(acc[cc][3]));
    }
    __syncthreads();
    stage_w128(WB0, WT_ha2 + 64*HD, t); cp_commit();

    cp_wait1(); __syncthreads();
#pragma unroll
    for (int c = 0; c < 16; c++) { acc[c][0]=0.f; acc[c][1]=0.f; acc[c][2]=0.f; acc[c][3]=0.f; }
#pragma unroll
    for (int kk = 0; kk < 8; kk++) {
        unsigned a4[4];
        a4[0] = __float_as_uint(Hs[(sr + g    )*PADH + 8*kk + q    ]);
        a4[1] = __float_as_uint(Hs[(sr + g + 8)*PADH + 8*kk + q    ]);
        a4[2] = __float_as_uint(Hs[(sr + g    )*PADH + 8*kk + q + 4]);
        a4[3] = __float_as_uint(Hs[(sr + g + 8)*PADH + 8*kk + q + 4]);
#pragma unroll
        for (int cc = 0; cc < 16; cc++) {
            unsigned b0 = __float_as_uint(WB1[(8*kk + q    )*PADW + 8*cc + g]);
            unsigned b1 = __float_as_uint(WB1[(8*kk + q + 4)*PADW + 8*cc + g]);
            mma8(acc[cc], a4, b0, b1);
        }
    }
    cp_wait_all(); __syncthreads();
#pragma unroll
    for (int kk = 0; kk < 8; kk++) {
        unsigned a4[4];
        a4[0] = __float_as_uint(Hs[(sr + g    )*PADH + 64 + 8*kk + q    ]);
        a4[1] = __float_as_uint(Hs[(sr + g + 8)*PADH + 64 + 8*kk + q    ]);
        a4[2] = __float_as_uint(Hs[(sr + g    )*PADH + 64 + 8*kk + q + 4]);
        a4[3] = __float_as_uint(Hs[(sr + g + 8)*PADH + 64 + 8*kk + q + 4]);
#pragma unroll
        for (int cc = 0; cc < 16; cc++) {
            unsigned b0 = __float_as_uint(WB0[(8*kk + q    )*PADW + 8*cc + g]);
            unsigned b1 = __float_as_uint(WB0[(8*kk + q + 4)*PADW + 8*cc + g]);
            mma8(acc[cc], a4, b0, b1);
        }
    }
#pragma unroll
    for (int cc = 0; cc < 16; cc++) {
        int col = 8*cc + 2*q;
        float2 bv = __ldg((const float2*)(b_ha2 + col));
        *(float2*)(&g_rhs[(size_t)(R0 + g    )*HD + col]) =
            make_float2(to_tf32(acc[cc][0] + bv.x), to_tf32(acc[cc][1] + bv.y));
        *(float2*)(&g_rhs[(size_t)(R0 + g + 8)*HD + col]) =
            make_float2(to_tf32(acc[cc][2] + bv.x), to_tf32(acc[cc][3] + bv.y));
    }
}

// ---------------------------------------------------------------------------
// Kernel 2: FUSED flash attention + GRU epilogue with smem-staged gru weights.
// 128 threads, 2 CTAs/SM (102.4KB smem). Attention identical to R15.
// GRU epilogue: the dead attention smem is reused as
//   Wgt  [0, GWC)                    one 64-row weight chunk (stride PADW)
//   RHs  [GWC + w*GSCR, +GSCR)       per-warp rh (stride PADH); As/Hns overlay
//   Zs   [GWC + 4*GSCR + w*GSCR)     per-warp z  (stride PADH)
// Phase pattern: compute -> sync -> stage next chunk -> wait -> sync.
// ---------------------------------------------------------------------------
__global__ void __launch_bounds__(128, 2) attn_gru_kernel(
    const float* __restrict__ Hp,
    const float* __restrict__ b_xr, const float* __restrict__ b_xz,
    const float* __restrict__ b_xh, const float* __restrict__ b_hh,
    const float* __restrict__ b_y,
    float* __restrict__ y_out, float* __restrict__ H_out) {
    extern __shared__ float sm[];
    float* Kb0 = sm;
    float* Vb0 = Kb0 + KT*KPAD;
    float* Kb1 = Vb0 + KT*VPAD;
    float* Vb1 = Kb1 + KT*KPAD;
    float* Ps  = Vb1 + KT*VPAD;
    float* Qstage = Kb1;

    const int b  = blockIdx.y;
    const int q0 = blockIdx.x * QT;
    const int t  = threadIdx.x;
    const int w  = t >> 5;
    const int lane = t & 31;
    const int g = lane >> 2;
    const int q = lane & 3;

    const float* Kg = g_rhs + (size_t)b*Nn*HD;
    const float* Vg = g_Xc  + (size_t)b*Nn*Cc;

    {
        const int kr = t >> 2, kc = t & 3;
#pragma unroll
        for (int i = 0; i < 8; i++)
            cp_async16(&Kb0[kr*KPAD + (kc + 4*i)*4], Kg + kr*HD + (kc + 4*i)*4);
#pragma unroll
        for (int i = 0; i < 4; i++)
            cp_async16(&Vb0[kr*VPAD + (kc + 4*i)*4], Vg + kr*Cc + (kc + 4*i)*4);
        cp_commit();
    }

    {
        const float* Qg = g_lhs + (size_t)(b*Nn + q0)*HD;
        for (int idx = t; idx < QT*(HD/4); idx += 128) {
            int r = idx >> 5, c4 = idx & 31;
            float4 v = ((const float4*)(Qg + r*HD))[c4];
            *(float4*)(&Qstage[r*KPAD + c4*4]) = v;
        }
    }
    __syncthreads();

    unsigned qf[16][4];
#pragma unroll
    for (int kk = 0; kk < 16; kk++) {
        qf[kk][0] = __float_as_uint(Qstage[(16*w + g    )*KPAD + 8*kk + q    ]);
        qf[kk][1] = __float_as_uint(Qstage[(16*w + g + 8)*KPAD + 8*kk + q    ]);
        qf[kk][2] = __float_as_uint(Qstage[(16*w + g    )*KPAD + 8*kk + q + 4]);
        qf[kk][3] = __float_as_uint(Qstage[(16*w + g + 8)*KPAD + 8*kk + q + 4]);
    }
    __syncthreads();

    float oacc[8][4];
#pragma unroll
    for (int c = 0; c < 8; c++)
#pragma unroll
        for (int j = 0; j < 4; j++) oacc[c][j] = 0.f;
    float m0 = -1e30f, m1 = -1e30f, l0 = 0.f, l1 = 0.f;

    float* Pw = Ps + 16*w*PPAD;

    const int NT = Nn / KT;
    for (int it = 0; it < NT; it++) {
        float* KsB = (it & 1) ? Kb1 : Kb0;
        float* VsB = (it & 1) ? Vb1 : Vb0;

        cp_wait_all();
        __syncthreads();

        if (it + 1 < NT) {
            float* KsN = (it & 1) ? Kb0 : Kb1;
            float* VsN = (it & 1) ? Vb0 : Vb1;
            const int k1 = (it + 1) * KT;
            const int kr = t >> 2, kc = t & 3;
#pragma unroll
            for (int i = 0; i < 8; i++)
                cp_async16(&KsN[kr*KPAD + (kc + 4*i)*4], Kg + (k1 + kr)*HD + (kc + 4*i)*4);
#pragma unroll
            for (int i = 0; i < 4; i++)
                cp_async16(&VsN[kr*VPAD + (kc + 4*i)*4], Vg + (k1 + kr)*Cc + (kc + 4*i)*4);
            cp_commit();
        }

        float sacc[4][4];
#pragma unroll
        for (int c = 0; c < 4; c++)
#pragma unroll
            for (int j = 0; j < 4; j++) sacc[c][j] = 0.f;

#pragma unroll
        for (int kk = 0; kk < 16; kk++) {
#pragma unroll
            for (int cc = 0; cc < 4; cc++) {
                unsigned b0 = __float_as_uint(KsB[(8*cc + g)*KPAD + 8*kk + q    ]);
                unsigned b1 = __float_as_uint(KsB[(8*cc + g)*KPAD + 8*kk + q + 4]);
                mma8(sacc[cc], qf[kk], b0, b1);
            }
        }

#pragma unroll
        for (int c = 0; c < 4; c++)
#pragma unroll
            for (int j = 0; j < 4; j++) {
                float v = sacc[c][j];
                sacc[c][j] = (v > 0.f) ? v : 0.01f*v;
            }

        float mx0 = -1e30f, mx1 = -1e30f;
#pragma unroll
        for (int c = 0; c < 4; c++) {
            mx0 = fmaxf(mx0, fmaxf(sacc[c][0], sacc[c][1]));
            mx1 = fmaxf(mx1, fmaxf(sacc[c][2], sacc[c][3]));
        }
        mx0 = fmaxf(mx0, __shfl_xor_sync(0xffffffffu, mx0, 1));
        mx0 = fmaxf(mx0, __shfl_xor_sync(0xffffffffu, mx0, 2));
        mx1 = fmaxf(mx1, __shfl_xor_sync(0xffffffffu, mx1, 1));
        mx1 = fmaxf(mx1, __shfl_xor_sync(0xffffffffu, mx1, 2));

        float mn0 = fmaxf(m0, mx0), mn1 = fmaxf(m1, mx1);
        float al0 = __expf(m0 - mn0), al1 = __expf(m1 - mn1);
        m0 = mn0; m1 = mn1;

        float rs0 = 0.f, rs1 = 0.f;
#pragma unroll
        for (int c = 0; c < 4; c++) {
            sacc[c][0] = __expf(sacc[c][0] - m0);
            sacc[c][1] = __expf(sacc[c][1] - m0);
            sacc[c][2] = __expf(sacc[c][2] - m1);
            sacc[c][3] = __expf(sacc[c][3] - m1);
            rs0 += sacc[c][0] + sacc[c][1];
            rs1 += sacc[c][2] + sacc[c][3];
        }
        rs0 += __shfl_xor_sync(0xffffffffu, rs0, 1);
        rs0 += __shfl_xor_sync(0xffffffffu, rs0, 2);
        rs1 += __shfl_xor_sync(0xffffffffu, rs1, 1);
        rs1 += __shfl_xor_sync(0xffffffffu, rs1, 2);
        l0 = l0*al0 + rs0;
        l1 = l1*al1 + rs1;

#pragma unroll
        for (int c = 0; c < 8; c++) {
            oacc[c][0] *= al0; oacc[c][1] *= al0;
            oacc[c][2] *= al1; oacc[c][3] *= al1;
        }

#pragma unroll
        for (int c = 0; c < 4; c++) {
            *(float2*)(&Pw[(g    )*PPAD + 8*c + 2*q]) = make_float2(to_tf32(sacc[c][0]), to_tf32(sacc[c][1]));
            *(float2*)(&Pw[(g + 8)*PPAD + 8*c + 2*q]) = make_float2(to_tf32(sacc[c][2]), to_tf32(sacc[c][3]));
        }
        __syncwarp();

#pragma unroll
        for (int kk = 0; kk < 4; kk++) {
            unsigned pa[4];
            pa[0] = __float_as_uint(Pw[(g    )*PPAD + 8*kk + q    ]);
            pa[1] = __float_as_uint(Pw[(g + 8)*PPAD + 8*kk + q    ]);
            pa[2] = __float_as_uint(Pw[(g    )*PPAD + 8*kk + q + 4]);
            pa[3] = __float_as_uint(Pw[(g + 8)*PPAD + 8*kk + q + 4]);
#pragma unroll
            for (int cc = 0; cc < 8; cc++) {
                unsigned b0 = __float_as_uint(VsB[(8*kk + q    )*VPAD + 8*cc + g]);
                unsigned b1 = __float_as_uint(VsB[(8*kk + q + 4)*VPAD + 8*cc + g]);
                mma8(oacc[cc], pa, b0, b1);
            }
        }
    }

    // ============== GRU epilogue with smem-staged weights ==============
    __syncthreads();   // all warps done with attention smem

    float* Wgt = sm;                             // weight chunk buffer
    float* RHs = sm + GWC + w*GSCR;              // per-warp rh / As / Hns
    float* Zs  = sm + GWC + 4*GSCR + w*GSCR;     // per-warp z
    float* Hns = RHs;

    const size_t R0g = (size_t)(b*Nn + q0 + 16*w);

    // stage chunk 0 (WT_xr) while we build A fragments
    stage_w128(Wgt, WT_xr, t); cp_commit();

    // normalized A -> per-warp smem (stride PADA inside RHs region), tf32
    {
        float inv0 = 1.f / l0, inv1 = 1.f / l1;
#pragma unroll
        for (int cc = 0; cc < 8; cc++) {
            *(float2*)(&RHs[(g    )*PADA + 8*cc + 2*q]) =
                make_float2(to_tf32(oacc[cc][0]*inv0), to_tf32(oacc[cc][1]*inv0));
            *(float2*)(&RHs[(g + 8)*PADA + 8*cc + 2*q]) =
                make_float2(to_tf32(oacc[cc][2]*inv1), to_tf32(oacc[cc][3]*inv1));
        }
    }
    __syncwarp();

    unsigned af[8][4];
#pragma unroll
    for (int kk = 0; kk < 8; kk++) {
        af[kk][0] = __float_as_uint(RHs[(g    )*PADA + 8*kk + q    ]);
        af[kk][1] = __float_as_uint(RHs[(g + 8)*PADA + 8*kk + q    ]);
        af[kk][2] = __float_as_uint(RHs[(g    )*PADA + 8*kk + q + 4]);
        af[kk][3] = __float_as_uint(RHs[(g + 8)*PADA + 8*kk + q + 4]);
    }
    __syncwarp();   // all lanes fragged before r-phase overwrites the As region

    cp_wait_all(); __syncthreads();   // chunk xr ready

    // ---- phase r: rh = tf32(sigm(A@Wxr + b) * Hp) -> RHs
    {
        float acc[16][4];
#pragma unroll
        for (int c = 0; c < 16; c++) { acc[c][0]=0.f; acc[c][1]=0.f; acc[c][2]=0.f; acc[c][3]=0.f; }
#pragma unroll
        for (int kk = 0; kk < 8; kk++) {
#pragma unroll
            for (int cc = 0; cc < 16; cc++) {
                unsigned b0 = __float_as_uint(Wgt[(8*kk + q    )*PADW + 8*cc + g]);
                unsigned b1 = __float_as_uint(Wgt[(8*kk + q + 4)*PADW + 8*cc + g]);
                mma8(acc[cc], af[kk], b0, b1);
            }
        }
#pragma unroll
        for (int cc = 0; cc < 16; cc++) {
            int col = 8*cc + 2*q;
            float2 br = __ldg((const float2*)(b_xr + col));
            float2 h0 = __ldg((const float2*)(Hp + (R0g + g    )*HD + col));
            float2 h1 = __ldg((const float2*)(Hp + (R0g + g + 8)*HD + col));
            *(float2*)(&RHs[(g    )*PADH + col]) =
                make_float2(to_tf32(sigm(acc[cc][0] + br.x) * h0.x),
                            to_tf32(sigm(acc[cc][1] + br.y) * h0.y));
            *(float2*)(&RHs[(g + 8)*PADH + col]) =
                make_float2(to_tf32(sigm(acc[cc][2] + br.x) * h1.x),
                            to_tf32(sigm(acc[cc][3] + br.y) * h1.y));
        }
    }
    __syncthreads();
    stage_w128(Wgt, WT_xz, t); cp_commit(); cp_wait_all(); __syncthreads();

    // ---- phase z: Zs = sigm(A@Wxz + b)
    {
        float acc[16][4];
#pragma unroll
        for (int c = 0; c < 16; c++) { acc[c][0]=0.f; acc[c][1]=0.f; acc[c][2]=0.f; acc[c][3]=0.f; }
#pragma unroll
        for (int kk = 0; kk < 8; kk++) {
#pragma unroll
            for (int cc = 0; cc < 16; cc++) {
                unsigned b0 = __float_as_uint(Wgt[(8*kk + q    )*PADW + 8*cc + g]);
                unsigned b1 = __float_as_uint(Wgt[(8*kk + q + 4)*PADW + 8*cc + g]);
                mma8(acc[cc], af[kk], b0, b1);
            }
        }
#pragma unroll
        for (int cc = 0; cc < 16; cc++) {
            int col = 8*cc + 2*q;
            float2 bz = __ldg((const float2*)(b_xz + col));
            *(float2*)(&Zs[(g    )*PADH + col]) =
                make_float2(sigm(acc[cc][0] + bz.x), sigm(acc[cc][1] + bz.y));
            *(float2*)(&Zs[(g + 8)*PADH + col]) =
                make_float2(sigm(acc[cc][2] + bz.x), sigm(acc[cc][3] + bz.y));
        }
    }
    __syncthreads();
    stage_w128(Wgt, WT_xh, t); cp_commit(); cp_wait_all(); __syncthreads();

    // ---- phase xh: xacc = X@Wxh (X frags direct from g_Xc, already tf32)
    float xacc[16][4];
#pragma unroll
    for (int c = 0; c < 16; c++) { xacc[c][0]=0.f; xacc[c][1]=0.f; xacc[c][2]=0.f; xacc[c][3]=0.f; }
#pragma unroll
    for (int kk = 0; kk < 8; kk++) {
        unsigned a4[4];
        a4[0] = __float_as_uint(__ldg(g_Xc + (R0g + g    )*Cc + 8*kk + q    ));
        a4[1] = __float_as_uint(__ldg(g_Xc + (R0g + g + 8)*Cc + 8*kk + q    ));
        a4[2] = __float_as_uint(__ldg(g_Xc + (R0g + g    )*Cc + 8*kk + q + 4));
        a4[3] = __float_as_uint(__ldg(g_Xc + (R0g + g + 8)*Cc + 8*kk + q + 4));
#pragma unroll
        for (int cc = 0; cc < 16; cc++) {
            unsigned b0 = __float_as_uint(Wgt[(8*kk + q    )*PADW + 8*cc + g]);
            unsigned b1 = __float_as_uint(Wgt[(8*kk + q + 4)*PADW + 8*cc + g]);
            mma8(xacc[cc], a4, b0, b1);
        }
    }
    __syncthreads();
    stage_w128(Wgt, WT_hh, t); cp_commit(); cp_wait_all(); __syncthreads();

    // ---- phase hh-lo: xacc += rh[:,0:64] @ Whh[0:64,:]
#pragma unroll
    for (int kk = 0; kk < 8; kk++) {
        unsigned a4[4];
        a4[0] = __float_as_uint(RHs[(g    )*PADH + 8*kk + q    ]);
        a4[1] = __float_as_uint(RHs[(g + 8)*PADH + 8*kk + q    ]);
        a4[2] = __float_as_uint(RHs[(g    )*PADH + 8*kk + q + 4]);
        a4[3] = __float_as_uint(RHs[(g + 8)*PADH + 8*kk + q + 4]);
#pragma unroll
        for (int cc = 0; cc < 16; cc++) {
            unsigned b0 = __float_as_uint(Wgt[(8*kk + q    )*PADW + 8*cc + g]);
            unsigned b1 = __float_as_uint(Wgt[(8*kk + q + 4)*PADW + 8*cc + g]);
            mma8(xacc[cc], a4, b0, b1);
        }
    }
    __syncthreads();
    stage_w128(Wgt, WT_hh + 64*HD, t); cp_commit(); cp_wait_all(); __syncthreads();

    // ---- phase hh-hi: xacc += rh[:,64:128] @ Whh[64:128,:]
#pragma unroll
    for (int kk = 0; kk < 8; kk++) {
        unsigned a4[4];
        a4[0] = __float_as_uint(RHs[(g    )*PADH + 64 + 8*kk + q    ]);
        a4[1] = __float_as_uint(RHs[(g + 8)*PADH + 64 + 8*kk + q    ]);
        a4[2] = __float_as_uint(RHs[(g    )*PADH + 64 + 8*kk + q + 4]);
        a4[3] = __float_as_uint(RHs[(g + 8)*PADH + 64 + 8*kk + q + 4]);
#pragma unroll
        for (int cc = 0; cc < 16; cc++) {
            unsigned b0 = __float_as_uint(Wgt[(8*kk + q    )*PADW + 8*cc + g]);
            unsigned b1 = __float_as_uint(Wgt[(8*kk + q + 4)*PADW + 8*cc + g]);
            mma8(xacc[cc], a4, b0, b1);
        }
    }
    __syncwarp();   // own-warp RHs reads done before Hns overlays

    // ---- phase Hn: Hn = z*Hp + (1-z)*tanh(xacc + b_xh + b_hh)
#pragma unroll
    for (int cc = 0; cc < 16; cc++) {
        int col = 8*cc + 2*q;
        float2 bh = __ldg((const float2*)(b_xh + col));
        float2 bg = __ldg((const float2*)(b_hh + col));
        float2 h0 = __ldg((const float2*)(Hp + (R0g + g    )*HD + col));
        float2 h1 = __ldg((const float2*)(Hp + (R0g + g + 8)*HD + col));
        float2 z0 = *(const float2*)(&Zs[(g    )*PADH + col]);
        float2 z1 = *(const float2*)(&Zs[(g + 8)*PADH + col]);
        float c00 = tanhf(xacc[cc][0] + bh.x + bg.x);
        float c01 = tanhf(xacc[cc][1] + bh.y + bg.y);
        float c10 = tanhf(xacc[cc][2] + bh.x + bg.x);
        float c11 = tanhf(xacc[cc][3] + bh.y + bg.y);
        float H00 = z0.x*h0.x + (1.f - z0.x)*c00;
        float H01 = z0.y*h0.y + (1.f - z0.y)*c01;
        float H10 = z1.x*h1.x + (1.f - z1.x)*c10;
        float H11 = z1.y*h1.y + (1.f - z1.y)*c11;
        *(float2*)(&H_out[(R0g + g    )*HD + col]) = make_float2(H00, H01);
        *(float2*)(&H_out[(R0g + g + 8)*HD + col]) = make_float2(H10, H11);
        *(float2*)(&Hns[(g    )*PADH + col]) = make_float2(to_tf32(H00), to_tf32(H01));
        *(float2*)(&Hns[(g + 8)*PADH + col]) = make_float2(to_tf32(H10), to_tf32(H11));
    }
    __syncthreads();
    stage_w64(Wgt, WT_y, t); cp_commit(); cp_wait_all(); __syncthreads();

    // ---- phase y-lo: yac = Hn[:,0:64] @ Wy[0:64,:]
    float yac[8][4];
#pragma unroll
    for (int c = 0; c < 8; c++) { yac[c][0]=0.f; yac[c][1]=0.f; yac[c][2]=0.f; yac[c][3]=0.f; }
#pragma unroll
    for (int kk = 0; kk < 8; kk++) {
        unsigned a4[4];
        a4[0] = __float_as_uint(Hns[(g    )*PADH + 8*kk + q    ]);
        a4[1] = __float_as_uint(Hns[(g + 8)*PADH + 8*kk + q    ]);
        a4[2] = __float_as_uint(Hns[(g    )*PADH + 8*kk + q + 4]);
        a4[3] = __float_as_uint(Hns[(g + 8)*PADH + 8*kk + q + 4]);
#pragma unroll
        for (int cc = 0; cc < 8; cc++) {
            unsigned b0 = __float_as_uint(Wgt[(8*kk + q    )*PADW + 8*cc + g]);
            unsigned b1 = __float_as_uint(Wgt[(8*kk + q + 4)*PADW + 8*cc + g]);
            mma8(yac[cc], a4, b0, b1);
        }
    }
    __syncthreads();
    stage_w64(Wgt, WT_y + 64*Cc, t); cp_commit(); cp_wait_all(); __syncthreads();

    // ---- phase y-hi: yac += Hn[:,64:128] @ Wy[64:128,:]
#pragma unroll
    for (int kk = 0; kk < 8; kk++) {
        unsigned a4[4];
        a4[0] = __float_as_uint(Hns[(g    )*PADH + 64 + 8*kk + q    ]);
        a4[1] = __float_as_uint(Hns[(g + 8)*PADH + 64 + 8*kk + q    ]);
        a4[2] = __float_as_uint(Hns[(g    )*PADH + 64 + 8*kk + q + 4]);
        a4[3] = __float_as_uint(Hns[(g + 8)*PADH + 64 + 8*kk + q + 4]);
#pragma unroll
        for (int cc = 0; cc < 8; cc++) {
            unsigned b0 = __float_as_uint(Wgt[(8*kk + q    )*PADW + 8*cc + g]);
            unsigned b1 = __float_as_uint(Wgt[(8*kk + q + 4)*PADW + 8*cc + g]);
            mma8(yac[cc], a4, b0, b1);
        }
    }
#pragma unroll
    for (int cc = 0; cc < 8; cc++) {
        int col = 8*cc + 2*q;
        float2 by = __ldg((const float2*)(b_y + col));
        *(float2*)(&y_out[(R0g + g    )*Cc + col]) =
            make_float2(yac[cc][0] + by.x, yac[cc][1] + by.y);
        *(float2*)(&y_out[(R0g + g + 8)*Cc + col]) =
            make_float2(yac[cc][2] + by.x, yac[cc][3] + by.y);
    }
}

// ---------------------------------------------------------------------------
extern "C" void kernel_launch(void* const* d_in, const int* in_sizes, int n_in,
                              void* d_out, int out_size) {
    const float* Hp    = (const float*)d_in[0];
    const float* X     = (const float*)d_in[1];
    const float* W_xr  = (const float*)d_in[2];
    const float* b_xr  = (const float*)d_in[3];
    const float* W_xz  = (const float*)d_in[4];
    const float* b_xz  = (const float*)d_in[5];
    const float* W_xh  = (const float*)d_in[6];
    const float* b_xh  = (const float*)d_in[7];
    const float* W_hh  = (const float*)d_in[8];
    const float* b_hh  = (const float*)d_in[9];
    const float* W_ha1 = (const float*)d_in[10];
    const float* W_ha2 = (const float*)d_in[11];
    const float* b_ha2 = (const float*)d_in[12];
    const float* W_y   = (const float*)d_in[13];
    const float* b_y   = (const float*)d_in[14];

    float* out = (float*)d_out;
    float* y_out = out;                        // [B,N,C]
    float* H_out = out + (size_t)Bb*Nn*Cc;     // [B,N,Hd]

    transpose_all<<<(73728 + 255)/256, 256>>>(W_xr, W_xz, W_xh, W_hh, W_ha1, W_ha2, W_y);

    size_t smem_prep = (size_t)(64*PADA + 64*PADH + 2*GWC) * sizeof(float);
    cudaFuncSetAttribute(prep_mma, cudaFuncAttributeMaxDynamicSharedMemorySize, (int)smem_prep);
    prep_mma<<<Bb*Nn/64, 128, smem_prep>>>(X, Hp, b_ha2);

    size_t smem_attn = (size_t)(GWC + 8*GSCR) * sizeof(float);   // 25600 floats = 102400 B
    cudaFuncSetAttribute(attn_gru_kernel, cudaFuncAttributeMaxDynamicSharedMemorySize, (int)smem_attn);
    attn_gru_kernel<<<dim3(Nn/QT, Bb), 128, smem_attn>>>(Hp, b_xr, b_xz, b_xh, b_hh, b_y,
                                                         y_out, H_out);
}

// round 17
// speedup vs baseline: 28.6444x; 1.0955x over previous
#include <cuda_runtime.h>

#define Bb 8
#define Nn 2048
#define Cc 64
#define HD 128

#define QT 64      // attn queries per block (4 warps x 16 rows)
#define KT 32      // attn keys per tile
#define KPAD 132   // Qstage stride: (4g+q) banks conflict-free
#define PPAD 36
#define PADA 68    // 64-col activation tiles
#define PADH 132   // 128-col activation tiles
#define PADW 136   // weight chunks: B-frag bank (8q+8cc+g)%32 all-distinct
#define GWC  (64*PADW)   // 8704 floats: one 64-row weight chunk
#define GSCR (16*PADH)   // 2112 floats: per-warp scratch (16 rows x 128)

#define KPK_T 4096   // packed K floats per 32-key tile
#define VPK_T 2048   // packed V floats per 32-key tile

// scratch (allocation-free rule: __device__ globals)
__device__ float g_lhs[Bb*Nn*HD];     // tf32 Q (row layout)
__device__ float g_Kpk[Bb*Nn*HD];     // K in B-fragment-packed tiles
__device__ float g_Vpk[Bb*Nn*Cc];     // V in B-fragment-packed tiles
__device__ float g_Xc[Bb*Nn*Cc];      // tf32 X (row layout, for gru xh)

// transposed weights [in][out]
__device__ float WT_xr[Cc*HD];
__device__ float WT_xz[Cc*HD];
__device__ float WT_xh[Cc*HD];
__device__ float WT_hh[HD*HD];
__device__ float WT_ha1[Cc*HD];
__device__ float WT_ha2[HD*HD];
__device__ float WT_y[HD*Cc];

__device__ __forceinline__ void cp_async16(void* smem_dst, const void* gmem_src) {
    unsigned s = (unsigned)__cvta_generic_to_shared(smem_dst);
    asm volatile("cp.async.ca.shared.global [%0], [%1], 16;\n" :: "r"(s), "l"(gmem_src));
}
__device__ __forceinline__ void cp_commit() { asm volatile("cp.async.commit_group;\n"); }
__device__ __forceinline__ void cp_wait_all() { asm volatile("cp.async.wait_group 0;\n" ::: "memory"); }
__device__ __forceinline__ void cp_wait1()   { asm volatile("cp.async.wait_group 1;\n" ::: "memory"); }

__device__ __forceinline__ float to_tf32(float x) {
    unsigned u;
    asm("cvt.rna.tf32.f32 %0, %1;" : "=r"(u) : "f"(x));
    return __uint_as_float(u);
}
__device__ __forceinline__ float sigm(float x) { return 1.f / (1.f + __expf(-x)); }

// D += A(16x8,row) * B(8x8,col)   tf32 inputs, f32 accum
__device__ __forceinline__ void mma8(float* c, const unsigned* a, unsigned b0, unsigned b1) {
    asm volatile(
        "mma.sync.aligned.m16n8k8.row.col.f32.tf32.tf32.f32 "
        "{%0,%1,%2,%3}, {%4,%5,%6,%7}, {%8,%9}, {%0,%1,%2,%3};\n"
        : "+f"(c[0]), "+f"(c[1]), "+f"(c[2]), "+f"(c[3])
        : "r"(a[0]), "r"(a[1]), "r"(a[2]), "r"(a[3]), "r"(b0), "r"(b1));
}
__device__ __forceinline__ unsigned fu(float x) { return __float_as_uint(x); }

// stage 64 rows x 128 cols of a row-major [*][128] weight into dst (stride PADW)
__device__ __forceinline__ void stage_w128(float* dst, const float* src, int t) {
#pragma unroll
    for (int i = 0; i < 16; i++) {
        int idx = t + 128*i;
        int r = idx >> 5, c4 = idx & 31;
        cp_async16(dst + r*PADW + 4*c4, src + r*HD + 4*c4);
    }
}
// stage 64 rows x 64 cols of a row-major [*][64] weight into dst (stride PADW)
__device__ __forceinline__ void stage_w64(float* dst, const float* src, int t) {
#pragma unroll
    for (int i = 0; i < 8; i++) {
        int idx = t + 128*i;
        int r = idx >> 4, c4 = idx & 15;
        cp_async16(dst + r*PADW + 4*c4, src + r*Cc + 4*c4);
    }
}

// ---------------------------------------------------------------------------
// Kernel 0: all 7 weight transposes in one launch.
// ---------------------------------------------------------------------------
__global__ void transpose_all(const float* __restrict__ W_xr, const float* __restrict__ W_xz,
                              const float* __restrict__ W_xh, const float* __restrict__ W_hh,
                              const float* __restrict__ W_ha1, const float* __restrict__ W_ha2,
                              const float* __restrict__ W_y) {
    int i = blockIdx.x * 256 + threadIdx.x;
    const float* src; float* dst; int R, C, off;
    if      (i < 8192)  { src = W_xr;  dst = WT_xr;  R = HD; C = Cc; off = 0; }
    else if (i < 16384) { src = W_xz;  dst = WT_xz;  R = HD; C = Cc; off = 8192; }
    else if (i < 24576) { src = W_xh;  dst = WT_xh;  R = HD; C = Cc; off = 16384; }
    else if (i < 40960) { src = W_hh;  dst = WT_hh;  R = HD; C = HD; off = 24576; }
    else if (i < 49152) { src = W_ha1; dst = WT_ha1; R = HD; C = Cc; off = 40960; }
    else if (i < 65536) { src = W_ha2; dst = WT_ha2; R = HD; C = HD; off = 49152; }
    else if (i < 73728) { src = W_y;   dst = WT_y;   R = Cc; C = HD; off = 65536; }
    else return;
    int j = i - off;
    int r = j / C, c = j - r*C;
    dst[c*R + r] = src[j];
}

// ---------------------------------------------------------------------------
// Kernel 1: prep via mma; writes Q rows + fragment-packed K/V tiles.
// 64 rows/block = 2 KT-tiles. rhs staged into Hs then packed to g_Kpk;
// X (tf32) in Xs packed to g_Vpk; g_Xc row layout kept for gru.
// ---------------------------------------------------------------------------
__global__ void __launch_bounds__(128) prep_mma(const float* __restrict__ X,
                                                const float* __restrict__ Hp,
                                                const float* __restrict__ b_ha2) {
    extern __shared__ float sm[];
    float* Xs  = sm;                 // 64*PADA
    float* Hs  = Xs + 64*PADA;       // 64*PADH : Hp tf32, then rhs (Ksm)
    float* WB0 = Hs + 64*PADH;       // GWC
    float* WB1 = WB0 + GWC;          // GWC

    const int t = threadIdx.x;
    const int w = t >> 5, lane = t & 31;
    const int g = lane >> 2, q = lane & 3;
    const int R0 = blockIdx.x * 64 + 16*w;
    const int sr = 16*w;

    stage_w128(WB0, WT_ha1, t); cp_commit();
    stage_w128(WB1, WT_ha2, t); cp_commit();

#pragma unroll
    for (int i = 0; i < 8; i++) {
        int idx = lane + 32*i;
        int r = idx >> 4, c4 = idx & 15;
        float4 v = *(const float4*)(X + (size_t)(R0 + r)*Cc + 4*c4);
        v.x = to_tf32(v.x); v.y = to_tf32(v.y); v.z = to_tf32(v.z); v.w = to_tf32(v.w);
        *(float4*)(&Xs[(sr + r)*PADA + 4*c4]) = v;
        *(float4*)(&g_Xc[(size_t)(R0 + r)*Cc + 4*c4]) = v;
    }
#pragma unroll
    for (int i = 0; i < 16; i++) {
        int idx = lane + 32*i;
        int r = idx >> 5, c4 = idx & 31;
        float4 v = *(const float4*)(Hp + (size_t)(R0 + r)*HD + 4*c4);
        v.x = to_tf32(v.x); v.y = to_tf32(v.y); v.z = to_tf32(v.z); v.w = to_tf32(v.w);
        *(float4*)(&Hs[(sr + r)*PADH + 4*c4]) = v;
    }
    __syncwarp();

    unsigned af[8][4];
#pragma unroll
    for (int kk = 0; kk < 8; kk++) {
        af[kk][0] = fu(Xs[(sr + g    )*PADA + 8*kk + q    ]);
        af[kk][1] = fu(Xs[(sr + g + 8)*PADA + 8*kk + q    ]);
        af[kk][2] = fu(Xs[(sr + g    )*PADA + 8*kk + q + 4]);
        af[kk][3] = fu(Xs[(sr + g + 8)*PADA + 8*kk + q + 4]);
    }

    float acc[16][4];

    // ---- lhs = X @ WT_ha1 (K=64) using WB0
    cp_wait1(); __syncthreads();
#pragma unroll
    for (int c = 0; c < 16; c++) { acc[c][0]=0.f; acc[c][1]=0.f; acc[c][2]=0.f; acc[c][3]=0.f; }
#pragma unroll
    for (int kk = 0; kk < 8; kk++) {
#pragma unroll
        for (int cc = 0; cc < 16; cc++) {
            unsigned b0 = fu(WB0[(8*kk + q    )*PADW + 8*cc + g]);
            unsigned b1 = fu(WB0[(8*kk + q + 4)*PADW + 8*cc + g]);
            mma8(acc[cc], af[kk], b0, b1);
        }
    }
#pragma unroll
    for (int cc = 0; cc < 16; cc++) {
        int col = 8*cc + 2*q;
        *(float2*)(&g_lhs[(size_t)(R0 + g    )*HD + col]) = make_float2(to_tf32(acc[cc][0]), to_tf32(acc[cc][1]));
        *(float2*)(&g_lhs[(size_t)(R0 + g + 8)*HD + col]) = make_float2(to_tf32(acc[cc][2]), to_tf32(acc[cc][3]));
    }
    __syncthreads();
    stage_w128(WB0, WT_ha2 + 64*HD, t); cp_commit();

    // ---- rhs = Hp @ WT_ha2 + b (K=128): lo half (WB1)
    cp_wait1(); __syncthreads();
#pragma unroll
    for (int c = 0; c < 16; c++) { acc[c][0]=0.f; acc[c][1]=0.f; acc[c][2]=0.f; acc[c][3]=0.f; }
#pragma unroll
    for (int kk = 0; kk < 8; kk++) {
        unsigned a4[4];
        a4[0] = fu(Hs[(sr + g    )*PADH + 8*kk + q    ]);
        a4[1] = fu(Hs[(sr + g + 8)*PADH + 8*kk + q    ]);
        a4[2] = fu(Hs[(sr + g    )*PADH + 8*kk + q + 4]);
        a4[3] = fu(Hs[(sr + g + 8)*PADH + 8*kk + q + 4]);
#pragma unroll
        for (int cc = 0; cc < 16; cc++) {
            unsigned b0 = fu(WB1[(8*kk + q    )*PADW + 8*cc + g]);
            unsigned b1 = fu(WB1[(8*kk + q + 4)*PADW + 8*cc + g]);
            mma8(acc[cc], a4, b0, b1);
        }
    }
    cp_wait_all(); __syncthreads();
#pragma unroll
    for (int kk = 0; kk < 8; kk++) {
        unsigned a4[4];
        a4[0] = fu(Hs[(sr + g    )*PADH + 64 + 8*kk + q    ]);
        a4[1] = fu(Hs[(sr + g + 8)*PADH + 64 + 8*kk + q    ]);
        a4[2] = fu(Hs[(sr + g    )*PADH + 64 + 8*kk + q + 4]);
        a4[3] = fu(Hs[(sr + g + 8)*PADH + 64 + 8*kk + q + 4]);
#pragma unroll
        for (int cc = 0; cc < 16; cc++) {
            unsigned b0 = fu(WB0[(8*kk + q    )*PADW + 8*cc + g]);
            unsigned b1 = fu(WB0[(8*kk + q + 4)*PADW + 8*cc + g]);
            mma8(acc[cc], a4, b0, b1);
        }
    }
    // write rhs (tf32) into Hs (own warp rows only; own Hs reads are done)
    __syncwarp();
#pragma unroll
    for (int cc = 0; cc < 16; cc++) {
        int col = 8*cc + 2*q;
        float2 bv = __ldg((const float2*)(b_ha2 + col));
        *(float2*)(&Hs[(sr + g    )*PADH + col]) =
            make_float2(to_tf32(acc[cc][0] + bv.x), to_tf32(acc[cc][1] + bv.y));
        *(float2*)(&Hs[(sr + g + 8)*PADH + col]) =
            make_float2(to_tf32(acc[cc][2] + bv.x), to_tf32(acc[cc][3] + bv.y));
    }
    __syncthreads();   // cross-warp rows visible for packing

    // ---- pack K tiles (2 per block): Kpk[tp][kk][reg][lane][comp] =
    //      K[tp*32 + 8*comp + (lane>>2)][8*kk + (lane&3) + 4*reg]
    {
        float* dst = g_Kpk + (size_t)blockIdx.x * (2*KPK_T);
        for (int i = t; i < 2048; i += 128) {
            int tp = i >> 10, kk = (i >> 6) & 15, reg = (i >> 5) & 1, ln = i & 31;
            int row = tp*32 + (ln >> 2);
            int col = 8*kk + (ln & 3) + 4*reg;
            float4 v;
            v.x = Hs[(row     )*PADH + col];
            v.y = Hs[(row +  8)*PADH + col];
            v.z = Hs[(row + 16)*PADH + col];
            v.w = Hs[(row + 24)*PADH + col];
            *(float4*)(dst + (size_t)i*4) = v;
        }
    }
    // ---- pack V tiles: Vpk[tp][kk4][reg][ch][lane][comp] =
    //      X[tp*32 + 8*kk4 + (lane&3) + 4*reg][8*(4*ch+comp) + (lane>>2)]
    {
        float* dst = g_Vpk + (size_t)blockIdx.x * (2*VPK_T);
        for (int i = t; i < 1024; i += 128) {
            int tp = i >> 9, kk4 = (i >> 7) & 3, reg = (i >> 6) & 1, ch = (i >> 5) & 1, ln = i & 31;
            int row = tp*32 + 8*kk4 + (ln & 3) + 4*reg;
            int col = 32*ch + (ln >> 2);
            float4 v;
            v.x = Xs[row*PADA + col     ];
            v.y = Xs[row*PADA + col +  8];
            v.z = Xs[row*PADA + col + 16];
            v.w = Xs[row*PADA + col + 24];
            *(float4*)(dst + (size_t)i*4) = v;
        }
    }
}

// ---------------------------------------------------------------------------
// Kernel 2: FUSED flash attention (packed-fragment K/V) + GRU epilogue.
// 128 threads, 2 CTAs/SM. smem:
//   attn: Kb0[4096] Vb0[2048] Kb1[4096] Vb1[2048] Ps[2304]  (Qstage = Kb1..Ps)
//   gru : Wgt[GWC] + per-warp RHs/Zs  (total 25600 floats = 102400 B)
// ---------------------------------------------------------------------------
__global__ void __launch_bounds__(128, 2) attn_gru_kernel(
    const float* __restrict__ Hp,
    const float* __restrict__ b_xr, const float* __restrict__ b_xz,
    const float* __restrict__ b_xh, const float* __restrict__ b_hh,
    const float* __restrict__ b_y,
    float* __restrict__ y_out, float* __restrict__ H_out) {
    extern __shared__ float sm[];
    float* Kb0 = sm;                 // 4096
    float* Vb0 = Kb0 + KPK_T;        // 2048
    float* Kb1 = Vb0 + VPK_T;        // 4096
    float* Vb1 = Kb1 + KPK_T;        // 2048
    float* Ps  = Vb1 + VPK_T;        // 2304
    float* Qstage = Kb1;             // 8448 = 4096+2048+2304 exactly

    const int b  = blockIdx.y;
    const int q0 = blockIdx.x * QT;
    const int t  = threadIdx.x;
    const int w  = t >> 5;
    const int lane = t & 31;
    const int g = lane >> 2;
    const int q = lane & 3;

    const float* Kg = g_Kpk + (size_t)b * (Nn/KT) * KPK_T;
    const float* Vg = g_Vpk + (size_t)b * (Nn/KT) * VPK_T;

    // prefetch tile 0 (linear packed copies)
    {
#pragma unroll
        for (int i = 0; i < 8; i++)
            cp_async16(&Kb0[(t + 128*i)*4], Kg + (t + 128*i)*4);
#pragma unroll
        for (int i = 0; i < 4; i++)
            cp_async16(&Vb0[(t + 128*i)*4], Vg + (t + 128*i)*4);
        cp_commit();
    }

    {
        const float* Qg = g_lhs + (size_t)(b*Nn + q0)*HD;
        for (int idx = t; idx < QT*(HD/4); idx += 128) {
            int r = idx >> 5, c4 = idx & 31;
            float4 v = ((const float4*)(Qg + r*HD))[c4];
            *(float4*)(&Qstage[r*KPAD + c4*4]) = v;
        }
    }
    __syncthreads();

    unsigned qf[16][4];
#pragma unroll
    for (int kk = 0; kk < 16; kk++) {
        qf[kk][0] = fu(Qstage[(16*w + g    )*KPAD + 8*kk + q    ]);
        qf[kk][1] = fu(Qstage[(16*w + g + 8)*KPAD + 8*kk + q    ]);
        qf[kk][2] = fu(Qstage[(16*w + g    )*KPAD + 8*kk + q + 4]);
        qf[kk][3] = fu(Qstage[(16*w + g + 8)*KPAD + 8*kk + q + 4]);
    }
    __syncthreads();

    float oacc[8][4];
#pragma unroll
    for (int c = 0; c < 8; c++)
#pragma unroll
        for (int j = 0; j < 4; j++) oacc[c][j] = 0.f;
    float m0 = -1e30f, m1 = -1e30f, l0 = 0.f, l1 = 0.f;

    float* Pw = Ps + 16*w*PPAD;

    const int NT = Nn / KT;
    for (int it = 0; it < NT; it++) {
        float* KsB = (it & 1) ? Kb1 : Kb0;
        float* VsB = (it & 1) ? Vb1 : Vb0;

        cp_wait_all();
        __syncthreads();

        if (it + 1 < NT) {
            float* KsN = (it & 1) ? Kb0 : Kb1;
            float* VsN = (it & 1) ? Vb0 : Vb1;
            const float* ksrc = Kg + (size_t)(it + 1)*KPK_T;
            const float* vsrc = Vg + (size_t)(it + 1)*VPK_T;
#pragma unroll
            for (int i = 0; i < 8; i++)
                cp_async16(&KsN[(t + 128*i)*4], ksrc + (t + 128*i)*4);
#pragma unroll
            for (int i = 0; i < 4; i++)
                cp_async16(&VsN[(t + 128*i)*4], vsrc + (t + 128*i)*4);
            cp_commit();
        }

        // ---- S = Q @ K^T : packed B-frag loads (2 x LDS.128 per kk)
        float sacc[4][4];
#pragma unroll
        for (int c = 0; c < 4; c++)
#pragma unroll
            for (int j = 0; j < 4; j++) sacc[c][j] = 0.f;

#pragma unroll
        for (int kk = 0; kk < 16; kk++) {
            float4 f0 = *(const float4*)(&KsB[(kk*2    )*128 + lane*4]);
            float4 f1 = *(const float4*)(&KsB[(kk*2 + 1)*128 + lane*4]);
            mma8(sacc[0], qf[kk], fu(f0.x), fu(f1.x));
            mma8(sacc[1], qf[kk], fu(f0.y), fu(f1.y));
            mma8(sacc[2], qf[kk], fu(f0.z), fu(f1.z));
            mma8(sacc[3], qf[kk], fu(f0.w), fu(f1.w));
        }

#pragma unroll
        for (int c = 0; c < 4; c++)
#pragma unroll
            for (int j = 0; j < 4; j++) {
                float v = sacc[c][j];
                sacc[c][j] = (v > 0.f) ? v : 0.01f*v;
            }

        float mx0 = -1e30f, mx1 = -1e30f;
#pragma unroll
        for (int c = 0; c < 4; c++) {
            mx0 = fmaxf(mx0, fmaxf(sacc[c][0], sacc[c][1]));
            mx1 = fmaxf(mx1, fmaxf(sacc[c][2], sacc[c][3]));
        }
        mx0 = fmaxf(mx0, __shfl_xor_sync(0xffffffffu, mx0, 1));
        mx0 = fmaxf(mx0, __shfl_xor_sync(0xffffffffu, mx0, 2));
        mx1 = fmaxf(mx1, __shfl_xor_sync(0xffffffffu, mx1, 1));
        mx1 = fmaxf(mx1, __shfl_xor_sync(0xffffffffu, mx1, 2));

        float mn0 = fmaxf(m0, mx0), mn1 = fmaxf(m1, mx1);
        float al0 = __expf(m0 - mn0), al1 = __expf(m1 - mn1);
        m0 = mn0; m1 = mn1;

        float rs0 = 0.f, rs1 = 0.f;
#pragma unroll
        for (int c = 0; c < 4; c++) {
            sacc[c][0] = __expf(sacc[c][0] - m0);
            sacc[c][1] = __expf(sacc[c][1] - m0);
            sacc[c][2] = __expf(sacc[c][2] - m1);
            sacc[c][3] = __expf(sacc[c][3] - m1);
            rs0 += sacc[c][0] + sacc[c][1];
            rs1 += sacc[c][2] + sacc[c][3];
        }
        rs0 += __shfl_xor_sync(0xffffffffu, rs0, 1);
        rs0 += __shfl_xor_sync(0xffffffffu, rs0, 2);
        rs1 += __shfl_xor_sync(0xffffffffu, rs1, 1);
        rs1 += __shfl_xor_sync(0xffffffffu, rs1, 2);
        l0 = l0*al0 + rs0;
        l1 = l1*al1 + rs1;

#pragma unroll
        for (int c = 0; c < 8; c++) {
            oacc[c][0] *= al0; oacc[c][1] *= al0;
            oacc[c][2] *= al1; oacc[c][3] *= al1;
        }

#pragma unroll
        for (int c = 0; c < 4; c++) {
            *(float2*)(&Pw[(g    )*PPAD + 8*c + 2*q]) = make_float2(to_tf32(sacc[c][0]), to_tf32(sacc[c][1]));
            *(float2*)(&Pw[(g + 8)*PPAD + 8*c + 2*q]) = make_float2(to_tf32(sacc[c][2]), to_tf32(sacc[c][3]));
        }
        __syncwarp();

        // ---- O += P @ V : packed V-frag loads (4 x LDS.128 per kk4)
#pragma unroll
        for (int kk = 0; kk < 4; kk++) {
            unsigned pa[4];
            pa[0] = fu(Pw[(g    )*PPAD + 8*kk + q    ]);
            pa[1] = fu(Pw[(g + 8)*PPAD + 8*kk + q    ]);
            pa[2] = fu(Pw[(g    )*PPAD + 8*kk + q + 4]);
            pa[3] = fu(Pw[(g + 8)*PPAD + 8*kk + q + 4]);
            float4 v00 = *(const float4*)(&VsB[((kk*2    )*2    )*128 + lane*4]);  // reg0 ch0
            float4 v01 = *(const float4*)(&VsB[((kk*2    )*2 + 1)*128 + lane*4]);  // reg0 ch1
            float4 v10 = *(const float4*)(&VsB[((kk*2 + 1)*2    )*128 + lane*4]);  // reg1 ch0
            float4 v11 = *(const float4*)(&VsB[((kk*2 + 1)*2 + 1)*128 + lane*4]);  // reg1 ch1
            mma8(oacc[0], pa, fu(v00.x), fu(v10.x));
            mma8(oacc[1], pa, fu(v00.y), fu(v10.y));
            mma8(oacc[2], pa, fu(v00.z), fu(v10.z));
            mma8(oacc[3], pa, fu(v00.w), fu(v10.w));
            mma8(oacc[4], pa, fu(v01.x), fu(v11.x));
            mma8(oacc[5], pa, fu(v01.y), fu(v11.y));
            mma8(oacc[6], pa, fu(v01.z), fu(v11.z));
            mma8(oacc[7], pa, fu(v01.w), fu(v11.w));
        }
    }

    // ============== GRU epilogue with smem-staged weights ==============
    __syncthreads();   // all warps done with attention smem

    float* Wgt = sm;                             // weight chunk buffer
    float* RHs = sm + GWC + w*GSCR;              // per-warp rh / As / Hns
    float* Zs  = sm + GWC + 4*GSCR + w*GSCR;     // per-warp z
    float* Hns = RHs;

    const size_t R0g = (size_t)(b*Nn + q0 + 16*w);

    stage_w128(Wgt, WT_xr, t); cp_commit();

    {
        float inv0 = 1.f / l0, inv1 = 1.f / l1;
#pragma unroll
        for (int cc = 0; cc < 8; cc++) {
            *(float2*)(&RHs[(g    )*PADA + 8*cc + 2*q]) =
                make_float2(to_tf32(oacc[cc][0]*inv0), to_tf32(oacc[cc][1]*inv0));
            *(float2*)(&RHs[(g + 8)*PADA + 8*cc + 2*q]) =
                make_float2(to_tf32(oacc[cc][2]*inv1), to_tf32(oacc[cc][3]*inv1));
        }
    }
    __syncwarp();

    unsigned af[8][4];
#pragma unroll
    for (int kk = 0; kk < 8; kk++) {
        af[kk][0] = fu(RHs[(g    )*PADA + 8*kk + q    ]);
        af[kk][1] = fu(RHs[(g + 8)*PADA + 8*kk + q    ]);
        af[kk][2] = fu(RHs[(g    )*PADA + 8*kk + q + 4]);
        af[kk][3] = fu(RHs[(g + 8)*PADA + 8*kk + q + 4]);
    }
    __syncwarp();

    cp_wait_all(); __syncthreads();   // chunk xr ready

    // ---- phase r
    {
        float acc[16][4];
#pragma unroll
        for (int c = 0; c < 16; c++) { acc[c][0]=0.f; acc[c][1]=0.f; acc[c][2]=0.f; acc[c][3]=0.f; }
#pragma unroll
        for (int kk = 0; kk < 8; kk++) {
#pragma unroll
            for (int cc = 0; cc < 16; cc++) {
                unsigned b0 = fu(Wgt[(8*kk + q    )*PADW + 8*cc + g]);
                unsigned b1 = fu(Wgt[(8*kk + q + 4)*PADW + 8*cc + g]);
                mma8(acc[cc], af[kk], b0, b1);
            }
        }
#pragma unroll
        for (int cc = 0; cc < 16; cc++) {
            int col = 8*cc + 2*q;
            float2 br = __ldg((const float2*)(b_xr + col));
            float2 h0 = __ldg((const float2*)(Hp + (R0g + g    )*HD + col));
            float2 h1 = __ldg((const float2*)(Hp + (R0g + g + 8)*HD + col));
            *(float2*)(&RHs[(g    )*PADH + col]) =
                make_float2(to_tf32(sigm(acc[cc][0] + br.x) * h0.x),
                            to_tf32(sigm(acc[cc][1] + br.y) * h0.y));
            *(float2*)(&RHs[(g + 8)*PADH + col]) =
                make_float2(to_tf32(sigm(acc[cc][2] + br.x) * h1.x),
                            to_tf32(sigm(acc[cc][3] + br.y) * h1.y));
        }
    }
    __syncthreads();
    stage_w128(Wgt, WT_xz, t); cp_commit(); cp_wait_all(); __syncthreads();

    // ---- phase z
    {
        float acc[16][4];
#pragma unroll
        for (int c = 0; c < 16; c++) { acc[c][0]=0.f; acc[c][1]=0.f; acc[c][2]=0.f; acc[c][3]=0.f; }
#pragma unroll
        for (int kk = 0; kk < 8; kk++) {
#pragma unroll
            for (int cc = 0; cc < 16; cc++) {
                unsigned b0 = fu(Wgt[(8*kk + q    )*PADW + 8*cc + g]);
                unsigned b1 = fu(Wgt[(8*kk + q + 4)*PADW + 8*cc + g]);
                mma8(acc[cc], af[kk], b0, b1);
            }
        }
#pragma unroll
        for (int cc = 0; cc < 16; cc++) {
            int col = 8*cc + 2*q;
            float2 bz = __ldg((const float2*)(b_xz + col));
            *(float2*)(&Zs[(g    )*PADH + col]) =
                make_float2(sigm(acc[cc][0] + bz.x), sigm(acc[cc][1] + bz.y));
            *(float2*)(&Zs[(g + 8)*PADH + col]) =
                make_float2(sigm(acc[cc][2] + bz.x), sigm(acc[cc][3] + bz.y));
        }
    }
    __syncthreads();
    stage_w128(Wgt, WT_xh, t); cp_commit(); cp_wait_all(); __syncthreads();

    // ---- phase xh
    float xacc[16][4];
#pragma unroll
    for (int c = 0; c < 16; c++) { xacc[c][0]=0.f; xacc[c][1]=0.f; xacc[c][2]=0.f; xacc[c][3]=0.f; }
#pragma unroll
    for (int kk = 0; kk < 8; kk++) {
        unsigned a4[4];
        a4[0] = fu(__ldg(g_Xc + (R0g + g    )*Cc + 8*kk + q    ));
        a4[1] = fu(__ldg(g_Xc + (R0g + g + 8)*Cc + 8*kk + q    ));
        a4[2] = fu(__ldg(g_Xc + (R0g + g    )*Cc + 8*kk + q + 4));
        a4[3] = fu(__ldg(g_Xc + (R0g + g + 8)*Cc + 8*kk + q + 4));
#pragma unroll
        for (int cc = 0; cc < 16; cc++) {
            unsigned b0 = fu(Wgt[(8*kk + q    )*PADW + 8*cc + g]);
            unsigned b1 = fu(Wgt[(8*kk + q + 4)*PADW + 8*cc + g]);
            mma8(xacc[cc], a4, b0, b1);
        }
    }
    __syncthreads();
    stage_w128(Wgt, WT_hh, t); cp_commit(); cp_wait_all(); __syncthreads();

    // ---- phase hh-lo
#pragma unroll
    for (int kk = 0; kk < 8; kk++) {
        unsigned a4[4];
        a4[0] = fu(RHs[(g    )*PADH + 8*kk + q    ]);
        a4[1] = fu(RHs[(g + 8)*PADH + 8*kk + q    ]);
        a4[2] = fu(RHs[(g    )*PADH + 8*kk + q + 4]);
        a4[3] = fu(RHs[(g + 8)*PADH + 8*kk + q + 4]);
#pragma unroll
        for (int cc = 0; cc < 16; cc++) {
            unsigned b0 = fu(Wgt[(8*kk + q    )*PADW + 8*cc + g]);
            unsigned b1 = fu(Wgt[(8*kk + q + 4)*PADW + 8*cc + g]);
            mma8(xacc[cc], a4, b0, b1);
        }
    }
    __syncthreads();
    stage_w128(Wgt, WT_hh + 64*HD, t); cp_commit(); cp_wait_all(); __syncthreads();

    // ---- phase hh-hi
#pragma unroll
    for (int kk = 0; kk < 8; kk++) {
        unsigned a4[4];
        a4[0] = fu(RHs[(g    )*PADH + 64 + 8*kk + q    ]);
        a4[1] = fu(RHs[(g + 8)*PADH + 64 + 8*kk + q    ]);
        a4[2] = fu(RHs[(g    )*PADH + 64 + 8*kk + q + 4]);
        a4[3] = fu(RHs[(g + 8)*PADH + 64 + 8*kk + q + 4]);
#pragma unroll
        for (int cc = 0; cc < 16; cc++) {
            unsigned b0 = fu(Wgt[(8*kk + q    )*PADW + 8*cc + g]);
            unsigned b1 = fu(Wgt[(8*kk + q + 4)*PADW + 8*cc + g]);
            mma8(xacc[cc], a4, b0, b1);
        }
    }
    __syncwarp();

    // ---- phase Hn
#pragma unroll
    for (int cc = 0; cc < 16; cc++) {
        int col = 8*cc + 2*q;
        float2 bh = __ldg((const float2*)(b_xh + col));
        float2 bg = __ldg((const float2*)(b_hh + col));
        float2 h0 = __ldg((const float2*)(Hp + (R0g + g    )*HD + col));
        float2 h1 = __ldg((const float2*)(Hp + (R0g + g + 8)*HD + col));
        float2 z0 = *(const float2*)(&Zs[(g    )*PADH + col]);
        float2 z1 = *(const float2*)(&Zs[(g + 8)*PADH + col]);
        float c00 = tanhf(xacc[cc][0] + bh.x + bg.x);
        float c01 = tanhf(xacc[cc][1] + bh.y + bg.y);
        float c10 = tanhf(xacc[cc][2] + bh.x + bg.x);
        float c11 = tanhf(xacc[cc][3] + bh.y + bg.y);
        float H00 = z0.x*h0.x + (1.f - z0.x)*c00;
        float H01 = z0.y*h0.y + (1.f - z0.y)*c01;
        float H10 = z1.x*h1.x + (1.f - z1.x)*c10;
        float H11 = z1.y*h1.y + (1.f - z1.y)*c11;
        *(float2*)(&H_out[(R0g + g    )*HD + col]) = make_float2(H00, H01);
        *(float2*)(&H_out[(R0g + g + 8)*HD + col]) = make_float2(H10, H11);
        *(float2*)(&Hns[(g    )*PADH + col]) = make_float2(to_tf32(H00), to_tf32(H01));
        *(float2*)(&Hns[(g + 8)*PADH + col]) = make_float2(to_tf32(H10), to_tf32(H11));
    }
    __syncthreads();
    stage_w64(Wgt, WT_y, t); cp_commit(); cp_wait_all(); __syncthreads();

    // ---- phase y-lo
    float yac[8][4];
#pragma unroll
    for (int c = 0; c < 8; c++) { yac[c][0]=0.f; yac[c][1]=0.f; yac[c][2]=0.f; yac[c][3]=0.f; }
#pragma unroll
    for (int kk = 0; kk < 8; kk++) {
        unsigned a4[4];
        a4[0] = fu(Hns[(g    )*PADH + 8*kk + q    ]);
        a4[1] = fu(Hns[(g + 8)*PADH + 8*kk + q    ]);
        a4[2] = fu(Hns[(g    )*PADH + 8*kk + q + 4]);
        a4[3] = fu(Hns[(g + 8)*PADH + 8*kk + q + 4]);
#pragma unroll
        for (int cc = 0; cc < 8; cc++) {
            unsigned b0 = fu(Wgt[(8*kk + q    )*PADW + 8*cc + g]);
            unsigned b1 = fu(Wgt[(8*kk + q + 4)*PADW + 8*cc + g]);
            mma8(yac[cc], a4, b0, b1);
        }
    }
    __syncthreads();
    stage_w64(Wgt, WT_y + 64*Cc, t); cp_commit(); cp_wait_all(); __syncthreads();

    // ---- phase y-hi
#pragma unroll
    for (int kk = 0; kk < 8; kk++) {
        unsigned a4[4];
        a4[0] = fu(Hns[(g    )*PADH + 64 + 8*kk + q    ]);
        a4[1] = fu(Hns[(g + 8)*PADH + 64 + 8*kk + q    ]);
        a4[2] = fu(Hns[(g    )*PADH + 64 + 8*kk + q + 4]);
        a4[3] = fu(Hns[(g + 8)*PADH + 64 + 8*kk + q + 4]);
#pragma unroll
        for (int cc = 0; cc < 8; cc++) {
            unsigned b0 = fu(Wgt[(8*kk + q    )*PADW + 8*cc + g]);
            unsigned b1 = fu(Wgt[(8*kk + q + 4)*PADW + 8*cc + g]);
            mma8(yac[cc], a4, b0, b1);
        }
    }
#pragma unroll
    for (int cc = 0; cc < 8; cc++) {
        int col = 8*cc + 2*q;
        float2 by = __ldg((const float2*)(b_y + col));
        *(float2*)(&y_out[(R0g + g    )*Cc + col]) =
            make_float2(yac[cc][0] + by.x, yac[cc][1] + by.y);
        *(float2*)(&y_out[(R0g + g + 8)*Cc + col]) =
            make_float2(yac[cc][2] + by.x, yac[cc][3] + by.y);
    }
}

// ---------------------------------------------------------------------------
extern "C" void kernel_launch(void* const* d_in, const int* in_sizes, int n_in,
                              void* d_out, int out_size) {
    const float* Hp    = (const float*)d_in[0];
    const float* X     = (const float*)d_in[1];
    const float* W_xr  = (const float*)d_in[2];
    const float* b_xr  = (const float*)d_in[3];
    const float* W_xz  = (const float*)d_in[4];
    const float* b_xz  = (const float*)d_in[5];
    const float* W_xh  = (const float*)d_in[6];
    const float* b_xh  = (const float*)d_in[7];
    const float* W_hh  = (const float*)d_in[8];
    const float* b_hh  = (const float*)d_in[9];
    const float* W_ha1 = (const float*)d_in[10];
    const float* W_ha2 = (const float*)d_in[11];
    const float* b_ha2 = (const float*)d_in[12];
    const float* W_y   = (const float*)d_in[13];
    const float* b_y   = (const float*)d_in[14];

    float* out = (float*)d_out;
    float* y_out = out;                        // [B,N,C]
    float* H_out = out + (size_t)Bb*Nn*Cc;     // [B,N,Hd]

    transpose_all<<<(73728 + 255)/256, 256>>>(W_xr, W_xz, W_xh, W_hh, W_ha1, W_ha2, W_y);

    size_t smem_prep = (size_t)(64*PADA + 64*PADH + 2*GWC) * sizeof(float);
    cudaFuncSetAttribute(prep_mma, cudaFuncAttributeMaxDynamicSharedMemorySize, (int)smem_prep);
    prep_mma<<<Bb*Nn/64, 128, smem_prep>>>(X, Hp, b_ha2);

    size_t smem_attn = (size_t)(GWC + 8*GSCR) * sizeof(float);   // 102400 B
    cudaFuncSetAttribute(attn_gru_kernel, cudaFuncAttributeMaxDynamicSharedMemorySize, (int)smem_attn);
    attn_gru_kernel<<<dim3(Nn/QT, Bb), 128, smem_attn>>>(Hp, b_xr, b_xz, b_xh, b_hh, b_y,
                                                         y_out, H_out);
}